// round 1
// baseline (speedup 1.0000x reference)
#include <cuda_runtime.h>

#define B_    8192
#define DIN   2048
#define DHID  512
#define DOUT  2048
#define DCLD  1024
#define KC    10
#define NIT   10

// ------------------------- device scratch (static, no runtime alloc) ------
__device__ float g_h[2][B_*DHID];          // hidden activations per view
__device__ float g_zH2[B_*DOUT];           // z2_H
__device__ float g_zL[2][B_*DCLD];         // aligned internal copies of z1_L/z2_L
__device__ float g_wcinv[DCLD];
__device__ float g_bns[2][DHID];
__device__ float g_bns2[2][DHID];
__device__ float g_bnm[2][DHID];
__device__ float g_bnis[2][DHID];
__device__ float g_rowss[2][B_];
__device__ float g_cent[2][KC*DCLD];
__device__ float g_csum[2][KC*DCLD];
__device__ float g_ccnt[2][KC];
__device__ float g_cn2[2][KC];
__device__ int   g_cl[2][B_];
__device__ float g_scal[4];                // cos1_sum, cos2_sum, ce1_sum, ce2_sum

// ------------------------- helpers ---------------------------------------
__device__ __forceinline__ float block_reduce_256(float v) {
    __shared__ float s[8];
#pragma unroll
    for (int o = 16; o; o >>= 1) v += __shfl_xor_sync(0xffffffffu, v, o);
    if ((threadIdx.x & 31) == 0) s[threadIdx.x >> 5] = v;
    __syncthreads();
    v = (threadIdx.x < 8) ? s[threadIdx.x] : 0.f;
    if (threadIdx.x < 32) {
#pragma unroll
        for (int o = 4; o; o >>= 1) v += __shfl_xor_sync(0xffffffffu, v, o);
    }
    return v;  // valid in thread 0
}

// ------------------------- init ------------------------------------------
__global__ void init_zero() {
    int i = blockIdx.x * 256 + threadIdx.x;
    if (i < 4) g_scal[i] = 0.f;
    if (i < 2 * B_) ((float*)g_rowss)[i] = 0.f;
    if (i < 2 * DHID) { ((float*)g_bns)[i] = 0.f; ((float*)g_bns2)[i] = 0.f; }
}

// column norms of Wc -> 1/max(||col||, 1e-12)
__global__ void wc_inv_kernel(const float* __restrict__ Wc) {
    int c = blockIdx.x * 256 + threadIdx.x;
    if (c >= DCLD) return;
    float s = 0.f;
    for (int r = 0; r < DIN; r++) { float v = Wc[(size_t)r * DCLD + c]; s += v * v; }
    g_wcinv[c] = 1.f / fmaxf(sqrtf(s), 1e-12f);
}

// ------------------------- SGEMM (128x128x8, 8x8 micro, double-buffered) --
// MODE 0: C = A*B + bias(aux[col])
// MODE 1: C = (A*B) * aux[col]; also atomically accumulates per-row sum of
//         squares into rowss (for later row normalization).
template<int MODE>
__global__ void __launch_bounds__(256) sgemm(
    const float* __restrict__ A, const float* __restrict__ Bmat,
    float* __restrict__ C, const float* __restrict__ aux,
    float* __restrict__ rowss, int N, int Kd)
{
    __shared__ float As[2][8][128];
    __shared__ float Bs[2][8][128];
    const int tid  = threadIdx.x;
    const int tx   = tid & 15;
    const int ty   = tid >> 4;
    const int aRow = tid >> 1;
    const int aCol = (tid & 1) << 2;
    const int bRow = tid >> 5;
    const int bCol = (tid & 31) << 2;
    const int mBase = blockIdx.y * 128;
    const int nBase = blockIdx.x * 128;

    const float* Ap = A + (size_t)(mBase + aRow) * Kd + aCol;
    const float* Bp = Bmat + (size_t)bRow * N + nBase + bCol;

    float acc[8][8];
#pragma unroll
    for (int i = 0; i < 8; i++)
#pragma unroll
        for (int j = 0; j < 8; j++) acc[i][j] = 0.f;

    float4 a4 = *(const float4*)Ap;
    float4 b4 = *(const float4*)Bp;
    As[0][aCol  ][aRow] = a4.x;
    As[0][aCol+1][aRow] = a4.y;
    As[0][aCol+2][aRow] = a4.z;
    As[0][aCol+3][aRow] = a4.w;
    *(float4*)&Bs[0][bRow][bCol] = b4;
    __syncthreads();

    const int nk = Kd >> 3;
    for (int kt = 1; kt < nk; kt++) {
        Ap += 8;
        Bp += (size_t)8 * N;
        a4 = *(const float4*)Ap;
        b4 = *(const float4*)Bp;
        const int cb = (kt - 1) & 1;
#pragma unroll
        for (int kk = 0; kk < 8; kk++) {
            float ar[8], br[8];
            *(float4*)&ar[0] = *(const float4*)&As[cb][kk][ty * 8];
            *(float4*)&ar[4] = *(const float4*)&As[cb][kk][ty * 8 + 4];
            *(float4*)&br[0] = *(const float4*)&Bs[cb][kk][tx * 8];
            *(float4*)&br[4] = *(const float4*)&Bs[cb][kk][tx * 8 + 4];
#pragma unroll
            for (int i = 0; i < 8; i++)
#pragma unroll
                for (int j = 0; j < 8; j++)
                    acc[i][j] = fmaf(ar[i], br[j], acc[i][j]);
        }
        const int nb = kt & 1;
        As[nb][aCol  ][aRow] = a4.x;
        As[nb][aCol+1][aRow] = a4.y;
        As[nb][aCol+2][aRow] = a4.z;
        As[nb][aCol+3][aRow] = a4.w;
        *(float4*)&Bs[nb][bRow][bCol] = b4;
        __syncthreads();
    }
    {
        const int cb = (nk - 1) & 1;
#pragma unroll
        for (int kk = 0; kk < 8; kk++) {
            float ar[8], br[8];
            *(float4*)&ar[0] = *(const float4*)&As[cb][kk][ty * 8];
            *(float4*)&ar[4] = *(const float4*)&As[cb][kk][ty * 8 + 4];
            *(float4*)&br[0] = *(const float4*)&Bs[cb][kk][tx * 8];
            *(float4*)&br[4] = *(const float4*)&Bs[cb][kk][tx * 8 + 4];
#pragma unroll
            for (int i = 0; i < 8; i++)
#pragma unroll
                for (int j = 0; j < 8; j++)
                    acc[i][j] = fmaf(ar[i], br[j], acc[i][j]);
        }
    }

    const int row0 = mBase + ty * 8;
    const int col0 = nBase + tx * 8;
    if (MODE == 0) {
#pragma unroll
        for (int i = 0; i < 8; i++) {
            float* cr = C + (size_t)(row0 + i) * N + col0;
#pragma unroll
            for (int j = 0; j < 8; j++) cr[j] = acc[i][j] + aux[col0 + j];
        }
    } else {
        float rs[8];
#pragma unroll
        for (int i = 0; i < 8; i++) {
            float* cr = C + (size_t)(row0 + i) * N + col0;
            float s = 0.f;
#pragma unroll
            for (int j = 0; j < 8; j++) {
                float v = acc[i][j] * aux[col0 + j];
                cr[j] = v;
                s = fmaf(v, v, s);
            }
            rs[i] = s;
        }
#pragma unroll
        for (int o = 8; o; o >>= 1)
#pragma unroll
            for (int i = 0; i < 8; i++)
                rs[i] += __shfl_xor_sync(0xffffffffu, rs[i], o);
        if (tx == 0)
#pragma unroll
            for (int i = 0; i < 8; i++) atomicAdd(&rowss[row0 + i], rs[i]);
    }
}

// ------------------------- batchnorm -------------------------------------
__global__ void bn_partial(int view) {
    int c  = blockIdx.x * 256 + threadIdx.x;   // 0..511
    int r0 = blockIdx.y * 256;
    const float* h = g_h[view];
    float s = 0.f, s2 = 0.f;
    for (int r = r0; r < r0 + 256; r++) {
        float v = h[(size_t)r * DHID + c];
        s += v;
        s2 = fmaf(v, v, s2);
    }
    atomicAdd(&g_bns[view][c], s);
    atomicAdd(&g_bns2[view][c], s2);
}

__global__ void bn_finish(int view) {
    int c = blockIdx.x * 256 + threadIdx.x;
    if (c >= DHID) return;
    float m = g_bns[view][c] * (1.f / B_);
    float v = g_bns2[view][c] * (1.f / B_) - m * m;
    g_bnm[view][c]  = m;
    g_bnis[view][c] = rsqrtf(v + 1e-5f);
}

__global__ void bn_relu(int view, const float* __restrict__ gamma,
                        const float* __restrict__ beta) {
    int i = blockIdx.x * 256 + threadIdx.x;
    int c = i & (DHID - 1);
    float h = g_h[view][i];
    float v = fmaf(gamma[c] * (h - g_bnm[view][c]), g_bnis[view][c], beta[c]);
    g_h[view][i] = fmaxf(v, 0.f);
}

// ------------------------- z_L row normalization + copy-out ---------------
__global__ void row_scale(float* __restrict__ z1L_out) {
    const int view = blockIdx.y;
    size_t i4 = (size_t)blockIdx.x * 256 + threadIdx.x;   // float4 index
    float4* z = (float4*)g_zL[view];
    float4 v = z[i4];
    int row = (int)((i4 * 4) >> 10);
    float rs = rsqrtf(g_rowss[view][row]);
    v.x *= rs; v.y *= rs; v.z *= rs; v.w *= rs;
    z[i4] = v;
    if (view == 0) {
        size_t b = i4 * 4;
        z1L_out[b]   = v.x;
        z1L_out[b+1] = v.y;
        z1L_out[b+2] = v.z;
        z1L_out[b+3] = v.w;
    }
}

// ------------------------- cosine(z_H, y_other) mean ----------------------
__global__ void __launch_bounds__(256) cos_kernel(const float* __restrict__ z1H,
                                                  const float* __restrict__ y1,
                                                  const float* __restrict__ y2) {
    const int pair = blockIdx.y;
    const float* a = pair ? g_zH2 : z1H;
    const float* b = pair ? y1 : y2;
    const int tid = threadIdx.x, lane = tid & 31, wid = tid >> 5;
    __shared__ float sw[8];
    float local = 0.f;
    for (int row = blockIdx.x * 8 + wid; row < B_; row += gridDim.x * 8) {
        const float* ar = a + (size_t)row * DOUT;
        const float* br = b + (size_t)row * DOUT;
        float d = 0.f, na = 0.f, nb = 0.f;
        for (int j = lane; j < DOUT; j += 32) {
            float x = ar[j], y = br[j];
            d  = fmaf(x, y, d);
            na = fmaf(x, x, na);
            nb = fmaf(y, y, nb);
        }
#pragma unroll
        for (int o = 16; o; o >>= 1) {
            d  += __shfl_xor_sync(0xffffffffu, d, o);
            na += __shfl_xor_sync(0xffffffffu, na, o);
            nb += __shfl_xor_sync(0xffffffffu, nb, o);
        }
        local += d / (fmaxf(sqrtf(na), 1e-8f) * fmaxf(sqrtf(nb), 1e-8f));
    }
    if (lane == 0) sw[wid] = local;
    __syncthreads();
    if (tid == 0) {
        float s = 0.f;
        for (int i = 0; i < 8; i++) s += sw[i];
        atomicAdd(&g_scal[pair], s);
    }
}

// ------------------------- kmeans -----------------------------------------
__global__ void km_init() {
    const int view = blockIdx.y, k = blockIdx.x, tid = threadIdx.x;
    const float* src = g_zL[view] + (size_t)k * DCLD;
    float p = 0.f;
    for (int j = tid; j < DCLD; j += 256) {
        float v = src[j];
        g_cent[view][k * DCLD + j] = v;
        p = fmaf(v, v, p);
    }
    p = block_reduce_256(p);
    if (tid == 0) g_cn2[view][k] = p;
}

__global__ void km_zero() {
    int i = blockIdx.x * 256 + threadIdx.x;
    if (i < 2 * KC * DCLD) ((float*)g_csum)[i] = 0.f;
    if (i < 2 * KC) ((float*)g_ccnt)[i] = 0.f;
}

__global__ void __launch_bounds__(256) km_assign() {
    extern __shared__ float sm[];
    float* sc   = sm;                  // KC*DCLD centers
    float* ss   = sm + KC * DCLD;      // KC*DCLD segment sums
    float* scnt = ss + KC * DCLD;      // KC
    float* scn2 = scnt + KC;           // KC
    const int view = blockIdx.y;
    const float* z = g_zL[view];
    const int tid = threadIdx.x;
    for (int i = tid; i < KC * DCLD; i += 256) { sc[i] = g_cent[view][i]; ss[i] = 0.f; }
    if (tid < KC) { scnt[tid] = 0.f; scn2[tid] = g_cn2[view][tid]; }
    __syncthreads();
    const int lane = tid & 31, wid = tid >> 5;
    for (int row = blockIdx.x * 8 + wid; row < B_; row += gridDim.x * 8) {
        const float4* xr = (const float4*)(z + (size_t)row * DCLD);
        float dots[KC];
#pragma unroll
        for (int k = 0; k < KC; k++) dots[k] = 0.f;
        for (int j = lane; j < DCLD / 4; j += 32) {
            float4 xv = xr[j];
#pragma unroll
            for (int k = 0; k < KC; k++) {
                float4 cv = *(const float4*)&sc[k * DCLD + 4 * j];
                dots[k] += xv.x * cv.x + xv.y * cv.y + xv.z * cv.z + xv.w * cv.w;
            }
        }
#pragma unroll
        for (int k = 0; k < KC; k++)
#pragma unroll
            for (int o = 16; o; o >>= 1)
                dots[k] += __shfl_xor_sync(0xffffffffu, dots[k], o);
        int bi = 0;
        float bd = scn2[0] - 2.f * dots[0];
#pragma unroll
        for (int k = 1; k < KC; k++) {
            float d = scn2[k] - 2.f * dots[k];
            if (d < bd) { bd = d; bi = k; }   // strict <: first-min like argmin
        }
        if (lane == 0) { g_cl[view][row] = bi; atomicAdd(&scnt[bi], 1.f); }
        float* dst = ss + bi * DCLD;
        const float* xs = z + (size_t)row * DCLD;
        for (int j = lane; j < DCLD; j += 32) atomicAdd(&dst[j], xs[j]);
    }
    __syncthreads();
    for (int i = tid; i < KC * DCLD; i += 256) {
        float v = ss[i];
        if (v != 0.f) atomicAdd(&g_csum[view][i], v);
    }
    if (tid < KC) {
        float v = scnt[tid];
        if (v != 0.f) atomicAdd(&g_ccnt[view][tid], v);
    }
}

__global__ void km_update() {
    const int view = blockIdx.y, k = blockIdx.x, tid = threadIdx.x;
    const float inv = 1.f / fmaxf(g_ccnt[view][k], 1.f);
    float p = 0.f;
    for (int j = tid; j < DCLD; j += 256) {
        float c = g_csum[view][k * DCLD + j] * inv;
        g_cent[view][k * DCLD + j] = c;
        p = fmaf(c, c, p);
    }
    p = block_reduce_256(p);
    if (tid == 0) g_cn2[view][k] = p;
}

// ------------------------- cross entropy ----------------------------------
__global__ void __launch_bounds__(256) ce_kernel() {
    __shared__ float sc[KC * DCLD];
    __shared__ float swarp[8];
    const int view = blockIdx.y;
    const float* z    = g_zL[view];
    const float* cent = g_cent[view ^ 1];
    const int*   lab  = g_cl[view ^ 1];
    const int tid = threadIdx.x;
    for (int i = tid; i < KC * DCLD; i += 256) sc[i] = cent[i];
    __syncthreads();
    const int lane = tid & 31, wid = tid >> 5;
    float local = 0.f;
    const float invT = 1.f / 0.07f;
    for (int row = blockIdx.x * 8 + wid; row < B_; row += gridDim.x * 8) {
        const float4* xr = (const float4*)(z + (size_t)row * DCLD);
        float dots[KC];
#pragma unroll
        for (int k = 0; k < KC; k++) dots[k] = 0.f;
        for (int j = lane; j < DCLD / 4; j += 32) {
            float4 xv = xr[j];
#pragma unroll
            for (int k = 0; k < KC; k++) {
                float4 cv = *(const float4*)&sc[k * DCLD + 4 * j];
                dots[k] += xv.x * cv.x + xv.y * cv.y + xv.z * cv.z + xv.w * cv.w;
            }
        }
#pragma unroll
        for (int k = 0; k < KC; k++)
#pragma unroll
            for (int o = 16; o; o >>= 1)
                dots[k] += __shfl_xor_sync(0xffffffffu, dots[k], o);
        float m = -1e30f;
#pragma unroll
        for (int k = 0; k < KC; k++) { dots[k] *= invT; m = fmaxf(m, dots[k]); }
        float s = 0.f;
#pragma unroll
        for (int k = 0; k < KC; k++) s += expf(dots[k] - m);
        float lse = logf(s) + m;
        local += lse - dots[lab[row]];
    }
    if (lane == 0) swarp[wid] = local;
    __syncthreads();
    if (tid == 0) {
        float s = 0.f;
        for (int i = 0; i < 8; i++) s += swarp[i];
        atomicAdd(&g_scal[2 + view], s);
    }
}

// ------------------------- finalize ---------------------------------------
__global__ void final_kernel(float* __restrict__ out,
                             const float* __restrict__ Lam) {
    if (threadIdx.x == 0) {
        float cos1 = g_scal[0] * (1.f / B_);
        float cos2 = g_scal[1] * (1.f / B_);
        float lss  = 2.f - cos1 - cos2;
        float ce1  = g_scal[2] * (1.f / B_);
        float ce2  = g_scal[3] * (1.f / B_);
        float lcld = 0.5f * (ce1 + ce2);
        out[0] = lss + (*Lam) * lcld;
        out[1] = lss;
        out[2] = lcld;
    }
}

// ------------------------- host launcher ----------------------------------
extern "C" void kernel_launch(void* const* d_in, const int* in_sizes, int n_in,
                              void* d_out, int out_size)
{
    (void)in_sizes; (void)n_in; (void)out_size;
    const float* y1    = (const float*)d_in[0];
    const float* y2    = (const float*)d_in[1];
    const float* Lam   = (const float*)d_in[2];
    const float* W1    = (const float*)d_in[3];
    const float* b1    = (const float*)d_in[4];
    const float* gamma = (const float*)d_in[5];
    const float* beta  = (const float*)d_in[6];
    const float* W2    = (const float*)d_in[7];
    const float* b2    = (const float*)d_in[8];
    const float* Wc    = (const float*)d_in[9];
    float* out = (float*)d_out;
    float* z1H = out + 3;
    float* z1L = out + 3 + (size_t)B_ * DOUT;

    float *p_h = 0, *p_zH2 = 0, *p_zL = 0, *p_wcinv = 0, *p_rowss = 0;
    cudaGetSymbolAddress((void**)&p_h,     g_h);
    cudaGetSymbolAddress((void**)&p_zH2,   g_zH2);
    cudaGetSymbolAddress((void**)&p_zL,    g_zL);
    cudaGetSymbolAddress((void**)&p_wcinv, g_wcinv);
    cudaGetSymbolAddress((void**)&p_rowss, g_rowss);

    const int ASSIGN_SMEM = (2 * KC * DCLD + 2 * KC) * (int)sizeof(float);
    cudaFuncSetAttribute(km_assign, cudaFuncAttributeMaxDynamicSharedMemorySize,
                         ASSIGN_SMEM);

    init_zero<<<64, 256>>>();
    wc_inv_kernel<<<DCLD / 256, 256>>>(Wc);

    for (int v = 0; v < 2; v++) {
        const float* y = v ? y2 : y1;
        float* hbuf = p_h + (size_t)v * B_ * DHID;
        sgemm<0><<<dim3(DHID / 128, B_ / 128), 256>>>(y, W1, hbuf, b1, 0, DHID, DIN);
        bn_partial<<<dim3(DHID / 256, 32), 256>>>(v);
        bn_finish<<<DHID / 256, 256>>>(v);
        bn_relu<<<(B_ * DHID) / 256, 256>>>(v, gamma, beta);
        sgemm<0><<<dim3(DOUT / 128, B_ / 128), 256>>>(hbuf, W2,
                v ? p_zH2 : z1H, b2, 0, DOUT, DHID);
        sgemm<1><<<dim3(DCLD / 128, B_ / 128), 256>>>(y, Wc,
                p_zL + (size_t)v * B_ * DCLD, p_wcinv,
                p_rowss + (size_t)v * B_, DCLD, DIN);
    }

    row_scale<<<dim3((B_ * DCLD / 4) / 256, 2), 256>>>(z1L);
    cos_kernel<<<dim3(128, 2), 256>>>(z1H, y1, y2);

    km_init<<<dim3(KC, 2), 256>>>();
    for (int it = 0; it < NIT; it++) {
        km_zero<<<80, 256>>>();
        km_assign<<<dim3(64, 2), 256, ASSIGN_SMEM>>>();
        km_update<<<dim3(KC, 2), 256>>>();
    }

    ce_kernel<<<dim3(64, 2), 256>>>();
    final_kernel<<<1, 32>>>(out, Lam);
}

// round 4
// speedup vs baseline: 1.0685x; 1.0685x over previous
#include <cuda_runtime.h>
#include <cuda_bf16.h>
#include <cstdint>

#define B_    8192
#define DIN   2048
#define DHID  512
#define DOUT  2048
#define DCLD  1024
#define KC    10
#define NIT   10

// ------------------------- device scratch (static, no runtime alloc) ------
__device__ float g_h[2][B_*DHID];          // hidden activations per view
__device__ float g_zH2[B_*DOUT];           // z2_H
__device__ float g_zL[2][B_*DCLD];         // aligned internal copies of z1_L/z2_L
__device__ float g_wcinv[DCLD];
__device__ float g_bns[2][DHID];
__device__ float g_bns2[2][DHID];
__device__ float g_bnm[2][DHID];
__device__ float g_bnis[2][DHID];
__device__ float g_rowss[2][B_];
__device__ float g_cent[2][KC*DCLD];
__device__ float g_csum[2][KC*DCLD];
__device__ float g_ccnt[2][KC];
__device__ float g_cn2[2][KC];
__device__ int   g_cl[2][B_];
__device__ float g_scal[4];                // cos1_sum, cos2_sum, ce1_sum, ce2_sum

// ------------------------- helpers ---------------------------------------
__device__ __forceinline__ float block_reduce_256(float v) {
    __shared__ float s[8];
#pragma unroll
    for (int o = 16; o; o >>= 1) v += __shfl_xor_sync(0xffffffffu, v, o);
    if ((threadIdx.x & 31) == 0) s[threadIdx.x >> 5] = v;
    __syncthreads();
    v = (threadIdx.x < 8) ? s[threadIdx.x] : 0.f;
    if (threadIdx.x < 32) {
#pragma unroll
        for (int o = 4; o; o >>= 1) v += __shfl_xor_sync(0xffffffffu, v, o);
    }
    return v;  // valid in thread 0
}

__device__ __forceinline__ void ldsm_x4(uint32_t* r, uint32_t addr) {
    asm volatile("ldmatrix.sync.aligned.m8n8.x4.shared.b16 {%0,%1,%2,%3}, [%4];\n"
        : "=r"(r[0]), "=r"(r[1]), "=r"(r[2]), "=r"(r[3]) : "r"(addr));
}
__device__ __forceinline__ void ldsm_x4_t(uint32_t* r, uint32_t addr) {
    asm volatile("ldmatrix.sync.aligned.m8n8.x4.trans.shared.b16 {%0,%1,%2,%3}, [%4];\n"
        : "=r"(r[0]), "=r"(r[1]), "=r"(r[2]), "=r"(r[3]) : "r"(addr));
}
__device__ __forceinline__ void mma16816(float* c, const uint32_t* a, const uint32_t* b) {
    asm volatile(
        "mma.sync.aligned.m16n8k16.row.col.f32.bf16.bf16.f32 "
        "{%0,%1,%2,%3}, {%4,%5,%6,%7}, {%8,%9}, {%0,%1,%2,%3};\n"
        : "+f"(c[0]), "+f"(c[1]), "+f"(c[2]), "+f"(c[3])
        : "r"(a[0]), "r"(a[1]), "r"(a[2]), "r"(a[3]), "r"(b[0]), "r"(b[1]));
}

__device__ __forceinline__ void split4(float4 v, uint32_t& h0, uint32_t& h1,
                                       uint32_t& l0, uint32_t& l1) {
    __nv_bfloat16 bx = __float2bfloat16_rn(v.x);
    __nv_bfloat16 by = __float2bfloat16_rn(v.y);
    __nv_bfloat16 bz = __float2bfloat16_rn(v.z);
    __nv_bfloat16 bw = __float2bfloat16_rn(v.w);
    __nv_bfloat16 rx = __float2bfloat16_rn(v.x - __bfloat162float(bx));
    __nv_bfloat16 ry = __float2bfloat16_rn(v.y - __bfloat162float(by));
    __nv_bfloat16 rz = __float2bfloat16_rn(v.z - __bfloat162float(bz));
    __nv_bfloat16 rw = __float2bfloat16_rn(v.w - __bfloat162float(bw));
    h0 = ((uint32_t)__bfloat16_as_ushort(by) << 16) | __bfloat16_as_ushort(bx);
    h1 = ((uint32_t)__bfloat16_as_ushort(bw) << 16) | __bfloat16_as_ushort(bz);
    l0 = ((uint32_t)__bfloat16_as_ushort(ry) << 16) | __bfloat16_as_ushort(rx);
    l1 = ((uint32_t)__bfloat16_as_ushort(rw) << 16) | __bfloat16_as_ushort(rz);
}

// ------------------------- init ------------------------------------------
__global__ void init_zero() {
    int i = blockIdx.x * 256 + threadIdx.x;
    if (i < 4) g_scal[i] = 0.f;
    if (i < 2 * B_) ((float*)g_rowss)[i] = 0.f;
    if (i < 2 * DHID) { ((float*)g_bns)[i] = 0.f; ((float*)g_bns2)[i] = 0.f; }
}

// column norms of Wc -> 1/max(||col||, 1e-12)
__global__ void wc_inv_kernel(const float* __restrict__ Wc) {
    int c = blockIdx.x * 256 + threadIdx.x;
    if (c >= DCLD) return;
    float s = 0.f;
    for (int r = 0; r < DIN; r++) { float v = Wc[(size_t)r * DCLD + c]; s += v * v; }
    g_wcinv[c] = 1.f / fmaxf(sqrtf(s), 1e-12f);
}

// ------------------------- tensor-core GEMM (bf16 split-precision) -------
// Block tile 128x128x32, 8 warps (warp tile 32x64), double-buffered smem.
// C = A*B with near-fp32 precision: 3 MMAs (hi*hi + hi*lo + lo*hi).
// MODE 0: +bias(aux[col]), scalar stores (C may be only 4-byte aligned!)
// MODE 1: *aux[col] + per-row sumsq atomics (C 16B-aligned internal buffer).
#define APAD 40
#define BPAD 136
#define ASZ  (128 * APAD)
#define BSZ  (32 * BPAD)
#define GEMM_SMEM ((4 * ASZ + 4 * BSZ) * 2)

template<int MODE>
__global__ void __launch_bounds__(256) mma_gemm(
    const float* __restrict__ A, const float* __restrict__ Bm,
    float* __restrict__ C, const float* __restrict__ aux,
    float* __restrict__ rowss, int N, int Kd)
{
    extern __shared__ __nv_bfloat16 smg[];
    __nv_bfloat16* Ah = smg;                     // [2][ASZ]
    __nv_bfloat16* Al = smg + 2 * ASZ;
    __nv_bfloat16* Bh = smg + 4 * ASZ;           // [2][BSZ]
    __nv_bfloat16* Bl = smg + 4 * ASZ + 2 * BSZ;

    const int tid  = threadIdx.x;
    const int lane = tid & 31;
    const int warp = tid >> 5;
    const int wm   = warp >> 1;       // 0..3
    const int wn   = warp & 1;        // 0..1
    const int mBase = blockIdx.y * 128;
    const int nBase = blockIdx.x * 128;

    // gmem load coords
    const int ar  = tid >> 3, ac4 = tid & 7;    // A: 32 rows/iter, 8 float4/row
    const int br  = tid >> 5, bc4 = tid & 31;   // B: 8 rows/iter, 32 float4/row

    // ldmatrix per-lane element offsets (in bf16 units, within a buffer)
    const int l7 = lane & 7;
    const int aRowSel = l7 + ((lane & 8) ? 8 : 0);
    const int aKSel   = (lane & 16) ? 8 : 0;
    uint32_t aoff[2];
#pragma unroll
    for (int i = 0; i < 2; i++)
        aoff[i] = (uint32_t)((wm * 32 + i * 16 + aRowSel) * APAD + aKSel);
    const int bKSel = l7 + ((lane & 8) ? 8 : 0);
    const int bNSel = (lane & 16) ? 8 : 0;
    uint32_t boff[4];
#pragma unroll
    for (int jp = 0; jp < 4; jp++)
        boff[jp] = (uint32_t)(bKSel * BPAD + wn * 64 + jp * 16 + bNSel);

    const uint32_t smBase = (uint32_t)__cvta_generic_to_shared(smg);

    float acc[2][8][4];
#pragma unroll
    for (int i = 0; i < 2; i++)
#pragma unroll
        for (int j = 0; j < 8; j++)
#pragma unroll
            for (int r = 0; r < 4; r++) acc[i][j][r] = 0.f;

    const int nk = Kd >> 5;
    float4 la[4], lb[4];

    // prologue: load+store chunk 0
#pragma unroll
    for (int it = 0; it < 4; it++) {
        la[it] = *(const float4*)(A + (size_t)(mBase + ar + it * 32) * Kd + ac4 * 4);
        lb[it] = *(const float4*)(Bm + (size_t)(br + it * 8) * N + nBase + bc4 * 4);
    }
#pragma unroll
    for (int it = 0; it < 4; it++) {
        uint32_t h0, h1, l0, l1;
        split4(la[it], h0, h1, l0, l1);
        int off = (ar + it * 32) * APAD + ac4 * 4;
        *(uint2*)(Ah + off) = make_uint2(h0, h1);
        *(uint2*)(Al + off) = make_uint2(l0, l1);
        split4(lb[it], h0, h1, l0, l1);
        off = (br + it * 8) * BPAD + bc4 * 4;
        *(uint2*)(Bh + off) = make_uint2(h0, h1);
        *(uint2*)(Bl + off) = make_uint2(l0, l1);
    }
    __syncthreads();

    for (int kt = 0; kt < nk; kt++) {
        // prefetch next chunk to registers
        if (kt + 1 < nk) {
            const int k0 = (kt + 1) * 32;
#pragma unroll
            for (int it = 0; it < 4; it++) {
                la[it] = *(const float4*)(A + (size_t)(mBase + ar + it * 32) * Kd + k0 + ac4 * 4);
                lb[it] = *(const float4*)(Bm + (size_t)(k0 + br + it * 8) * N + nBase + bc4 * 4);
            }
        }
        const int cb = kt & 1;
        const uint32_t ahB = smBase + (uint32_t)(cb * ASZ) * 2u;
        const uint32_t alB = smBase + (uint32_t)((2 * ASZ) + cb * ASZ) * 2u;
        const uint32_t bhB = smBase + (uint32_t)((4 * ASZ) + cb * BSZ) * 2u;
        const uint32_t blB = smBase + (uint32_t)((4 * ASZ) + 2 * BSZ + cb * BSZ) * 2u;

#pragma unroll
        for (int ks = 0; ks < 2; ks++) {
            uint32_t a[2][2][4];
#pragma unroll
            for (int i = 0; i < 2; i++) {
                ldsm_x4(a[i][0], ahB + (aoff[i] + ks * 16) * 2u);
                ldsm_x4(a[i][1], alB + (aoff[i] + ks * 16) * 2u);
            }
            uint32_t b[8][2][2];
#pragma unroll
            for (int jp = 0; jp < 4; jp++) {
                uint32_t t[4];
                ldsm_x4_t(t, bhB + (boff[jp] + ks * 16 * BPAD) * 2u);
                b[2 * jp][0][0] = t[0]; b[2 * jp][0][1] = t[1];
                b[2 * jp + 1][0][0] = t[2]; b[2 * jp + 1][0][1] = t[3];
                ldsm_x4_t(t, blB + (boff[jp] + ks * 16 * BPAD) * 2u);
                b[2 * jp][1][0] = t[0]; b[2 * jp][1][1] = t[1];
                b[2 * jp + 1][1][0] = t[2]; b[2 * jp + 1][1][1] = t[3];
            }
#pragma unroll
            for (int i = 0; i < 2; i++)
#pragma unroll
                for (int j = 0; j < 8; j++) mma16816(acc[i][j], a[i][0], b[j][0]);
#pragma unroll
            for (int i = 0; i < 2; i++)
#pragma unroll
                for (int j = 0; j < 8; j++) mma16816(acc[i][j], a[i][0], b[j][1]);
#pragma unroll
            for (int i = 0; i < 2; i++)
#pragma unroll
                for (int j = 0; j < 8; j++) mma16816(acc[i][j], a[i][1], b[j][0]);
        }

        if (kt + 1 < nk) {
            const int nb = (kt + 1) & 1;
            __nv_bfloat16* AhN = Ah + nb * ASZ;
            __nv_bfloat16* AlN = Al + nb * ASZ;
            __nv_bfloat16* BhN = Bh + nb * BSZ;
            __nv_bfloat16* BlN = Bl + nb * BSZ;
#pragma unroll
            for (int it = 0; it < 4; it++) {
                uint32_t h0, h1, l0, l1;
                split4(la[it], h0, h1, l0, l1);
                int off = (ar + it * 32) * APAD + ac4 * 4;
                *(uint2*)(AhN + off) = make_uint2(h0, h1);
                *(uint2*)(AlN + off) = make_uint2(l0, l1);
                split4(lb[it], h0, h1, l0, l1);
                off = (br + it * 8) * BPAD + bc4 * 4;
                *(uint2*)(BhN + off) = make_uint2(h0, h1);
                *(uint2*)(BlN + off) = make_uint2(l0, l1);
            }
        }
        __syncthreads();
    }

    // epilogue
    const int g  = lane >> 2;
    const int t4 = lane & 3;
#pragma unroll
    for (int i = 0; i < 2; i++) {
        const int r0 = mBase + wm * 32 + i * 16 + g;
        float s0 = 0.f, s1 = 0.f;
#pragma unroll
        for (int j = 0; j < 8; j++) {
            const int n = nBase + wn * 64 + j * 8 + 2 * t4;
            float a0 = aux[n], a1 = aux[n + 1];
            if (MODE == 0) {
                // scalar stores: C may be a 4-byte-aligned-only pointer (out+3)
                float* c0 = C + (size_t)r0 * N + n;
                float* c1 = C + (size_t)(r0 + 8) * N + n;
                c0[0] = acc[i][j][0] + a0;
                c0[1] = acc[i][j][1] + a1;
                c1[0] = acc[i][j][2] + a0;
                c1[1] = acc[i][j][3] + a1;
            } else {
                float v0 = acc[i][j][0] * a0, v1 = acc[i][j][1] * a1;
                float v2 = acc[i][j][2] * a0, v3 = acc[i][j][3] * a1;
                *(float2*)(C + (size_t)r0 * N + n)       = make_float2(v0, v1);
                *(float2*)(C + (size_t)(r0 + 8) * N + n) = make_float2(v2, v3);
                s0 = fmaf(v0, v0, fmaf(v1, v1, s0));
                s1 = fmaf(v2, v2, fmaf(v3, v3, s1));
            }
        }
        if (MODE == 1) {
            s0 += __shfl_xor_sync(0xffffffffu, s0, 1);
            s0 += __shfl_xor_sync(0xffffffffu, s0, 2);
            s1 += __shfl_xor_sync(0xffffffffu, s1, 1);
            s1 += __shfl_xor_sync(0xffffffffu, s1, 2);
            if (t4 == 0) {
                atomicAdd(&rowss[r0], s0);
                atomicAdd(&rowss[r0 + 8], s1);
            }
        }
    }
}

// ------------------------- batchnorm -------------------------------------
__global__ void bn_partial(int view) {
    int c  = blockIdx.x * 256 + threadIdx.x;   // 0..511
    int r0 = blockIdx.y * 256;
    const float* h = g_h[view];
    float s = 0.f, s2 = 0.f;
    for (int r = r0; r < r0 + 256; r++) {
        float v = h[(size_t)r * DHID + c];
        s += v;
        s2 = fmaf(v, v, s2);
    }
    atomicAdd(&g_bns[view][c], s);
    atomicAdd(&g_bns2[view][c], s2);
}

__global__ void bn_finish(int view) {
    int c = blockIdx.x * 256 + threadIdx.x;
    if (c >= DHID) return;
    float m = g_bns[view][c] * (1.f / B_);
    float v = g_bns2[view][c] * (1.f / B_) - m * m;
    g_bnm[view][c]  = m;
    g_bnis[view][c] = rsqrtf(v + 1e-5f);
}

__global__ void bn_relu(int view, const float* __restrict__ gamma,
                        const float* __restrict__ beta) {
    int i = blockIdx.x * 256 + threadIdx.x;
    int c = i & (DHID - 1);
    float h = g_h[view][i];
    float v = fmaf(gamma[c] * (h - g_bnm[view][c]), g_bnis[view][c], beta[c]);
    g_h[view][i] = fmaxf(v, 0.f);
}

// ------------------------- z_L row normalization + copy-out ---------------
__global__ void row_scale(float* __restrict__ z1L_out) {
    const int view = blockIdx.y;
    size_t i4 = (size_t)blockIdx.x * 256 + threadIdx.x;   // float4 index
    float4* z = (float4*)g_zL[view];
    float4 v = z[i4];
    int row = (int)((i4 * 4) >> 10);
    float rs = rsqrtf(g_rowss[view][row]);
    v.x *= rs; v.y *= rs; v.z *= rs; v.w *= rs;
    z[i4] = v;
    if (view == 0) {
        size_t b = i4 * 4;
        z1L_out[b]   = v.x;
        z1L_out[b+1] = v.y;
        z1L_out[b+2] = v.z;
        z1L_out[b+3] = v.w;
    }
}

// ------------------------- cosine(z_H, y_other) mean ----------------------
__global__ void __launch_bounds__(256) cos_kernel(const float* __restrict__ z1H,
                                                  const float* __restrict__ y1,
                                                  const float* __restrict__ y2) {
    const int pair = blockIdx.y;
    const float* a = pair ? g_zH2 : z1H;
    const float* b = pair ? y1 : y2;
    const int tid = threadIdx.x, lane = tid & 31, wid = tid >> 5;
    __shared__ float sw[8];
    float local = 0.f;
    for (int row = blockIdx.x * 8 + wid; row < B_; row += gridDim.x * 8) {
        const float* ar = a + (size_t)row * DOUT;
        const float* br = b + (size_t)row * DOUT;
        float d = 0.f, na = 0.f, nb = 0.f;
        for (int j = lane; j < DOUT; j += 32) {
            float x = ar[j], y = br[j];
            d  = fmaf(x, y, d);
            na = fmaf(x, x, na);
            nb = fmaf(y, y, nb);
        }
#pragma unroll
        for (int o = 16; o; o >>= 1) {
            d  += __shfl_xor_sync(0xffffffffu, d, o);
            na += __shfl_xor_sync(0xffffffffu, na, o);
            nb += __shfl_xor_sync(0xffffffffu, nb, o);
        }
        local += d / (fmaxf(sqrtf(na), 1e-8f) * fmaxf(sqrtf(nb), 1e-8f));
    }
    if (lane == 0) sw[wid] = local;
    __syncthreads();
    if (tid == 0) {
        float s = 0.f;
        for (int i = 0; i < 8; i++) s += sw[i];
        atomicAdd(&g_scal[pair], s);
    }
}

// ------------------------- kmeans -----------------------------------------
__global__ void km_init() {
    const int view = blockIdx.y, k = blockIdx.x, tid = threadIdx.x;
    const float* src = g_zL[view] + (size_t)k * DCLD;
    float p = 0.f;
    for (int j = tid; j < DCLD; j += 256) {
        float v = src[j];
        g_cent[view][k * DCLD + j] = v;
        p = fmaf(v, v, p);
    }
    p = block_reduce_256(p);
    if (tid == 0) g_cn2[view][k] = p;
}

__global__ void km_zero() {
    int i = blockIdx.x * 256 + threadIdx.x;
    if (i < 2 * KC * DCLD) ((float*)g_csum)[i] = 0.f;
    if (i < 2 * KC) ((float*)g_ccnt)[i] = 0.f;
}

__global__ void __launch_bounds__(256) km_assign() {
    extern __shared__ float sm[];
    float* sc   = sm;                  // KC*DCLD centers
    float* ss   = sm + KC * DCLD;      // KC*DCLD segment sums
    float* scnt = ss + KC * DCLD;      // KC
    float* scn2 = scnt + KC;           // KC
    const int view = blockIdx.y;
    const float* z = g_zL[view];
    const int tid = threadIdx.x;
    for (int i = tid; i < KC * DCLD; i += 256) { sc[i] = g_cent[view][i]; ss[i] = 0.f; }
    if (tid < KC) { scnt[tid] = 0.f; scn2[tid] = g_cn2[view][tid]; }
    __syncthreads();
    const int lane = tid & 31, wid = tid >> 5;
    for (int row = blockIdx.x * 8 + wid; row < B_; row += gridDim.x * 8) {
        const float4* xr = (const float4*)(z + (size_t)row * DCLD);
        float dots[KC];
#pragma unroll
        for (int k = 0; k < KC; k++) dots[k] = 0.f;
        for (int j = lane; j < DCLD / 4; j += 32) {
            float4 xv = xr[j];
#pragma unroll
            for (int k = 0; k < KC; k++) {
                float4 cv = *(const float4*)&sc[k * DCLD + 4 * j];
                dots[k] += xv.x * cv.x + xv.y * cv.y + xv.z * cv.z + xv.w * cv.w;
            }
        }
#pragma unroll
        for (int k = 0; k < KC; k++)
#pragma unroll
            for (int o = 16; o; o >>= 1)
                dots[k] += __shfl_xor_sync(0xffffffffu, dots[k], o);
        int bi = 0;
        float bd = scn2[0] - 2.f * dots[0];
#pragma unroll
        for (int k = 1; k < KC; k++) {
            float d = scn2[k] - 2.f * dots[k];
            if (d < bd) { bd = d; bi = k; }   // strict <: first-min like argmin
        }
        if (lane == 0) { g_cl[view][row] = bi; atomicAdd(&scnt[bi], 1.f); }
        float* dst = ss + bi * DCLD;
        const float* xs = z + (size_t)row * DCLD;
        for (int j = lane; j < DCLD; j += 32) atomicAdd(&dst[j], xs[j]);
    }
    __syncthreads();
    for (int i = tid; i < KC * DCLD; i += 256) {
        float v = ss[i];
        if (v != 0.f) atomicAdd(&g_csum[view][i], v);
    }
    if (tid < KC) {
        float v = scnt[tid];
        if (v != 0.f) atomicAdd(&g_ccnt[view][tid], v);
    }
}

__global__ void km_update() {
    const int view = blockIdx.y, k = blockIdx.x, tid = threadIdx.x;
    const float inv = 1.f / fmaxf(g_ccnt[view][k], 1.f);
    float p = 0.f;
    for (int j = tid; j < DCLD; j += 256) {
        float c = g_csum[view][k * DCLD + j] * inv;
        g_cent[view][k * DCLD + j] = c;
        p = fmaf(c, c, p);
    }
    p = block_reduce_256(p);
    if (tid == 0) g_cn2[view][k] = p;
}

// ------------------------- cross entropy ----------------------------------
__global__ void __launch_bounds__(256) ce_kernel() {
    __shared__ float sc[KC * DCLD];
    __shared__ float swarp[8];
    const int view = blockIdx.y;
    const float* z    = g_zL[view];
    const float* cent = g_cent[view ^ 1];
    const int*   lab  = g_cl[view ^ 1];
    const int tid = threadIdx.x;
    for (int i = tid; i < KC * DCLD; i += 256) sc[i] = cent[i];
    __syncthreads();
    const int lane = tid & 31, wid = tid >> 5;
    float local = 0.f;
    const float invT = 1.f / 0.07f;
    for (int row = blockIdx.x * 8 + wid; row < B_; row += gridDim.x * 8) {
        const float4* xr = (const float4*)(z + (size_t)row * DCLD);
        float dots[KC];
#pragma unroll
        for (int k = 0; k < KC; k++) dots[k] = 0.f;
        for (int j = lane; j < DCLD / 4; j += 32) {
            float4 xv = xr[j];
#pragma unroll
            for (int k = 0; k < KC; k++) {
                float4 cv = *(const float4*)&sc[k * DCLD + 4 * j];
                dots[k] += xv.x * cv.x + xv.y * cv.y + xv.z * cv.z + xv.w * cv.w;
            }
        }
#pragma unroll
        for (int k = 0; k < KC; k++)
#pragma unroll
            for (int o = 16; o; o >>= 1)
                dots[k] += __shfl_xor_sync(0xffffffffu, dots[k], o);
        float m = -1e30f;
#pragma unroll
        for (int k = 0; k < KC; k++) { dots[k] *= invT; m = fmaxf(m, dots[k]); }
        float s = 0.f;
#pragma unroll
        for (int k = 0; k < KC; k++) s += expf(dots[k] - m);
        float lse = logf(s) + m;
        local += lse - dots[lab[row]];
    }
    if (lane == 0) swarp[wid] = local;
    __syncthreads();
    if (tid == 0) {
        float s = 0.f;
        for (int i = 0; i < 8; i++) s += swarp[i];
        atomicAdd(&g_scal[2 + view], s);
    }
}

// ------------------------- finalize ---------------------------------------
__global__ void final_kernel(float* __restrict__ out,
                             const float* __restrict__ Lam) {
    if (threadIdx.x == 0) {
        float cos1 = g_scal[0] * (1.f / B_);
        float cos2 = g_scal[1] * (1.f / B_);
        float lss  = 2.f - cos1 - cos2;
        float ce1  = g_scal[2] * (1.f / B_);
        float ce2  = g_scal[3] * (1.f / B_);
        float lcld = 0.5f * (ce1 + ce2);
        out[0] = lss + (*Lam) * lcld;
        out[1] = lss;
        out[2] = lcld;
    }
}

// ------------------------- host launcher ----------------------------------
extern "C" void kernel_launch(void* const* d_in, const int* in_sizes, int n_in,
                              void* d_out, int out_size)
{
    (void)in_sizes; (void)n_in; (void)out_size;
    const float* y1    = (const float*)d_in[0];
    const float* y2    = (const float*)d_in[1];
    const float* Lam   = (const float*)d_in[2];
    const float* W1    = (const float*)d_in[3];
    const float* b1    = (const float*)d_in[4];
    const float* gamma = (const float*)d_in[5];
    const float* beta  = (const float*)d_in[6];
    const float* W2    = (const float*)d_in[7];
    const float* b2    = (const float*)d_in[8];
    const float* Wc    = (const float*)d_in[9];
    float* out = (float*)d_out;
    float* z1H = out + 3;
    float* z1L = out + 3 + (size_t)B_ * DOUT;

    float *p_h = 0, *p_zH2 = 0, *p_zL = 0, *p_wcinv = 0, *p_rowss = 0;
    cudaGetSymbolAddress((void**)&p_h,     g_h);
    cudaGetSymbolAddress((void**)&p_zH2,   g_zH2);
    cudaGetSymbolAddress((void**)&p_zL,    g_zL);
    cudaGetSymbolAddress((void**)&p_wcinv, g_wcinv);
    cudaGetSymbolAddress((void**)&p_rowss, g_rowss);

    const int ASSIGN_SMEM = (2 * KC * DCLD + 2 * KC) * (int)sizeof(float);
    cudaFuncSetAttribute(km_assign, cudaFuncAttributeMaxDynamicSharedMemorySize,
                         ASSIGN_SMEM);
    cudaFuncSetAttribute(mma_gemm<0>, cudaFuncAttributeMaxDynamicSharedMemorySize,
                         GEMM_SMEM);
    cudaFuncSetAttribute(mma_gemm<1>, cudaFuncAttributeMaxDynamicSharedMemorySize,
                         GEMM_SMEM);

    init_zero<<<64, 256>>>();
    wc_inv_kernel<<<DCLD / 256, 256>>>(Wc);

    for (int v = 0; v < 2; v++) {
        const float* y = v ? y2 : y1;
        float* hbuf = p_h + (size_t)v * B_ * DHID;
        mma_gemm<0><<<dim3(DHID / 128, B_ / 128), 256, GEMM_SMEM>>>(
            y, W1, hbuf, b1, 0, DHID, DIN);
        bn_partial<<<dim3(DHID / 256, 32), 256>>>(v);
        bn_finish<<<DHID / 256, 256>>>(v);
        bn_relu<<<(B_ * DHID) / 256, 256>>>(v, gamma, beta);
        mma_gemm<0><<<dim3(DOUT / 128, B_ / 128), 256, GEMM_SMEM>>>(
            hbuf, W2, v ? p_zH2 : z1H, b2, 0, DOUT, DHID);
        mma_gemm<1><<<dim3(DCLD / 128, B_ / 128), 256, GEMM_SMEM>>>(
            y, Wc, p_zL + (size_t)v * B_ * DCLD, p_wcinv,
            p_rowss + (size_t)v * B_, DCLD, DIN);
    }

    row_scale<<<dim3((B_ * DCLD / 4) / 256, 2), 256>>>(z1L);
    cos_kernel<<<dim3(128, 2), 256>>>(z1H, y1, y2);

    km_init<<<dim3(KC, 2), 256>>>();
    for (int it = 0; it < NIT; it++) {
        km_zero<<<80, 256>>>();
        km_assign<<<dim3(64, 2), 256, ASSIGN_SMEM>>>();
        km_update<<<dim3(KC, 2), 256>>>();
    }

    ce_kernel<<<dim3(64, 2), 256>>>();
    final_kernel<<<1, 32>>>(out, Lam);
}

// round 7
// speedup vs baseline: 2.1624x; 2.0237x over previous
#include <cuda_runtime.h>
#include <cuda_bf16.h>
#include <cstdint>

#define B_    8192
#define DIN   2048
#define DHID  512
#define DOUT  2048
#define DCLD  1024
#define KC    10
#define NIT   10

// ------------------------- device scratch (static, no runtime alloc) ------
__device__ float g_h[2][B_*DHID];          // hidden activations fp32 (for BN stats)
__device__ float g_zH2[B_*DOUT];           // z2_H
__device__ float g_zL[2][B_*DCLD];         // aligned internal copies of z1_L/z2_L
__device__ float g_wcinv[DCLD];
__device__ float g_bns[2][DHID];
__device__ float g_bns2[2][DHID];
__device__ float g_bnm[2][DHID];
__device__ float g_bnis[2][DHID];
__device__ float g_rowss[2][B_];
__device__ float g_cent[2][KC*DCLD];
__device__ float g_csum[2][KC*DCLD];
__device__ float g_ccnt[2][KC];
__device__ float g_cn2[2][KC];
__device__ int   g_cl[2][B_];
__device__ float g_scal[4];                // cos1_sum, cos2_sum, ce1_sum, ce2_sum
// pre-split bf16 operands (hi/lo), original layouts (no transpose)
__device__ __nv_bfloat16 g_yh[2][B_*DIN];
__device__ __nv_bfloat16 g_yl[2][B_*DIN];
__device__ __nv_bfloat16 g_hsh[2][B_*DHID];
__device__ __nv_bfloat16 g_hsl[2][B_*DHID];
__device__ __nv_bfloat16 g_w1h[DIN*DHID], g_w1l[DIN*DHID];
__device__ __nv_bfloat16 g_w2h[DHID*DOUT], g_w2l[DHID*DOUT];
__device__ __nv_bfloat16 g_wch[DIN*DCLD], g_wcl[DIN*DCLD];

// ------------------------- helpers ---------------------------------------
__device__ __forceinline__ float block_reduce_256(float v) {
    __shared__ float s[8];
#pragma unroll
    for (int o = 16; o; o >>= 1) v += __shfl_xor_sync(0xffffffffu, v, o);
    if ((threadIdx.x & 31) == 0) s[threadIdx.x >> 5] = v;
    __syncthreads();
    v = (threadIdx.x < 8) ? s[threadIdx.x] : 0.f;
    if (threadIdx.x < 32) {
#pragma unroll
        for (int o = 4; o; o >>= 1) v += __shfl_xor_sync(0xffffffffu, v, o);
    }
    return v;
}

__device__ __forceinline__ void ldsm_x4(uint32_t* r, uint32_t addr) {
    asm volatile("ldmatrix.sync.aligned.m8n8.x4.shared.b16 {%0,%1,%2,%3}, [%4];\n"
        : "=r"(r[0]), "=r"(r[1]), "=r"(r[2]), "=r"(r[3]) : "r"(addr));
}
__device__ __forceinline__ void ldsm_x4_t(uint32_t* r, uint32_t addr) {
    asm volatile("ldmatrix.sync.aligned.m8n8.x4.trans.shared.b16 {%0,%1,%2,%3}, [%4];\n"
        : "=r"(r[0]), "=r"(r[1]), "=r"(r[2]), "=r"(r[3]) : "r"(addr));
}
__device__ __forceinline__ void mma16816(float* c, const uint32_t* a, const uint32_t* b) {
    asm volatile(
        "mma.sync.aligned.m16n8k16.row.col.f32.bf16.bf16.f32 "
        "{%0,%1,%2,%3}, {%4,%5,%6,%7}, {%8,%9}, {%0,%1,%2,%3};\n"
        : "+f"(c[0]), "+f"(c[1]), "+f"(c[2]), "+f"(c[3])
        : "r"(a[0]), "r"(a[1]), "r"(a[2]), "r"(a[3]), "r"(b[0]), "r"(b[1]));
}

#define CP_ASYNC16(dst, src) \
    asm volatile("cp.async.cg.shared.global [%0], [%1], 16;\n" \
        :: "r"(dst), "l"((const void*)(src)))
#define CP_COMMIT() asm volatile("cp.async.commit_group;\n" ::: "memory")
#define CP_WAIT2()  asm volatile("cp.async.wait_group 2;\n" ::: "memory")

__device__ __forceinline__ void split4(float4 v, uint32_t& h0, uint32_t& h1,
                                       uint32_t& l0, uint32_t& l1) {
    __nv_bfloat16 bx = __float2bfloat16_rn(v.x);
    __nv_bfloat16 by = __float2bfloat16_rn(v.y);
    __nv_bfloat16 bz = __float2bfloat16_rn(v.z);
    __nv_bfloat16 bw = __float2bfloat16_rn(v.w);
    __nv_bfloat16 rx = __float2bfloat16_rn(v.x - __bfloat162float(bx));
    __nv_bfloat16 ry = __float2bfloat16_rn(v.y - __bfloat162float(by));
    __nv_bfloat16 rz = __float2bfloat16_rn(v.z - __bfloat162float(bz));
    __nv_bfloat16 rw = __float2bfloat16_rn(v.w - __bfloat162float(bw));
    h0 = ((uint32_t)__bfloat16_as_ushort(by) << 16) | __bfloat16_as_ushort(bx);
    h1 = ((uint32_t)__bfloat16_as_ushort(bw) << 16) | __bfloat16_as_ushort(bz);
    l0 = ((uint32_t)__bfloat16_as_ushort(ry) << 16) | __bfloat16_as_ushort(rx);
    l1 = ((uint32_t)__bfloat16_as_ushort(rw) << 16) | __bfloat16_as_ushort(rz);
}

// ------------------------- init / preprocessing ---------------------------
__global__ void init_zero() {
    int i = blockIdx.x * 256 + threadIdx.x;   // 80 blocks -> 20480 threads
    if (i < 4) g_scal[i] = 0.f;
    if (i < 2 * B_) ((float*)g_rowss)[i] = 0.f;
    if (i < 2 * DHID) { ((float*)g_bns)[i] = 0.f; ((float*)g_bns2)[i] = 0.f; }
    if (i < 2 * KC * DCLD) ((float*)g_csum)[i] = 0.f;
    if (i < 2 * KC) ((float*)g_ccnt)[i] = 0.f;
}

__global__ void wc_inv_kernel(const float* __restrict__ Wc) {
    int c = blockIdx.x * 256 + threadIdx.x;
    if (c >= DCLD) return;
    float s = 0.f;
    for (int r = 0; r < DIN; r++) { float v = Wc[(size_t)r * DCLD + c]; s += v * v; }
    g_wcinv[c] = 1.f / fmaxf(sqrtf(s), 1e-12f);
}

// elementwise fp32 -> bf16 hi/lo split (keeps layout)
__global__ void split_fp32(const float4* __restrict__ src,
                           uint2* __restrict__ hi, uint2* __restrict__ lo, int n4) {
    int i = blockIdx.x * 256 + threadIdx.x;
    if (i >= n4) return;
    float4 v = src[i];
    uint32_t h0, h1, l0, l1;
    split4(v, h0, h1, l0, l1);
    hi[i] = make_uint2(h0, h1);
    lo[i] = make_uint2(l0, l1);
}

// ------------------------- pipelined mma.sync GEMM ------------------------
// Block 128x128, 8 warps (warp 32x64), K-chunks of 32, 4-stage cp.async ring.
// All operands pre-split bf16 hi/lo in gmem (A:[M][K], B:[K][N]).
// 3-pass split precision: hi*hi + hi*lo + lo*hi, fp32 accumulate.
// MODE 0: C = A*B + aux[col]   (scalar stores: C may be only 4B-aligned)
// MODE 1: C = (A*B)*aux[col] + per-row sumsq atomics into rowss.
#define APAD 40            // A smem row: 32 k + 8 pad (elems); 80 B/row
#define BPAD 136           // B smem row: 128 n + 8 pad (elems); 272 B/row
#define STG_A 10240        // 128*APAD*2 bytes (one of hi/lo)
#define STG_B 8704         // 32*BPAD*2 bytes
#define STAGE 37888        // 2*STG_A + 2*STG_B
#define NSTG  4
#define GEMM_SMEM (NSTG * STAGE)

template<int MODE>
__global__ void __launch_bounds__(256) mma_gemm(
    const __nv_bfloat16* __restrict__ Ah0, const __nv_bfloat16* __restrict__ Al0,
    const __nv_bfloat16* __restrict__ Ah1, const __nv_bfloat16* __restrict__ Al1,
    float* __restrict__ C0, float* __restrict__ C1,
    const __nv_bfloat16* __restrict__ Bh_g, const __nv_bfloat16* __restrict__ Bl_g,
    const float* __restrict__ aux,
    float* __restrict__ rowss0, float* __restrict__ rowss1,
    int N, int Kd)
{
    extern __shared__ char smc[];
    const int tid  = threadIdx.x;
    const int lane = tid & 31;
    const int warp = tid >> 5;
    const int wm   = warp >> 1;       // 0..3
    const int wn   = warp & 1;        // 0..1
    const int mBase = blockIdx.y * 128;
    const int nBase = blockIdx.x * 128;
    const __nv_bfloat16* Ah_g = blockIdx.z ? Ah1 : Ah0;
    const __nv_bfloat16* Al_g = blockIdx.z ? Al1 : Al0;
    float* C     = blockIdx.z ? C1 : C0;
    float* rowss = blockIdx.z ? rowss1 : rowss0;

    const uint32_t sb = (uint32_t)__cvta_generic_to_shared(smc);

    // cp.async coords (per thread, 8 x 16B per chunk)
    const int arow = tid >> 2, aseg = tid & 3;      // + i*64 rows (i=0,1)
    const int brow = tid >> 4, bseg = tid & 15;     // + i*16 rows

    // ldmatrix per-lane element offsets
    const int l7 = lane & 7;
    const int aRowSel = l7 + ((lane & 8) ? 8 : 0);
    const int aKSel   = (lane & 16) ? 8 : 0;
    uint32_t aoff[2];
#pragma unroll
    for (int i = 0; i < 2; i++)
        aoff[i] = (uint32_t)((wm * 32 + i * 16 + aRowSel) * APAD + aKSel);
    const int bKSel = l7 + ((lane & 8) ? 8 : 0);
    const int bNSel = (lane & 16) ? 8 : 0;
    uint32_t boff[4];
#pragma unroll
    for (int jp = 0; jp < 4; jp++)
        boff[jp] = (uint32_t)(bKSel * BPAD + wn * 64 + jp * 16 + bNSel);

    float acc[2][8][4];
#pragma unroll
    for (int i = 0; i < 2; i++)
#pragma unroll
        for (int j = 0; j < 8; j++)
#pragma unroll
            for (int r = 0; r < 4; r++) acc[i][j][r] = 0.f;

    const int nk = Kd >> 5;

#define LOAD_CHUNK(kt, s) do { \
    const int _k0 = (kt) * 32; \
    const uint32_t _st = sb + (uint32_t)(s) * STAGE; \
    _Pragma("unroll") \
    for (int _i = 0; _i < 2; _i++) { \
        int _ar = arow + _i * 64; \
        const __nv_bfloat16* _ga = Ah_g + (size_t)(mBase + _ar) * Kd + _k0 + aseg * 8; \
        CP_ASYNC16(_st + _ar * 80 + aseg * 16, _ga); \
        const __nv_bfloat16* _gal = Al_g + (size_t)(mBase + _ar) * Kd + _k0 + aseg * 8; \
        CP_ASYNC16(_st + STG_A + _ar * 80 + aseg * 16, _gal); \
        int _br = brow + _i * 16; \
        const __nv_bfloat16* _gb = Bh_g + (size_t)(_k0 + _br) * N + nBase + bseg * 8; \
        CP_ASYNC16(_st + 2 * STG_A + _br * 272 + bseg * 16, _gb); \
        const __nv_bfloat16* _gbl = Bl_g + (size_t)(_k0 + _br) * N + nBase + bseg * 8; \
        CP_ASYNC16(_st + 2 * STG_A + STG_B + _br * 272 + bseg * 16, _gbl); \
    } \
    CP_COMMIT(); \
} while (0)

    LOAD_CHUNK(0, 0);
    LOAD_CHUNK(1, 1);
    LOAD_CHUNK(2, 2);

    for (int kt = 0; kt < nk; kt++) {
        CP_WAIT2();
        __syncthreads();
        if (kt + 3 < nk) LOAD_CHUNK(kt + 3, (kt + 3) & 3);

        const uint32_t st  = sb + (uint32_t)(kt & 3) * STAGE;
        const uint32_t ahB = st;
        const uint32_t alB = st + STG_A;
        const uint32_t bhB = st + 2 * STG_A;
        const uint32_t blB = st + 2 * STG_A + STG_B;
#pragma unroll
        for (int ks = 0; ks < 2; ks++) {
            uint32_t a[2][2][4];
#pragma unroll
            for (int i = 0; i < 2; i++) {
                ldsm_x4(a[i][0], ahB + (aoff[i] + ks * 16) * 2u);
                ldsm_x4(a[i][1], alB + (aoff[i] + ks * 16) * 2u);
            }
            uint32_t b[8][2][2];
#pragma unroll
            for (int jp = 0; jp < 4; jp++) {
                uint32_t t[4];
                ldsm_x4_t(t, bhB + (boff[jp] + ks * 16 * BPAD) * 2u);
                b[2 * jp][0][0] = t[0]; b[2 * jp][0][1] = t[1];
                b[2 * jp + 1][0][0] = t[2]; b[2 * jp + 1][0][1] = t[3];
                ldsm_x4_t(t, blB + (boff[jp] + ks * 16 * BPAD) * 2u);
                b[2 * jp][1][0] = t[0]; b[2 * jp][1][1] = t[1];
                b[2 * jp + 1][1][0] = t[2]; b[2 * jp + 1][1][1] = t[3];
            }
#pragma unroll
            for (int i = 0; i < 2; i++)
#pragma unroll
                for (int j = 0; j < 8; j++) mma16816(acc[i][j], a[i][0], b[j][0]);
#pragma unroll
            for (int i = 0; i < 2; i++)
#pragma unroll
                for (int j = 0; j < 8; j++) mma16816(acc[i][j], a[i][0], b[j][1]);
#pragma unroll
            for (int i = 0; i < 2; i++)
#pragma unroll
                for (int j = 0; j < 8; j++) mma16816(acc[i][j], a[i][1], b[j][0]);
        }
        __syncthreads();
    }

    // epilogue
    const int g  = lane >> 2;
    const int t4 = lane & 3;
#pragma unroll
    for (int i = 0; i < 2; i++) {
        const int r0 = mBase + wm * 32 + i * 16 + g;
        float s0 = 0.f, s1 = 0.f;
#pragma unroll
        for (int j = 0; j < 8; j++) {
            const int n = nBase + wn * 64 + j * 8 + 2 * t4;
            float a0 = aux[n], a1 = aux[n + 1];
            if (MODE == 0) {
                float* c0 = C + (size_t)r0 * N + n;
                float* c1 = C + (size_t)(r0 + 8) * N + n;
                c0[0] = acc[i][j][0] + a0;
                c0[1] = acc[i][j][1] + a1;
                c1[0] = acc[i][j][2] + a0;
                c1[1] = acc[i][j][3] + a1;
            } else {
                float v0 = acc[i][j][0] * a0, v1 = acc[i][j][1] * a1;
                float v2 = acc[i][j][2] * a0, v3 = acc[i][j][3] * a1;
                *(float2*)(C + (size_t)r0 * N + n)       = make_float2(v0, v1);
                *(float2*)(C + (size_t)(r0 + 8) * N + n) = make_float2(v2, v3);
                s0 = fmaf(v0, v0, fmaf(v1, v1, s0));
                s1 = fmaf(v2, v2, fmaf(v3, v3, s1));
            }
        }
        if (MODE == 1) {
            s0 += __shfl_xor_sync(0xffffffffu, s0, 1);
            s0 += __shfl_xor_sync(0xffffffffu, s0, 2);
            s1 += __shfl_xor_sync(0xffffffffu, s1, 1);
            s1 += __shfl_xor_sync(0xffffffffu, s1, 2);
            if (t4 == 0) {
                atomicAdd(&rowss[r0], s0);
                atomicAdd(&rowss[r0 + 8], s1);
            }
        }
    }
#undef LOAD_CHUNK
}

// ------------------------- batchnorm --------------------------------------
__global__ void bn_partial(int view) {
    int c  = blockIdx.x * 256 + threadIdx.x;
    int r0 = blockIdx.y * 256;
    const float* h = g_h[view];
    float s = 0.f, s2 = 0.f;
    for (int r = r0; r < r0 + 256; r++) {
        float v = h[(size_t)r * DHID + c];
        s += v;
        s2 = fmaf(v, v, s2);
    }
    atomicAdd(&g_bns[view][c], s);
    atomicAdd(&g_bns2[view][c], s2);
}

__global__ void bn_finish(int view) {
    int c = blockIdx.x * 256 + threadIdx.x;
    if (c >= DHID) return;
    float m = g_bns[view][c] * (1.f / B_);
    float v = g_bns2[view][c] * (1.f / B_) - m * m;
    g_bnm[view][c]  = m;
    g_bnis[view][c] = rsqrtf(v + 1e-5f);
}

// BN+relu, emits bf16 hi/lo split of the activation for GEMM2
__global__ void bn_relu(int view, const float* __restrict__ gamma,
                        const float* __restrict__ beta) {
    int i = blockIdx.x * 256 + threadIdx.x;
    int c = i & (DHID - 1);
    float h = g_h[view][i];
    float v = fmaf(gamma[c] * (h - g_bnm[view][c]), g_bnis[view][c], beta[c]);
    v = fmaxf(v, 0.f);
    __nv_bfloat16 hi = __float2bfloat16_rn(v);
    __nv_bfloat16 lo = __float2bfloat16_rn(v - __bfloat162float(hi));
    g_hsh[view][i] = hi;
    g_hsl[view][i] = lo;
}

// ------------------------- z_L row normalization + copy-out ---------------
__global__ void row_scale(float* __restrict__ z1L_out) {
    const int view = blockIdx.y;
    size_t i4 = (size_t)blockIdx.x * 256 + threadIdx.x;
    float4* z = (float4*)g_zL[view];
    float4 v = z[i4];
    int row = (int)((i4 * 4) >> 10);
    float rs = rsqrtf(g_rowss[view][row]);
    v.x *= rs; v.y *= rs; v.z *= rs; v.w *= rs;
    z[i4] = v;
    if (view == 0) {
        size_t b = i4 * 4;
        z1L_out[b]   = v.x;
        z1L_out[b+1] = v.y;
        z1L_out[b+2] = v.z;
        z1L_out[b+3] = v.w;
    }
}

// ------------------------- cosine(z_H, y_other) mean ----------------------
__global__ void __launch_bounds__(256) cos_kernel(const float* __restrict__ z1H,
                                                  const float* __restrict__ y1,
                                                  const float* __restrict__ y2) {
    const int pair = blockIdx.y;
    const float* a = pair ? g_zH2 : z1H;
    const float* b = pair ? y1 : y2;
    const int tid = threadIdx.x, lane = tid & 31, wid = tid >> 5;
    __shared__ float sw[8];
    float local = 0.f;
    for (int row = blockIdx.x * 8 + wid; row < B_; row += gridDim.x * 8) {
        const float* ar = a + (size_t)row * DOUT;
        const float* br = b + (size_t)row * DOUT;
        float d = 0.f, na = 0.f, nb = 0.f;
        for (int j = lane; j < DOUT; j += 32) {
            float x = ar[j], y = br[j];
            d  = fmaf(x, y, d);
            na = fmaf(x, x, na);
            nb = fmaf(y, y, nb);
        }
#pragma unroll
        for (int o = 16; o; o >>= 1) {
            d  += __shfl_xor_sync(0xffffffffu, d, o);
            na += __shfl_xor_sync(0xffffffffu, na, o);
            nb += __shfl_xor_sync(0xffffffffu, nb, o);
        }
        local += d / (fmaxf(sqrtf(na), 1e-8f) * fmaxf(sqrtf(nb), 1e-8f));
    }
    if (lane == 0) sw[wid] = local;
    __syncthreads();
    if (tid == 0) {
        float s = 0.f;
        for (int i = 0; i < 8; i++) s += sw[i];
        atomicAdd(&g_scal[pair], s);
    }
}

// ------------------------- kmeans ------------------------------------------
__global__ void km_init() {
    const int view = blockIdx.y, k = blockIdx.x, tid = threadIdx.x;
    const float* src = g_zL[view] + (size_t)k * DCLD;
    float p = 0.f;
    for (int j = tid; j < DCLD; j += 256) {
        float v = src[j];
        g_cent[view][k * DCLD + j] = v;
        p = fmaf(v, v, p);
    }
    p = block_reduce_256(p);
    if (tid == 0) g_cn2[view][k] = p;
}

// labels + counts only (no per-element atomics)
__global__ void __launch_bounds__(256) km_labels() {
    __shared__ float sc[KC * DCLD];
    __shared__ float scn2[KC];
    __shared__ int   scnt[KC];
    const int view = blockIdx.y;
    const float* z = g_zL[view];
    const int tid = threadIdx.x;
    for (int i = tid; i < KC * DCLD; i += 256) sc[i] = g_cent[view][i];
    if (tid < KC) { scn2[tid] = g_cn2[view][tid]; scnt[tid] = 0; }
    __syncthreads();
    const int lane = tid & 31, wid = tid >> 5;
    for (int row = blockIdx.x * 8 + wid; row < B_; row += gridDim.x * 8) {
        const float4* xr = (const float4*)(z + (size_t)row * DCLD);
        float dots[KC];
#pragma unroll
        for (int k = 0; k < KC; k++) dots[k] = 0.f;
        for (int j = lane; j < DCLD / 4; j += 32) {
            float4 xv = xr[j];
#pragma unroll
            for (int k = 0; k < KC; k++) {
                float4 cv = *(const float4*)&sc[k * DCLD + 4 * j];
                dots[k] += xv.x * cv.x + xv.y * cv.y + xv.z * cv.z + xv.w * cv.w;
            }
        }
#pragma unroll
        for (int k = 0; k < KC; k++)
#pragma unroll
            for (int o = 16; o; o >>= 1)
                dots[k] += __shfl_xor_sync(0xffffffffu, dots[k], o);
        int bi = 0;
        float bd = scn2[0] - 2.f * dots[0];
#pragma unroll
        for (int k = 1; k < KC; k++) {
            float d = scn2[k] - 2.f * dots[k];
            if (d < bd) { bd = d; bi = k; }   // strict <: first-min like argmin
        }
        if (lane == 0) { g_cl[view][row] = bi; atomicAdd(&scnt[bi], 1); }
    }
    __syncthreads();
    if (tid < KC) atomicAdd(&g_ccnt[view][tid], (float)scnt[tid]);
}

// column-owned segment sum: no smem atomics, 2-way banked accumulators
__global__ void __launch_bounds__(256) km_segsum() {
    __shared__ float sacc[2][KC][256];
    __shared__ int   slab[256];
    const int view = blockIdx.z;
    const int tid = threadIdx.x;
    const int c  = blockIdx.x * 256 + tid;
    const int r0 = blockIdx.y * 256;
#pragma unroll
    for (int k = 0; k < KC; k++) { sacc[0][k][tid] = 0.f; sacc[1][k][tid] = 0.f; }
    slab[tid] = g_cl[view][r0 + tid];
    __syncthreads();
    const float* z = g_zL[view] + (size_t)r0 * DCLD + c;
#pragma unroll 8
    for (int i = 0; i < 256; i += 2) {
        sacc[0][slab[i]][tid]     += z[(size_t)i * DCLD];
        sacc[1][slab[i + 1]][tid] += z[(size_t)(i + 1) * DCLD];
    }
#pragma unroll
    for (int k = 0; k < KC; k++)
        atomicAdd(&g_csum[view][k * DCLD + c], sacc[0][k][tid] + sacc[1][k][tid]);
}

// update centers; re-zero csum/ccnt for the next iteration (replaces km_zero)
__global__ void km_update() {
    const int view = blockIdx.y, k = blockIdx.x, tid = threadIdx.x;
    const float inv = 1.f / fmaxf(g_ccnt[view][k], 1.f);
    float p = 0.f;
    for (int j = tid; j < DCLD; j += 256) {
        float c = g_csum[view][k * DCLD + j];
        g_csum[view][k * DCLD + j] = 0.f;
        c *= inv;
        g_cent[view][k * DCLD + j] = c;
        p = fmaf(c, c, p);
    }
    p = block_reduce_256(p);
    if (tid == 0) { g_cn2[view][k] = p; g_ccnt[view][k] = 0.f; }
}

// ------------------------- cross entropy -----------------------------------
__global__ void __launch_bounds__(256) ce_kernel() {
    __shared__ float sc[KC * DCLD];
    __shared__ float swarp[8];
    const int view = blockIdx.y;
    const float* z    = g_zL[view];
    const float* cent = g_cent[view ^ 1];
    const int*   lab  = g_cl[view ^ 1];
    const int tid = threadIdx.x;
    for (int i = tid; i < KC * DCLD; i += 256) sc[i] = cent[i];
    __syncthreads();
    const int lane = tid & 31, wid = tid >> 5;
    float local = 0.f;
    const float invT = 1.f / 0.07f;
    for (int row = blockIdx.x * 8 + wid; row < B_; row += gridDim.x * 8) {
        const float4* xr = (const float4*)(z + (size_t)row * DCLD);
        float dots[KC];
#pragma unroll
        for (int k = 0; k < KC; k++) dots[k] = 0.f;
        for (int j = lane; j < DCLD / 4; j += 32) {
            float4 xv = xr[j];
#pragma unroll
            for (int k = 0; k < KC; k++) {
                float4 cv = *(const float4*)&sc[k * DCLD + 4 * j];
                dots[k] += xv.x * cv.x + xv.y * cv.y + xv.z * cv.z + xv.w * cv.w;
            }
        }
#pragma unroll
        for (int k = 0; k < KC; k++)
#pragma unroll
            for (int o = 16; o; o >>= 1)
                dots[k] += __shfl_xor_sync(0xffffffffu, dots[k], o);
        float m = -1e30f;
#pragma unroll
        for (int k = 0; k < KC; k++) { dots[k] *= invT; m = fmaxf(m, dots[k]); }
        float s = 0.f;
#pragma unroll
        for (int k = 0; k < KC; k++) s += expf(dots[k] - m);
        float lse = logf(s) + m;
        local += lse - dots[lab[row]];
    }
    if (lane == 0) swarp[wid] = local;
    __syncthreads();
    if (tid == 0) {
        float s = 0.f;
        for (int i = 0; i < 8; i++) s += swarp[i];
        atomicAdd(&g_scal[2 + view], s);
    }
}

// ------------------------- finalize ----------------------------------------
__global__ void final_kernel(float* __restrict__ out,
                             const float* __restrict__ Lam) {
    if (threadIdx.x == 0) {
        float cos1 = g_scal[0] * (1.f / B_);
        float cos2 = g_scal[1] * (1.f / B_);
        float lss  = 2.f - cos1 - cos2;
        float ce1  = g_scal[2] * (1.f / B_);
        float ce2  = g_scal[3] * (1.f / B_);
        float lcld = 0.5f * (ce1 + ce2);
        out[0] = lss + (*Lam) * lcld;
        out[1] = lss;
        out[2] = lcld;
    }
}

// ------------------------- host launcher -----------------------------------
extern "C" void kernel_launch(void* const* d_in, const int* in_sizes, int n_in,
                              void* d_out, int out_size)
{
    (void)in_sizes; (void)n_in; (void)out_size;
    const float* y1    = (const float*)d_in[0];
    const float* y2    = (const float*)d_in[1];
    const float* Lam   = (const float*)d_in[2];
    const float* W1    = (const float*)d_in[3];
    const float* b1    = (const float*)d_in[4];
    const float* gamma = (const float*)d_in[5];
    const float* beta  = (const float*)d_in[6];
    const float* W2    = (const float*)d_in[7];
    const float* b2    = (const float*)d_in[8];
    const float* Wc    = (const float*)d_in[9];
    float* out = (float*)d_out;
    float* z1H = out + 3;
    float* z1L = out + 3 + (size_t)B_ * DOUT;

    float *p_h = 0, *p_zH2 = 0, *p_zL = 0, *p_wcinv = 0, *p_rowss = 0;
    __nv_bfloat16 *p_yh = 0, *p_yl = 0, *p_hsh = 0, *p_hsl = 0;
    __nv_bfloat16 *p_w1h = 0, *p_w1l = 0, *p_w2h = 0, *p_w2l = 0, *p_wch = 0, *p_wcl = 0;
    cudaGetSymbolAddress((void**)&p_h,     g_h);
    cudaGetSymbolAddress((void**)&p_zH2,   g_zH2);
    cudaGetSymbolAddress((void**)&p_zL,    g_zL);
    cudaGetSymbolAddress((void**)&p_wcinv, g_wcinv);
    cudaGetSymbolAddress((void**)&p_rowss, g_rowss);
    cudaGetSymbolAddress((void**)&p_yh,    g_yh);
    cudaGetSymbolAddress((void**)&p_yl,    g_yl);
    cudaGetSymbolAddress((void**)&p_hsh,   g_hsh);
    cudaGetSymbolAddress((void**)&p_hsl,   g_hsl);
    cudaGetSymbolAddress((void**)&p_w1h,   g_w1h);
    cudaGetSymbolAddress((void**)&p_w1l,   g_w1l);
    cudaGetSymbolAddress((void**)&p_w2h,   g_w2h);
    cudaGetSymbolAddress((void**)&p_w2l,   g_w2l);
    cudaGetSymbolAddress((void**)&p_wch,   g_wch);
    cudaGetSymbolAddress((void**)&p_wcl,   g_wcl);

    cudaFuncSetAttribute(mma_gemm<0>, cudaFuncAttributeMaxDynamicSharedMemorySize,
                         GEMM_SMEM);
    cudaFuncSetAttribute(mma_gemm<1>, cudaFuncAttributeMaxDynamicSharedMemorySize,
                         GEMM_SMEM);

    const int NY4 = B_ * DIN / 4;

    init_zero<<<80, 256>>>();                                    // 1
    wc_inv_kernel<<<DCLD / 256, 256>>>(Wc);                      // 2
    split_fp32<<<NY4 / 256, 256>>>((const float4*)y1,
        (uint2*)p_yh, (uint2*)p_yl, NY4);                        // 3
    split_fp32<<<NY4 / 256, 256>>>((const float4*)y2,
        (uint2*)(p_yh + (size_t)B_ * DIN),
        (uint2*)(p_yl + (size_t)B_ * DIN), NY4);                 // 4
    split_fp32<<<(DIN * DHID / 4) / 256, 256>>>((const float4*)W1,
        (uint2*)p_w1h, (uint2*)p_w1l, DIN * DHID / 4);           // 5

    // GEMM1: h = y @ W1 + b1 (both views via z-dim) -- ncu capture slot 6
    mma_gemm<0><<<dim3(DHID / 128, B_ / 128, 2), 256, GEMM_SMEM>>>(
        p_yh, p_yl, p_yh + (size_t)B_ * DIN, p_yl + (size_t)B_ * DIN,
        p_h, p_h + (size_t)B_ * DHID,
        p_w1h, p_w1l, b1, 0, 0, DHID, DIN);                      // 6

    split_fp32<<<(DHID * DOUT / 4) / 256, 256>>>((const float4*)W2,
        (uint2*)p_w2h, (uint2*)p_w2l, DHID * DOUT / 4);
    split_fp32<<<(DIN * DCLD / 4) / 256, 256>>>((const float4*)Wc,
        (uint2*)p_wch, (uint2*)p_wcl, DIN * DCLD / 4);

    for (int v = 0; v < 2; v++) bn_partial<<<dim3(DHID / 256, 32), 256>>>(v);
    for (int v = 0; v < 2; v++) bn_finish<<<DHID / 256, 256>>>(v);
    for (int v = 0; v < 2; v++) bn_relu<<<(B_ * DHID) / 256, 256>>>(v, gamma, beta);

    // GEMM2: z_H = relu_h @ W2 + b2
    mma_gemm<0><<<dim3(DOUT / 128, B_ / 128, 2), 256, GEMM_SMEM>>>(
        p_hsh, p_hsl, p_hsh + (size_t)B_ * DHID, p_hsl + (size_t)B_ * DHID,
        z1H, p_zH2,
        p_w2h, p_w2l, b2, 0, 0, DOUT, DHID);

    // GEMM3: z_L_pre = (y @ Wc) * wcinv  (+ row sumsq)
    mma_gemm<1><<<dim3(DCLD / 128, B_ / 128, 2), 256, GEMM_SMEM>>>(
        p_yh, p_yl, p_yh + (size_t)B_ * DIN, p_yl + (size_t)B_ * DIN,
        p_zL, p_zL + (size_t)B_ * DCLD,
        p_wch, p_wcl, p_wcinv, p_rowss, p_rowss + B_, DCLD, DIN);

    row_scale<<<dim3((B_ * DCLD / 4) / 256, 2), 256>>>(z1L);
    cos_kernel<<<dim3(128, 2), 256>>>(z1H, y1, y2);

    km_init<<<dim3(KC, 2), 256>>>();
    for (int it = 0; it < NIT; it++) {
        km_labels<<<dim3(64, 2), 256>>>();
        km_segsum<<<dim3(DCLD / 256, B_ / 256, 2), 256>>>();
        km_update<<<dim3(KC, 2), 256>>>();
    }

    ce_kernel<<<dim3(64, 2), 256>>>();
    final_kernel<<<1, 32>>>(out, Lam);
}

// round 10
// speedup vs baseline: 2.6409x; 1.2213x over previous
#include <cuda_runtime.h>
#include <cuda_fp16.h>
#include <cstdint>

#define B_    8192
#define DIN   2048
#define DHID  512
#define DOUT  2048
#define DCLD  1024
#define KC    10
#define NIT   10

// ------------------------- device scratch (static, no runtime alloc) ------
__device__ float g_h[2][B_*DHID];          // hidden activations fp32 (for BN stats)
__device__ float g_zH2[B_*DOUT];           // z2_H
__device__ float g_zL[2][B_*DCLD];         // aligned internal copies of z1_L/z2_L
__device__ float g_wcinv[DCLD];
__device__ float g_bns[2][DHID];
__device__ float g_bns2[2][DHID];
__device__ float g_bnm[2][DHID];
__device__ float g_bnis[2][DHID];
__device__ float g_rowss[2][B_];
__device__ float g_cent[2][KC*DCLD];
__device__ float g_csum[2][KC*DCLD];
__device__ float g_ccnt[2][KC];
__device__ float g_cn2[2][KC];
__device__ int   g_cl[2][B_];
__device__ float g_scal[4];                // cos1_sum, cos2_sum, ce1_sum, ce2_sum
// fp16 operands: A single-precision-split-free (fp16), B split hi/lo
__device__ __half g_yf[2][B_*DIN];         // y views, fp16
__device__ __half g_hf[2][B_*DHID];        // relu(bn(h)), fp16
__device__ __half g_w1h[DIN*DHID], g_w1l[DIN*DHID];
__device__ __half g_w2h[DHID*DOUT], g_w2l[DHID*DOUT];
__device__ __half g_wch[DIN*DCLD], g_wcl[DIN*DCLD];

// ------------------------- helpers ---------------------------------------
__device__ __forceinline__ float block_reduce_256(float v) {
    __shared__ float s[8];
#pragma unroll
    for (int o = 16; o; o >>= 1) v += __shfl_xor_sync(0xffffffffu, v, o);
    if ((threadIdx.x & 31) == 0) s[threadIdx.x >> 5] = v;
    __syncthreads();
    v = (threadIdx.x < 8) ? s[threadIdx.x] : 0.f;
    if (threadIdx.x < 32) {
#pragma unroll
        for (int o = 4; o; o >>= 1) v += __shfl_xor_sync(0xffffffffu, v, o);
    }
    return v;
}

__device__ __forceinline__ void ldsm_x4(uint32_t* r, uint32_t addr) {
    asm volatile("ldmatrix.sync.aligned.m8n8.x4.shared.b16 {%0,%1,%2,%3}, [%4];\n"
        : "=r"(r[0]), "=r"(r[1]), "=r"(r[2]), "=r"(r[3]) : "r"(addr));
}
__device__ __forceinline__ void ldsm_x4_t(uint32_t* r, uint32_t addr) {
    asm volatile("ldmatrix.sync.aligned.m8n8.x4.trans.shared.b16 {%0,%1,%2,%3}, [%4];\n"
        : "=r"(r[0]), "=r"(r[1]), "=r"(r[2]), "=r"(r[3]) : "r"(addr));
}
__device__ __forceinline__ void mma16816h(float* c, const uint32_t* a, const uint32_t* b) {
    asm volatile(
        "mma.sync.aligned.m16n8k16.row.col.f32.f16.f16.f32 "
        "{%0,%1,%2,%3}, {%4,%5,%6,%7}, {%8,%9}, {%0,%1,%2,%3};\n"
        : "+f"(c[0]), "+f"(c[1]), "+f"(c[2]), "+f"(c[3])
        : "r"(a[0]), "r"(a[1]), "r"(a[2]), "r"(a[3]), "r"(b[0]), "r"(b[1]));
}

#define CP_ASYNC16(dst, src) \
    asm volatile("cp.async.cg.shared.global [%0], [%1], 16;\n" \
        :: "r"(dst), "l"((const void*)(src)))
#define CP_COMMIT() asm volatile("cp.async.commit_group;\n" ::: "memory")
#define CP_WAIT3()  asm volatile("cp.async.wait_group 3;\n" ::: "memory")

__device__ __forceinline__ uint32_t packh2(float a, float b) {
    __half ha = __float2half_rn(a), hb = __float2half_rn(b);
    return ((uint32_t)__half_as_ushort(hb) << 16) | (uint32_t)__half_as_ushort(ha);
}

// ------------------------- init / preprocessing ---------------------------
__global__ void init_zero() {
    int i = blockIdx.x * 256 + threadIdx.x;   // 80 blocks -> 20480 threads
    if (i < 4) g_scal[i] = 0.f;
    if (i < 2 * B_) ((float*)g_rowss)[i] = 0.f;
    if (i < 2 * DHID) { ((float*)g_bns)[i] = 0.f; ((float*)g_bns2)[i] = 0.f; }
    if (i < 2 * KC * DCLD) ((float*)g_csum)[i] = 0.f;
    if (i < 2 * KC) ((float*)g_ccnt)[i] = 0.f;
}

__global__ void wc_inv_kernel(const float* __restrict__ Wc) {
    int c = blockIdx.x * 256 + threadIdx.x;
    if (c >= DCLD) return;
    float s = 0.f;
    for (int r = 0; r < DIN; r++) { float v = Wc[(size_t)r * DCLD + c]; s += v * v; }
    g_wcinv[c] = 1.f / fmaxf(sqrtf(s), 1e-12f);
}

// fp32 -> fp16 (A operands)
__global__ void conv_fp16(const float4* __restrict__ src, uint2* __restrict__ dst, int n4) {
    int i = blockIdx.x * 256 + threadIdx.x;
    if (i >= n4) return;
    float4 v = src[i];
    dst[i] = make_uint2(packh2(v.x, v.y), packh2(v.z, v.w));
}

// fp32 -> fp16 hi/lo split (B operands / weights)
__global__ void split_w16(const float4* __restrict__ src,
                          uint2* __restrict__ hi, uint2* __restrict__ lo, int n4) {
    int i = blockIdx.x * 256 + threadIdx.x;
    if (i >= n4) return;
    float4 v = src[i];
    __half hx = __float2half_rn(v.x), hy = __float2half_rn(v.y);
    __half hz = __float2half_rn(v.z), hw = __float2half_rn(v.w);
    hi[i] = make_uint2(
        ((uint32_t)__half_as_ushort(hy) << 16) | __half_as_ushort(hx),
        ((uint32_t)__half_as_ushort(hw) << 16) | __half_as_ushort(hz));
    lo[i] = make_uint2(
        packh2(v.x - __half2float(hx), v.y - __half2float(hy)),
        packh2(v.z - __half2float(hz), v.w - __half2float(hw)));
}

// ------------------------- pipelined mma.sync GEMM ------------------------
// Block 128x128, 8 warps (warp 32x64), K-chunks of 32, 5-stage cp.async ring
// with ONE __syncthreads per chunk. A fp16 single, B fp16 hi/lo => 2 passes:
// C = A*Bhi + A*Blo  (B rounding error ~2^-22; A rounding ~1.4e-4 rel RMS).
// MODE 0: C = A*B + aux[col]   (scalar stores: C may be only 4B-aligned)
// MODE 1: C = (A*B)*aux[col] + per-row sumsq atomics into rowss.
#define APAD 40            // A smem row: 32 k + 8 pad halfs; 80 B/row
#define BPAD 136           // B smem row: 128 n + 8 pad halfs; 272 B/row
#define ST_A 10240         // 128*APAD*2
#define ST_B 8704          // 32*BPAD*2 (one of hi/lo)
#define STAGE 27648        // ST_A + 2*ST_B
#define NSTG  5
#define GEMM_SMEM (NSTG * STAGE)

template<int MODE>
__global__ void __launch_bounds__(256) mma_gemm(
    const __half* __restrict__ Af0, const __half* __restrict__ Af1,
    float* __restrict__ C0, float* __restrict__ C1,
    const __half* __restrict__ Bh_g, const __half* __restrict__ Bl_g,
    const float* __restrict__ aux,
    float* __restrict__ rowss0, float* __restrict__ rowss1,
    int N, int Kd)
{
    extern __shared__ char smc[];
    const int tid  = threadIdx.x;
    const int lane = tid & 31;
    const int warp = tid >> 5;
    const int wm   = warp >> 1;       // 0..3
    const int wn   = warp & 1;        // 0..1
    const int mBase = blockIdx.y * 128;
    const int nBase = blockIdx.x * 128;
    const __half* A_g = blockIdx.z ? Af1 : Af0;
    float* C     = blockIdx.z ? C1 : C0;
    float* rowss = blockIdx.z ? rowss1 : rowss0;

    const uint32_t sb = (uint32_t)__cvta_generic_to_shared(smc);

    // cp.async coords (per thread: A 2x16B, Bh 2x16B, Bl 2x16B per chunk)
    const int arow = tid >> 2, aseg = tid & 3;      // rows + i*64
    const int brow = tid >> 4, bseg = tid & 15;     // rows + i*16

    // ldmatrix per-lane element offsets
    const int l7 = lane & 7;
    const int aRowSel = l7 + ((lane & 8) ? 8 : 0);
    const int aKSel   = (lane & 16) ? 8 : 0;
    uint32_t aoff[2];
#pragma unroll
    for (int i = 0; i < 2; i++)
        aoff[i] = (uint32_t)((wm * 32 + i * 16 + aRowSel) * APAD + aKSel);
    const int bKSel = l7 + ((lane & 8) ? 8 : 0);
    const int bNSel = (lane & 16) ? 8 : 0;
    uint32_t boff[4];
#pragma unroll
    for (int jp = 0; jp < 4; jp++)
        boff[jp] = (uint32_t)(bKSel * BPAD + wn * 64 + jp * 16 + bNSel);

    float acc[2][8][4];
#pragma unroll
    for (int i = 0; i < 2; i++)
#pragma unroll
        for (int j = 0; j < 8; j++)
#pragma unroll
            for (int r = 0; r < 4; r++) acc[i][j][r] = 0.f;

    const int nk = Kd >> 5;

#define LOAD_CHUNK(kt, s) do { \
    const int _k0 = (kt) * 32; \
    const uint32_t _st = sb + (uint32_t)(s) * STAGE; \
    _Pragma("unroll") \
    for (int _i = 0; _i < 2; _i++) { \
        int _ar = arow + _i * 64; \
        CP_ASYNC16(_st + _ar * 80 + aseg * 16, \
                   A_g + (size_t)(mBase + _ar) * Kd + _k0 + aseg * 8); \
        int _br = brow + _i * 16; \
        CP_ASYNC16(_st + ST_A + _br * 272 + bseg * 16, \
                   Bh_g + (size_t)(_k0 + _br) * N + nBase + bseg * 8); \
        CP_ASYNC16(_st + ST_A + ST_B + _br * 272 + bseg * 16, \
                   Bl_g + (size_t)(_k0 + _br) * N + nBase + bseg * 8); \
    } \
    CP_COMMIT(); \
} while (0)

    LOAD_CHUNK(0, 0);
    LOAD_CHUNK(1, 1);
    LOAD_CHUNK(2, 2);
    LOAD_CHUNK(3, 3);

    for (int kt = 0; kt < nk; kt++) {
        CP_WAIT3();
        __syncthreads();           // single barrier per chunk (see hazard note)
        if (kt + 4 < nk) LOAD_CHUNK(kt + 4, (kt + 4) % NSTG);

        const uint32_t st  = sb + (uint32_t)(kt % NSTG) * STAGE;
        const uint32_t aB  = st;
        const uint32_t bhB = st + ST_A;
        const uint32_t blB = st + ST_A + ST_B;
#pragma unroll
        for (int ks = 0; ks < 2; ks++) {
            uint32_t a[2][4];
#pragma unroll
            for (int i = 0; i < 2; i++)
                ldsm_x4(a[i], aB + (aoff[i] + ks * 16) * 2u);
            uint32_t b[8][2][2];
#pragma unroll
            for (int jp = 0; jp < 4; jp++) {
                uint32_t t[4];
                ldsm_x4_t(t, bhB + (boff[jp] + ks * 16 * BPAD) * 2u);
                b[2 * jp][0][0] = t[0]; b[2 * jp][0][1] = t[1];
                b[2 * jp + 1][0][0] = t[2]; b[2 * jp + 1][0][1] = t[3];
                ldsm_x4_t(t, blB + (boff[jp] + ks * 16 * BPAD) * 2u);
                b[2 * jp][1][0] = t[0]; b[2 * jp][1][1] = t[1];
                b[2 * jp + 1][1][0] = t[2]; b[2 * jp + 1][1][1] = t[3];
            }
#pragma unroll
            for (int i = 0; i < 2; i++)
#pragma unroll
                for (int j = 0; j < 8; j++) mma16816h(acc[i][j], a[i], b[j][0]);
#pragma unroll
            for (int i = 0; i < 2; i++)
#pragma unroll
                for (int j = 0; j < 8; j++) mma16816h(acc[i][j], a[i], b[j][1]);
        }
    }

    // epilogue
    const int g  = lane >> 2;
    const int t4 = lane & 3;
#pragma unroll
    for (int i = 0; i < 2; i++) {
        const int r0 = mBase + wm * 32 + i * 16 + g;
        float s0 = 0.f, s1 = 0.f;
#pragma unroll
        for (int j = 0; j < 8; j++) {
            const int n = nBase + wn * 64 + j * 8 + 2 * t4;
            float a0 = aux[n], a1 = aux[n + 1];
            if (MODE == 0) {
                float* c0 = C + (size_t)r0 * N + n;
                float* c1 = C + (size_t)(r0 + 8) * N + n;
                c0[0] = acc[i][j][0] + a0;
                c0[1] = acc[i][j][1] + a1;
                c1[0] = acc[i][j][2] + a0;
                c1[1] = acc[i][j][3] + a1;
            } else {
                float v0 = acc[i][j][0] * a0, v1 = acc[i][j][1] * a1;
                float v2 = acc[i][j][2] * a0, v3 = acc[i][j][3] * a1;
                *(float2*)(C + (size_t)r0 * N + n)       = make_float2(v0, v1);
                *(float2*)(C + (size_t)(r0 + 8) * N + n) = make_float2(v2, v3);
                s0 = fmaf(v0, v0, fmaf(v1, v1, s0));
                s1 = fmaf(v2, v2, fmaf(v3, v3, s1));
            }
        }
        if (MODE == 1) {
            s0 += __shfl_xor_sync(0xffffffffu, s0, 1);
            s0 += __shfl_xor_sync(0xffffffffu, s0, 2);
            s1 += __shfl_xor_sync(0xffffffffu, s1, 1);
            s1 += __shfl_xor_sync(0xffffffffu, s1, 2);
            if (t4 == 0) {
                atomicAdd(&rowss[r0], s0);
                atomicAdd(&rowss[r0 + 8], s1);
            }
        }
    }
#undef LOAD_CHUNK
}

// ------------------------- batchnorm --------------------------------------
__global__ void bn_partial(int view) {
    int c  = blockIdx.x * 256 + threadIdx.x;
    int r0 = blockIdx.y * 256;
    const float* h = g_h[view];
    float s = 0.f, s2 = 0.f;
    for (int r = r0; r < r0 + 256; r++) {
        float v = h[(size_t)r * DHID + c];
        s += v;
        s2 = fmaf(v, v, s2);
    }
    atomicAdd(&g_bns[view][c], s);
    atomicAdd(&g_bns2[view][c], s2);
}

__global__ void bn_finish(int view) {
    int c = blockIdx.x * 256 + threadIdx.x;
    if (c >= DHID) return;
    float m = g_bns[view][c] * (1.f / B_);
    float v = g_bns2[view][c] * (1.f / B_) - m * m;
    g_bnm[view][c]  = m;
    g_bnis[view][c] = rsqrtf(v + 1e-5f);
}

// BN+relu, emits fp16 activation for GEMM2
__global__ void bn_relu(int view, const float* __restrict__ gamma,
                        const float* __restrict__ beta) {
    int i = blockIdx.x * 256 + threadIdx.x;
    int c = i & (DHID - 1);
    float h = g_h[view][i];
    float v = fmaf(gamma[c] * (h - g_bnm[view][c]), g_bnis[view][c], beta[c]);
    v = fmaxf(v, 0.f);
    g_hf[view][i] = __float2half_rn(v);
}

// ------------------------- z_L row normalization + copy-out ---------------
__global__ void row_scale(float* __restrict__ z1L_out) {
    const int view = blockIdx.y;
    size_t i4 = (size_t)blockIdx.x * 256 + threadIdx.x;
    float4* z = (float4*)g_zL[view];
    float4 v = z[i4];
    int row = (int)((i4 * 4) >> 10);
    float rs = rsqrtf(g_rowss[view][row]);
    v.x *= rs; v.y *= rs; v.z *= rs; v.w *= rs;
    z[i4] = v;
    if (view == 0) {
        size_t b = i4 * 4;
        z1L_out[b]   = v.x;
        z1L_out[b+1] = v.y;
        z1L_out[b+2] = v.z;
        z1L_out[b+3] = v.w;
    }
}

// ------------------------- cosine(z_H, y_other) mean ----------------------
__global__ void __launch_bounds__(256) cos_kernel(const float* __restrict__ z1H,
                                                  const float* __restrict__ y1,
                                                  const float* __restrict__ y2) {
    const int pair = blockIdx.y;
    const float* a = pair ? g_zH2 : z1H;
    const float* b = pair ? y1 : y2;
    const int tid = threadIdx.x, lane = tid & 31, wid = tid >> 5;
    __shared__ float sw[8];
    float local = 0.f;
    for (int row = blockIdx.x * 8 + wid; row < B_; row += gridDim.x * 8) {
        const float* ar = a + (size_t)row * DOUT;
        const float* br = b + (size_t)row * DOUT;
        float d = 0.f, na = 0.f, nb = 0.f;
        for (int j = lane; j < DOUT; j += 32) {
            float x = ar[j], y = br[j];
            d  = fmaf(x, y, d);
            na = fmaf(x, x, na);
            nb = fmaf(y, y, nb);
        }
#pragma unroll
        for (int o = 16; o; o >>= 1) {
            d  += __shfl_xor_sync(0xffffffffu, d, o);
            na += __shfl_xor_sync(0xffffffffu, na, o);
            nb += __shfl_xor_sync(0xffffffffu, nb, o);
        }
        local += d / (fmaxf(sqrtf(na), 1e-8f) * fmaxf(sqrtf(nb), 1e-8f));
    }
    if (lane == 0) sw[wid] = local;
    __syncthreads();
    if (tid == 0) {
        float s = 0.f;
        for (int i = 0; i < 8; i++) s += sw[i];
        atomicAdd(&g_scal[pair], s);
    }
}

// ------------------------- kmeans ------------------------------------------
__global__ void km_init() {
    const int view = blockIdx.y, k = blockIdx.x, tid = threadIdx.x;
    const float* src = g_zL[view] + (size_t)k * DCLD;
    float p = 0.f;
    for (int j = tid; j < DCLD; j += 256) {
        float v = src[j];
        g_cent[view][k * DCLD + j] = v;
        p = fmaf(v, v, p);
    }
    p = block_reduce_256(p);
    if (tid == 0) g_cn2[view][k] = p;
}

// fused: labels + counts + column-owned segment sums, one kernel
// grid (64, 2): block handles 128 rows; smem = centers 40KB + partials 40KB
__global__ void __launch_bounds__(256) km_assign() {
    extern __shared__ float sm[];
    float* sc = sm;                 // KC*DCLD centers
    float* ps = sm + KC * DCLD;     // KC*DCLD partial sums
    __shared__ float scn2[KC];
    __shared__ int   scnt[KC];
    __shared__ int   slab[128];
    const int view = blockIdx.y;
    const float* z = g_zL[view];
    const int tid = threadIdx.x, lane = tid & 31, wid = tid >> 5;
    for (int i = tid; i < KC * DCLD; i += 256) { sc[i] = g_cent[view][i]; ps[i] = 0.f; }
    if (tid < KC) { scn2[tid] = g_cn2[view][tid]; scnt[tid] = 0; }
    __syncthreads();
    const int rbase = blockIdx.x * 128;
    // phase A: labels (warp per row, 16 rows per warp)
    for (int rr = 0; rr < 16; rr++) {
        const int r = wid * 16 + rr;
        const float4* xr = (const float4*)(z + (size_t)(rbase + r) * DCLD);
        float dots[KC];
#pragma unroll
        for (int k = 0; k < KC; k++) dots[k] = 0.f;
        for (int j = lane; j < DCLD / 4; j += 32) {
            float4 xv = xr[j];
#pragma unroll
            for (int k = 0; k < KC; k++) {
                float4 cv = *(const float4*)&sc[k * DCLD + 4 * j];
                dots[k] += xv.x * cv.x + xv.y * cv.y + xv.z * cv.z + xv.w * cv.w;
            }
        }
#pragma unroll
        for (int k = 0; k < KC; k++)
#pragma unroll
            for (int o = 16; o; o >>= 1)
                dots[k] += __shfl_xor_sync(0xffffffffu, dots[k], o);
        int bi = 0;
        float bd = scn2[0] - 2.f * dots[0];
#pragma unroll
        for (int k = 1; k < KC; k++) {
            float d = scn2[k] - 2.f * dots[k];
            if (d < bd) { bd = d; bi = k; }   // strict <: first-min like argmin
        }
        if (lane == 0) {
            g_cl[view][rbase + r] = bi;
            atomicAdd(&scnt[bi], 1);
            slab[r] = bi;
        }
    }
    __syncthreads();
    // phase B: column-owned accumulation (thread owns cols tid, tid+256, ...)
    for (int r = 0; r < 128; r++) {
        const int lb = slab[r];
        const float* zr = z + (size_t)(rbase + r) * DCLD;
#pragma unroll
        for (int j = 0; j < 4; j++)
            ps[lb * DCLD + tid + j * 256] += zr[tid + j * 256];
    }
    __syncthreads();
    for (int i = tid; i < KC * DCLD; i += 256) {
        float v = ps[i];
        if (v != 0.f) atomicAdd(&g_csum[view][i], v);
    }
    if (tid < KC && scnt[tid]) atomicAdd(&g_ccnt[view][tid], (float)scnt[tid]);
}

// update centers; re-zero csum/ccnt for the next iteration
__global__ void km_update() {
    const int view = blockIdx.y, k = blockIdx.x, tid = threadIdx.x;
    const float inv = 1.f / fmaxf(g_ccnt[view][k], 1.f);
    float p = 0.f;
    for (int j = tid; j < DCLD; j += 256) {
        float c = g_csum[view][k * DCLD + j];
        g_csum[view][k * DCLD + j] = 0.f;
        c *= inv;
        g_cent[view][k * DCLD + j] = c;
        p = fmaf(c, c, p);
    }
    p = block_reduce_256(p);
    if (tid == 0) { g_cn2[view][k] = p; g_ccnt[view][k] = 0.f; }
}

// ------------------------- cross entropy -----------------------------------
__global__ void __launch_bounds__(256) ce_kernel() {
    __shared__ float sc[KC * DCLD];
    __shared__ float swarp[8];
    const int view = blockIdx.y;
    const float* z    = g_zL[view];
    const float* cent = g_cent[view ^ 1];
    const int*   lab  = g_cl[view ^ 1];
    const int tid = threadIdx.x;
    for (int i = tid; i < KC * DCLD; i += 256) sc[i] = cent[i];
    __syncthreads();
    const int lane = tid & 31, wid = tid >> 5;
    float local = 0.f;
    const float invT = 1.f / 0.07f;
    for (int row = blockIdx.x * 8 + wid; row < B_; row += gridDim.x * 8) {
        const float4* xr = (const float4*)(z + (size_t)row * DCLD);
        float dots[KC];
#pragma unroll
        for (int k = 0; k < KC; k++) dots[k] = 0.f;
        for (int j = lane; j < DCLD / 4; j += 32) {
            float4 xv = xr[j];
#pragma unroll
            for (int k = 0; k < KC; k++) {
                float4 cv = *(const float4*)&sc[k * DCLD + 4 * j];
                dots[k] += xv.x * cv.x + xv.y * cv.y + xv.z * cv.z + xv.w * cv.w;
            }
        }
#pragma unroll
        for (int k = 0; k < KC; k++)
#pragma unroll
            for (int o = 16; o; o >>= 1)
                dots[k] += __shfl_xor_sync(0xffffffffu, dots[k], o);
        float m = -1e30f;
#pragma unroll
        for (int k = 0; k < KC; k++) { dots[k] *= invT; m = fmaxf(m, dots[k]); }
        float s = 0.f;
#pragma unroll
        for (int k = 0; k < KC; k++) s += expf(dots[k] - m);
        float lse = logf(s) + m;
        local += lse - dots[lab[row]];
    }
    if (lane == 0) swarp[wid] = local;
    __syncthreads();
    if (tid == 0) {
        float s = 0.f;
        for (int i = 0; i < 8; i++) s += swarp[i];
        atomicAdd(&g_scal[2 + view], s);
    }
}

// ------------------------- finalize ----------------------------------------
__global__ void final_kernel(float* __restrict__ out,
                             const float* __restrict__ Lam) {
    if (threadIdx.x == 0) {
        float cos1 = g_scal[0] * (1.f / B_);
        float cos2 = g_scal[1] * (1.f / B_);
        float lss  = 2.f - cos1 - cos2;
        float ce1  = g_scal[2] * (1.f / B_);
        float ce2  = g_scal[3] * (1.f / B_);
        float lcld = 0.5f * (ce1 + ce2);
        out[0] = lss + (*Lam) * lcld;
        out[1] = lss;
        out[2] = lcld;
    }
}

// ------------------------- host launcher -----------------------------------
extern "C" void kernel_launch(void* const* d_in, const int* in_sizes, int n_in,
                              void* d_out, int out_size)
{
    (void)in_sizes; (void)n_in; (void)out_size;
    const float* y1    = (const float*)d_in[0];
    const float* y2    = (const float*)d_in[1];
    const float* Lam   = (const float*)d_in[2];
    const float* W1    = (const float*)d_in[3];
    const float* b1    = (const float*)d_in[4];
    const float* gamma = (const float*)d_in[5];
    const float* beta  = (const float*)d_in[6];
    const float* W2    = (const float*)d_in[7];
    const float* b2    = (const float*)d_in[8];
    const float* Wc    = (const float*)d_in[9];
    float* out = (float*)d_out;
    float* z1H = out + 3;
    float* z1L = out + 3 + (size_t)B_ * DOUT;

    float *p_h = 0, *p_zH2 = 0, *p_zL = 0, *p_wcinv = 0, *p_rowss = 0;
    __half *p_yf = 0, *p_hf = 0;
    __half *p_w1h = 0, *p_w1l = 0, *p_w2h = 0, *p_w2l = 0, *p_wch = 0, *p_wcl = 0;
    cudaGetSymbolAddress((void**)&p_h,     g_h);
    cudaGetSymbolAddress((void**)&p_zH2,   g_zH2);
    cudaGetSymbolAddress((void**)&p_zL,    g_zL);
    cudaGetSymbolAddress((void**)&p_wcinv, g_wcinv);
    cudaGetSymbolAddress((void**)&p_rowss, g_rowss);
    cudaGetSymbolAddress((void**)&p_yf,    g_yf);
    cudaGetSymbolAddress((void**)&p_hf,    g_hf);
    cudaGetSymbolAddress((void**)&p_w1h,   g_w1h);
    cudaGetSymbolAddress((void**)&p_w1l,   g_w1l);
    cudaGetSymbolAddress((void**)&p_w2h,   g_w2h);
    cudaGetSymbolAddress((void**)&p_w2l,   g_w2l);
    cudaGetSymbolAddress((void**)&p_wch,   g_wch);
    cudaGetSymbolAddress((void**)&p_wcl,   g_wcl);

    cudaFuncSetAttribute(mma_gemm<0>, cudaFuncAttributeMaxDynamicSharedMemorySize,
                         GEMM_SMEM);
    cudaFuncSetAttribute(mma_gemm<1>, cudaFuncAttributeMaxDynamicSharedMemorySize,
                         GEMM_SMEM);
    const int ASSIGN_SMEM = 2 * KC * DCLD * (int)sizeof(float);
    cudaFuncSetAttribute(km_assign, cudaFuncAttributeMaxDynamicSharedMemorySize,
                         ASSIGN_SMEM);

    const int NY4 = B_ * DIN / 4;

    init_zero<<<80, 256>>>();
    wc_inv_kernel<<<DCLD / 256, 256>>>(Wc);
    conv_fp16<<<NY4 / 256, 256>>>((const float4*)y1, (uint2*)p_yf, NY4);
    conv_fp16<<<NY4 / 256, 256>>>((const float4*)y2,
        (uint2*)(p_yf + (size_t)B_ * DIN), NY4);
    split_w16<<<(DIN * DHID / 4) / 256, 256>>>((const float4*)W1,
        (uint2*)p_w1h, (uint2*)p_w1l, DIN * DHID / 4);

    // GEMM1: h = y @ W1 + b1 (both views via z-dim)
    mma_gemm<0><<<dim3(DHID / 128, B_ / 128, 2), 256, GEMM_SMEM>>>(
        p_yf, p_yf + (size_t)B_ * DIN,
        p_h, p_h + (size_t)B_ * DHID,
        p_w1h, p_w1l, b1, 0, 0, DHID, DIN);

    split_w16<<<(DHID * DOUT / 4) / 256, 256>>>((const float4*)W2,
        (uint2*)p_w2h, (uint2*)p_w2l, DHID * DOUT / 4);
    split_w16<<<(DIN * DCLD / 4) / 256, 256>>>((const float4*)Wc,
        (uint2*)p_wch, (uint2*)p_wcl, DIN * DCLD / 4);

    for (int v = 0; v < 2; v++) bn_partial<<<dim3(DHID / 256, 32), 256>>>(v);
    for (int v = 0; v < 2; v++) bn_finish<<<DHID / 256, 256>>>(v);
    for (int v = 0; v < 2; v++) bn_relu<<<(B_ * DHID) / 256, 256>>>(v, gamma, beta);

    // GEMM2: z_H = relu_h @ W2 + b2
    mma_gemm<0><<<dim3(DOUT / 128, B_ / 128, 2), 256, GEMM_SMEM>>>(
        p_hf, p_hf + (size_t)B_ * DHID,
        z1H, p_zH2,
        p_w2h, p_w2l, b2, 0, 0, DOUT, DHID);

    // GEMM3: z_L_pre = (y @ Wc) * wcinv  (+ row sumsq)
    mma_gemm<1><<<dim3(DCLD / 128, B_ / 128, 2), 256, GEMM_SMEM>>>(
        p_yf, p_yf + (size_t)B_ * DIN,
        p_zL, p_zL + (size_t)B_ * DCLD,
        p_wch, p_wcl, p_wcinv, p_rowss, p_rowss + B_, DCLD, DIN);

    row_scale<<<dim3((B_ * DCLD / 4) / 256, 2), 256>>>(z1L);
    cos_kernel<<<dim3(128, 2), 256>>>(z1H, y1, y2);

    km_init<<<dim3(KC, 2), 256>>>();
    for (int it = 0; it < NIT; it++) {
        km_assign<<<dim3(B_ / 128, 2), 256, ASSIGN_SMEM>>>();
        km_update<<<dim3(KC, 2), 256>>>();
    }

    ce_kernel<<<dim3(64, 2), 256>>>();
    final_kernel<<<1, 32>>>(out, Lam);
}

// round 11
// speedup vs baseline: 2.9925x; 1.1331x over previous
#include <cuda_runtime.h>
#include <cuda_fp16.h>
#include <cstdint>

#define B_    8192
#define DIN   2048
#define DHID  512
#define DOUT  2048
#define DCLD  1024
#define KC    10
#define NIT   10

// ------------------------- device scratch (static, no runtime alloc) ------
__device__ float g_h[2][B_*DHID];          // hidden activations fp32 (for BN stats)
__device__ float g_zH2[B_*DOUT];           // z2_H
__device__ float g_zL[2][B_*DCLD];         // aligned internal copies of z1_L/z2_L
__device__ float g_wcsq[DCLD];
__device__ float g_wcinv[DCLD];
__device__ float g_bns[2][DHID];
__device__ float g_bns2[2][DHID];
__device__ float g_bnm[2][DHID];
__device__ float g_bnis[2][DHID];
__device__ float g_rowss[2][B_];
__device__ float g_csum3[3][2][KC*DCLD];   // rotating kmeans segment sums
__device__ float g_ccnt3[3][2][KC];
__device__ int   g_cl[2][B_];
__device__ float g_scal[4];                // cos1_sum, cos2_sum, ce1_sum, ce2_sum
// fp16 operands: A single fp16, B split hi/lo
__device__ __half g_yf[2][B_*DIN];
__device__ __half g_hf[2][B_*DHID];
__device__ __half g_w1h[DIN*DHID], g_w1l[DIN*DHID];
__device__ __half g_w2h[DHID*DOUT], g_w2l[DHID*DOUT];
__device__ __half g_wch[DIN*DCLD], g_wcl[DIN*DCLD];

// ------------------------- helpers ---------------------------------------
__device__ __forceinline__ float block_reduce_256(float v) {
    __shared__ float s[8];
#pragma unroll
    for (int o = 16; o; o >>= 1) v += __shfl_xor_sync(0xffffffffu, v, o);
    if ((threadIdx.x & 31) == 0) s[threadIdx.x >> 5] = v;
    __syncthreads();
    v = (threadIdx.x < 8) ? s[threadIdx.x] : 0.f;
    if (threadIdx.x < 32) {
#pragma unroll
        for (int o = 4; o; o >>= 1) v += __shfl_xor_sync(0xffffffffu, v, o);
    }
    return v;
}

__device__ __forceinline__ void ldsm_x4(uint32_t* r, uint32_t addr) {
    asm volatile("ldmatrix.sync.aligned.m8n8.x4.shared.b16 {%0,%1,%2,%3}, [%4];\n"
        : "=r"(r[0]), "=r"(r[1]), "=r"(r[2]), "=r"(r[3]) : "r"(addr));
}
__device__ __forceinline__ void ldsm_x4_t(uint32_t* r, uint32_t addr) {
    asm volatile("ldmatrix.sync.aligned.m8n8.x4.trans.shared.b16 {%0,%1,%2,%3}, [%4];\n"
        : "=r"(r[0]), "=r"(r[1]), "=r"(r[2]), "=r"(r[3]) : "r"(addr));
}
__device__ __forceinline__ void mma16816h(float* c, const uint32_t* a, const uint32_t* b) {
    asm volatile(
        "mma.sync.aligned.m16n8k16.row.col.f32.f16.f16.f32 "
        "{%0,%1,%2,%3}, {%4,%5,%6,%7}, {%8,%9}, {%0,%1,%2,%3};\n"
        : "+f"(c[0]), "+f"(c[1]), "+f"(c[2]), "+f"(c[3])
        : "r"(a[0]), "r"(a[1]), "r"(a[2]), "r"(a[3]), "r"(b[0]), "r"(b[1]));
}

#define CP_ASYNC16(dst, src) \
    asm volatile("cp.async.cg.shared.global [%0], [%1], 16;\n" \
        :: "r"(dst), "l"((const void*)(src)))
#define CP_COMMIT() asm volatile("cp.async.commit_group;\n" ::: "memory")
#define CP_WAIT2()  asm volatile("cp.async.wait_group 2;\n" ::: "memory")

__device__ __forceinline__ uint32_t packh2(float a, float b) {
    __half ha = __float2half_rn(a), hb = __float2half_rn(b);
    return ((uint32_t)__half_as_ushort(hb) << 16) | (uint32_t)__half_as_ushort(ha);
}

// ------------------------- init / preprocessing ---------------------------
__global__ void init_zero() {
    int i = blockIdx.x * 256 + threadIdx.x;   // 160 blocks -> 40960 threads
    if (i < 4) g_scal[i] = 0.f;
    if (i < 2 * B_) ((float*)g_rowss)[i] = 0.f;
    if (i < 2 * DHID) { ((float*)g_bns)[i] = 0.f; ((float*)g_bns2)[i] = 0.f; }
    if (i < 2 * 2 * KC * DCLD) ((float*)g_csum3)[i] = 0.f;   // bufs 0,1
    if (i < 2 * 2 * KC) ((float*)g_ccnt3)[i] = 0.f;          // bufs 0,1
    if (i < DCLD) g_wcsq[i] = 0.f;
}

__global__ void wc_part(const float* __restrict__ Wc) {   // grid (4,16)
    int c  = blockIdx.x * 256 + threadIdx.x;
    int r0 = blockIdx.y * 128;
    float s = 0.f;
    for (int r = r0; r < r0 + 128; r++) {
        float v = Wc[(size_t)r * DCLD + c];
        s = fmaf(v, v, s);
    }
    atomicAdd(&g_wcsq[c], s);
}
__global__ void wc_fin() {
    int c = blockIdx.x * 256 + threadIdx.x;
    if (c < DCLD) g_wcinv[c] = 1.f / fmaxf(sqrtf(g_wcsq[c]), 1e-12f);
}

// fp32 -> fp16 (A operands)
__global__ void conv_fp16(const float4* __restrict__ src, uint2* __restrict__ dst, int n4) {
    int i = blockIdx.x * 256 + threadIdx.x;
    if (i >= n4) return;
    float4 v = src[i];
    dst[i] = make_uint2(packh2(v.x, v.y), packh2(v.z, v.w));
}

// fp32 -> fp16 hi/lo split (B operands / weights)
__global__ void split_w16(const float4* __restrict__ src,
                          uint2* __restrict__ hi, uint2* __restrict__ lo, int n4) {
    int i = blockIdx.x * 256 + threadIdx.x;
    if (i >= n4) return;
    float4 v = src[i];
    __half hx = __float2half_rn(v.x), hy = __float2half_rn(v.y);
    __half hz = __float2half_rn(v.z), hw = __float2half_rn(v.w);
    hi[i] = make_uint2(
        ((uint32_t)__half_as_ushort(hy) << 16) | __half_as_ushort(hx),
        ((uint32_t)__half_as_ushort(hw) << 16) | __half_as_ushort(hz));
    lo[i] = make_uint2(
        packh2(v.x - __half2float(hx), v.y - __half2float(hy)),
        packh2(v.z - __half2float(hz), v.w - __half2float(hw)));
}

// ------------------------- pipelined mma.sync GEMM ------------------------
// Block 128x128, 8 warps (warp 32x64), K-chunks of 32, 4-stage cp.async ring,
// ONE __syncthreads per chunk, 2 CTAs/SM (smem 110.6KB, regs capped at 128).
// A fp16 single, B fp16 hi/lo => 2 passes: C = A*Bhi + A*Blo.
// MODE 0: C = A*B + aux[col]   (scalar stores: C may be only 4B-aligned)
// MODE 1: C = (A*B)*aux[col] + per-row sumsq atomics into rowss.
#define APAD 40            // A smem row: 32 k + 8 pad halfs; 80 B/row
#define BPAD 136           // B smem row: 128 n + 8 pad halfs; 272 B/row
#define ST_A 10240         // 128*APAD*2
#define ST_B 8704          // 32*BPAD*2 (one of hi/lo)
#define STAGE 27648        // ST_A + 2*ST_B
#define NSTG  4
#define GEMM_SMEM (NSTG * STAGE)

template<int MODE>
__global__ void __launch_bounds__(256, 2) mma_gemm(
    const __half* __restrict__ Af0, const __half* __restrict__ Af1,
    float* __restrict__ C0, float* __restrict__ C1,
    const __half* __restrict__ Bh_g, const __half* __restrict__ Bl_g,
    const float* __restrict__ aux,
    float* __restrict__ rowss0, float* __restrict__ rowss1,
    int N, int Kd)
{
    extern __shared__ char smc[];
    const int tid  = threadIdx.x;
    const int lane = tid & 31;
    const int warp = tid >> 5;
    const int wm   = warp >> 1;       // 0..3
    const int wn   = warp & 1;        // 0..1
    const int mBase = blockIdx.y * 128;
    const int nBase = blockIdx.x * 128;
    const __half* A_g = blockIdx.z ? Af1 : Af0;
    float* C     = blockIdx.z ? C1 : C0;
    float* rowss = blockIdx.z ? rowss1 : rowss0;

    const uint32_t sb = (uint32_t)__cvta_generic_to_shared(smc);

    // cp.async coords (per thread: A 2x16B, Bh 2x16B, Bl 2x16B per chunk)
    const int arow = tid >> 2, aseg = tid & 3;      // rows + i*64
    const int brow = tid >> 4, bseg = tid & 15;     // rows + i*16

    // ldmatrix per-lane element offsets
    const int l7 = lane & 7;
    const int aRowSel = l7 + ((lane & 8) ? 8 : 0);
    const int aKSel   = (lane & 16) ? 8 : 0;
    uint32_t aoff[2];
#pragma unroll
    for (int i = 0; i < 2; i++)
        aoff[i] = (uint32_t)((wm * 32 + i * 16 + aRowSel) * APAD + aKSel);
    const int bKSel = l7 + ((lane & 8) ? 8 : 0);
    const int bNSel = (lane & 16) ? 8 : 0;
    uint32_t boff[4];
#pragma unroll
    for (int jp = 0; jp < 4; jp++)
        boff[jp] = (uint32_t)(bKSel * BPAD + wn * 64 + jp * 16 + bNSel);

    float acc[2][8][4];
#pragma unroll
    for (int i = 0; i < 2; i++)
#pragma unroll
        for (int j = 0; j < 8; j++)
#pragma unroll
            for (int r = 0; r < 4; r++) acc[i][j][r] = 0.f;

    const int nk = Kd >> 5;

#define LOAD_CHUNK(kt, s) do { \
    const int _k0 = (kt) * 32; \
    const uint32_t _st = sb + (uint32_t)(s) * STAGE; \
    _Pragma("unroll") \
    for (int _i = 0; _i < 2; _i++) { \
        int _ar = arow + _i * 64; \
        CP_ASYNC16(_st + _ar * 80 + aseg * 16, \
                   A_g + (size_t)(mBase + _ar) * Kd + _k0 + aseg * 8); \
        int _br = brow + _i * 16; \
        CP_ASYNC16(_st + ST_A + _br * 272 + bseg * 16, \
                   Bh_g + (size_t)(_k0 + _br) * N + nBase + bseg * 8); \
        CP_ASYNC16(_st + ST_A + ST_B + _br * 272 + bseg * 16, \
                   Bl_g + (size_t)(_k0 + _br) * N + nBase + bseg * 8); \
    } \
    CP_COMMIT(); \
} while (0)

    LOAD_CHUNK(0, 0);
    LOAD_CHUNK(1, 1);
    LOAD_CHUNK(2, 2);

    for (int kt = 0; kt < nk; kt++) {
        CP_WAIT2();
        __syncthreads();   // all warps done reading stage (kt-1)&3 before reuse
        if (kt + 3 < nk) LOAD_CHUNK(kt + 3, (kt + 3) & 3);

        const uint32_t st  = sb + (uint32_t)(kt & 3) * STAGE;
        const uint32_t aB  = st;
        const uint32_t bB[2] = { st + ST_A, st + ST_A + ST_B };
#pragma unroll
        for (int ks = 0; ks < 2; ks++) {
            uint32_t a[2][4];
#pragma unroll
            for (int i = 0; i < 2; i++)
                ldsm_x4(a[i], aB + (aoff[i] + ks * 16) * 2u);
#pragma unroll
            for (int p = 0; p < 2; p++) {       // hi pass, then lo pass
                uint32_t b[4][4];
#pragma unroll
                for (int jp = 0; jp < 4; jp++)
                    ldsm_x4_t(b[jp], bB[p] + (boff[jp] + ks * 16 * BPAD) * 2u);
#pragma unroll
                for (int i = 0; i < 2; i++)
#pragma unroll
                    for (int jp = 0; jp < 4; jp++) {
                        mma16816h(acc[i][2 * jp],     a[i], &b[jp][0]);
                        mma16816h(acc[i][2 * jp + 1], a[i], &b[jp][2]);
                    }
            }
        }
    }

    // epilogue
    const int g  = lane >> 2;
    const int t4 = lane & 3;
#pragma unroll
    for (int i = 0; i < 2; i++) {
        const int r0 = mBase + wm * 32 + i * 16 + g;
        float s0 = 0.f, s1 = 0.f;
#pragma unroll
        for (int j = 0; j < 8; j++) {
            const int n = nBase + wn * 64 + j * 8 + 2 * t4;
            float a0 = aux[n], a1 = aux[n + 1];
            if (MODE == 0) {
                float* c0 = C + (size_t)r0 * N + n;
                float* c1 = C + (size_t)(r0 + 8) * N + n;
                c0[0] = acc[i][j][0] + a0;
                c0[1] = acc[i][j][1] + a1;
                c1[0] = acc[i][j][2] + a0;
                c1[1] = acc[i][j][3] + a1;
            } else {
                float v0 = acc[i][j][0] * a0, v1 = acc[i][j][1] * a1;
                float v2 = acc[i][j][2] * a0, v3 = acc[i][j][3] * a1;
                *(float2*)(C + (size_t)r0 * N + n)       = make_float2(v0, v1);
                *(float2*)(C + (size_t)(r0 + 8) * N + n) = make_float2(v2, v3);
                s0 = fmaf(v0, v0, fmaf(v1, v1, s0));
                s1 = fmaf(v2, v2, fmaf(v3, v3, s1));
            }
        }
        if (MODE == 1) {
            s0 += __shfl_xor_sync(0xffffffffu, s0, 1);
            s0 += __shfl_xor_sync(0xffffffffu, s0, 2);
            s1 += __shfl_xor_sync(0xffffffffu, s1, 1);
            s1 += __shfl_xor_sync(0xffffffffu, s1, 2);
            if (t4 == 0) {
                atomicAdd(&rowss[r0], s0);
                atomicAdd(&rowss[r0 + 8], s1);
            }
        }
    }
#undef LOAD_CHUNK
}

// ------------------------- batchnorm --------------------------------------
__global__ void bn_partial(int view) {
    int c  = blockIdx.x * 256 + threadIdx.x;
    int r0 = blockIdx.y * 256;
    const float* h = g_h[view];
    float s = 0.f, s2 = 0.f;
    for (int r = r0; r < r0 + 256; r++) {
        float v = h[(size_t)r * DHID + c];
        s += v;
        s2 = fmaf(v, v, s2);
    }
    atomicAdd(&g_bns[view][c], s);
    atomicAdd(&g_bns2[view][c], s2);
}

__global__ void bn_finish(int view) {
    int c = blockIdx.x * 256 + threadIdx.x;
    if (c >= DHID) return;
    float m = g_bns[view][c] * (1.f / B_);
    float v = g_bns2[view][c] * (1.f / B_) - m * m;
    g_bnm[view][c]  = m;
    g_bnis[view][c] = rsqrtf(v + 1e-5f);
}

// BN+relu, emits fp16 activation for GEMM2
__global__ void bn_relu(int view, const float* __restrict__ gamma,
                        const float* __restrict__ beta) {
    int i = blockIdx.x * 256 + threadIdx.x;
    int c = i & (DHID - 1);
    float h = g_h[view][i];
    float v = fmaf(gamma[c] * (h - g_bnm[view][c]), g_bnis[view][c], beta[c]);
    v = fmaxf(v, 0.f);
    g_hf[view][i] = __float2half_rn(v);
}

// ------------------------- z_L row normalization + copy-out ---------------
__global__ void row_scale(float* __restrict__ z1L_out) {
    const int view = blockIdx.y;
    size_t i4 = (size_t)blockIdx.x * 256 + threadIdx.x;
    float4* z = (float4*)g_zL[view];
    float4 v = z[i4];
    int row = (int)((i4 * 4) >> 10);
    float rs = rsqrtf(g_rowss[view][row]);
    v.x *= rs; v.y *= rs; v.z *= rs; v.w *= rs;
    z[i4] = v;
    if (view == 0) {
        size_t b = i4 * 4;
        z1L_out[b]   = v.x;
        z1L_out[b+1] = v.y;
        z1L_out[b+2] = v.z;
        z1L_out[b+3] = v.w;
    }
}

// ------------------------- cosine(z_H, y_other) mean ----------------------
__global__ void __launch_bounds__(256) cos_kernel(const float* __restrict__ z1H,
                                                  const float* __restrict__ y1,
                                                  const float* __restrict__ y2) {
    const int pair = blockIdx.y;
    const float* a = pair ? g_zH2 : z1H;
    const float* b = pair ? y1 : y2;
    const int tid = threadIdx.x, lane = tid & 31, wid = tid >> 5;
    __shared__ float sw[8];
    float local = 0.f;
    for (int row = blockIdx.x * 8 + wid; row < B_; row += gridDim.x * 8) {
        const float* ar = a + (size_t)row * DOUT;
        const float* br = b + (size_t)row * DOUT;
        float d = 0.f, na = 0.f, nb = 0.f;
        for (int j = lane; j < DOUT; j += 32) {
            float x = ar[j], y = br[j];
            d  = fmaf(x, y, d);
            na = fmaf(x, x, na);
            nb = fmaf(y, y, nb);
        }
#pragma unroll
        for (int o = 16; o; o >>= 1) {
            d  += __shfl_xor_sync(0xffffffffu, d, o);
            na += __shfl_xor_sync(0xffffffffu, na, o);
            nb += __shfl_xor_sync(0xffffffffu, nb, o);
        }
        local += d / (fmaxf(sqrtf(na), 1e-8f) * fmaxf(sqrtf(nb), 1e-8f));
    }
    if (lane == 0) sw[wid] = local;
    __syncthreads();
    if (tid == 0) {
        float s = 0.f;
        for (int i = 0; i < 8; i++) s += sw[i];
        atomicAdd(&g_scal[pair], s);
    }
}

// ------------------------- kmeans ------------------------------------------
// seed: csum buf2 = first KC rows, ccnt buf2 = 1  (centers = csum/ccnt)
__global__ void km_init() {
    const int view = blockIdx.y, k = blockIdx.x, tid = threadIdx.x;
    for (int j = tid; j < DCLD; j += 256)
        g_csum3[2][view][k * DCLD + j] = g_zL[view][(size_t)k * DCLD + j];
    if (tid == 0) g_ccnt3[2][view][k] = 1.f;
}

// one full kmeans iteration: build centers from csum[rbuf], label 128 rows,
// accumulate segment sums into csum[wbuf], zero csum[zbuf] slice.
__global__ void __launch_bounds__(256) km_step(int it) {
    extern __shared__ float sm[];
    float* sc = sm;                 // KC*DCLD centers
    float* ps = sm + KC * DCLD;     // KC*DCLD partial sums
    __shared__ float sinv[KC], scn2[KC];
    __shared__ float sred[KC][8];
    __shared__ int   scnt[KC], slab[128];
    const int view = blockIdx.y;
    const int tid = threadIdx.x, lane = tid & 31, wid = tid >> 5;
    const int rbuf = (it + 2) % 3, wbuf = it % 3, zbuf = (it + 1) % 3;
    const float* z = g_zL[view];

    if (tid < KC) {
        sinv[tid] = 1.f / fmaxf(g_ccnt3[rbuf][view][tid], 1.f);
        scnt[tid] = 0;
    }
    __syncthreads();
    for (int i = tid; i < KC * DCLD; i += 256) {
        sc[i] = g_csum3[rbuf][view][i] * sinv[i >> 10];
        ps[i] = 0.f;
    }
    __syncthreads();
    // centers' squared norms (block-wide, one sync)
    float loc[KC];
#pragma unroll
    for (int k = 0; k < KC; k++) {
        float s = 0.f;
#pragma unroll
        for (int j = 0; j < 4; j++) {
            float v = sc[k * DCLD + tid + j * 256];
            s = fmaf(v, v, s);
        }
        loc[k] = s;
    }
#pragma unroll
    for (int k = 0; k < KC; k++)
#pragma unroll
        for (int o = 16; o; o >>= 1)
            loc[k] += __shfl_xor_sync(0xffffffffu, loc[k], o);
    if (lane == 0)
#pragma unroll
        for (int k = 0; k < KC; k++) sred[k][wid] = loc[k];
    __syncthreads();
    if (tid < KC) {
        float s = 0.f;
#pragma unroll
        for (int w = 0; w < 8; w++) s += sred[tid][w];
        scn2[tid] = s;
    }
    __syncthreads();

    const int rbase = blockIdx.x * 128;
    // phase A: labels (warp per row, 16 rows per warp)
    for (int rr = 0; rr < 16; rr++) {
        const int r = wid * 16 + rr;
        const float4* xr = (const float4*)(z + (size_t)(rbase + r) * DCLD);
        float dots[KC];
#pragma unroll
        for (int k = 0; k < KC; k++) dots[k] = 0.f;
        for (int j = lane; j < DCLD / 4; j += 32) {
            float4 xv = xr[j];
#pragma unroll
            for (int k = 0; k < KC; k++) {
                float4 cv = *(const float4*)&sc[k * DCLD + 4 * j];
                dots[k] += xv.x * cv.x + xv.y * cv.y + xv.z * cv.z + xv.w * cv.w;
            }
        }
#pragma unroll
        for (int k = 0; k < KC; k++)
#pragma unroll
            for (int o = 16; o; o >>= 1)
                dots[k] += __shfl_xor_sync(0xffffffffu, dots[k], o);
        int bi = 0;
        float bd = scn2[0] - 2.f * dots[0];
#pragma unroll
        for (int k = 1; k < KC; k++) {
            float d = scn2[k] - 2.f * dots[k];
            if (d < bd) { bd = d; bi = k; }   // strict <: first-min like argmin
        }
        if (lane == 0) {
            g_cl[view][rbase + r] = bi;
            atomicAdd(&scnt[bi], 1);
            slab[r] = bi;
        }
    }
    __syncthreads();
    // phase B: column-owned accumulation
    for (int r = 0; r < 128; r++) {
        const int lb = slab[r];
        const float* zr = z + (size_t)(rbase + r) * DCLD;
#pragma unroll
        for (int j = 0; j < 4; j++)
            ps[lb * DCLD + tid + j * 256] += zr[tid + j * 256];
    }
    __syncthreads();
    for (int i = tid; i < KC * DCLD; i += 256) {
        float v = ps[i];
        if (v != 0.f) atomicAdd(&g_csum3[wbuf][view][i], v);
    }
    if (tid < KC && scnt[tid]) atomicAdd(&g_ccnt3[wbuf][view][tid], (float)scnt[tid]);
    // zero zbuf (read last iteration; next written at it+1 after launch boundary)
    if (tid < KC * DCLD / 64)
        g_csum3[zbuf][view][blockIdx.x * (KC * DCLD / 64) + tid] = 0.f;
    if (blockIdx.x == 0 && tid < KC) g_ccnt3[zbuf][view][tid] = 0.f;
}

// ------------------------- cross entropy -----------------------------------
// final centers = csum[(NIT-1)%3] / ccnt ; labels = g_cl (iteration NIT)
#define CE_BUF ((NIT - 1) % 3)
__global__ void __launch_bounds__(256) ce_kernel() {
    __shared__ float sc[KC * DCLD];
    __shared__ float swarp[8];
    __shared__ float sinv[KC];
    const int view = blockIdx.y;
    const float* z   = g_zL[view];
    const int*   lab = g_cl[view ^ 1];
    const int tid = threadIdx.x;
    if (tid < KC)
        sinv[tid] = 1.f / fmaxf(g_ccnt3[CE_BUF][view ^ 1][tid], 1.f);
    __syncthreads();
    for (int i = tid; i < KC * DCLD; i += 256)
        sc[i] = g_csum3[CE_BUF][view ^ 1][i] * sinv[i >> 10];
    __syncthreads();
    const int lane = tid & 31, wid = tid >> 5;
    float local = 0.f;
    const float invT = 1.f / 0.07f;
    for (int row = blockIdx.x * 8 + wid; row < B_; row += gridDim.x * 8) {
        const float4* xr = (const float4*)(z + (size_t)row * DCLD);
        float dots[KC];
#pragma unroll
        for (int k = 0; k < KC; k++) dots[k] = 0.f;
        for (int j = lane; j < DCLD / 4; j += 32) {
            float4 xv = xr[j];
#pragma unroll
            for (int k = 0; k < KC; k++) {
                float4 cv = *(const float4*)&sc[k * DCLD + 4 * j];
                dots[k] += xv.x * cv.x + xv.y * cv.y + xv.z * cv.z + xv.w * cv.w;
            }
        }
#pragma unroll
        for (int k = 0; k < KC; k++)
#pragma unroll
            for (int o = 16; o; o >>= 1)
                dots[k] += __shfl_xor_sync(0xffffffffu, dots[k], o);
        float m = -1e30f;
#pragma unroll
        for (int k = 0; k < KC; k++) { dots[k] *= invT; m = fmaxf(m, dots[k]); }
        float s = 0.f;
#pragma unroll
        for (int k = 0; k < KC; k++) s += expf(dots[k] - m);
        float lse = logf(s) + m;
        local += lse - dots[lab[row]];
    }
    if (lane == 0) swarp[wid] = local;
    __syncthreads();
    if (tid == 0) {
        float s = 0.f;
        for (int i = 0; i < 8; i++) s += swarp[i];
        atomicAdd(&g_scal[2 + view], s);
    }
}

// ------------------------- finalize ----------------------------------------
__global__ void final_kernel(float* __restrict__ out,
                             const float* __restrict__ Lam) {
    if (threadIdx.x == 0) {
        float cos1 = g_scal[0] * (1.f / B_);
        float cos2 = g_scal[1] * (1.f / B_);
        float lss  = 2.f - cos1 - cos2;
        float ce1  = g_scal[2] * (1.f / B_);
        float ce2  = g_scal[3] * (1.f / B_);
        float lcld = 0.5f * (ce1 + ce2);
        out[0] = lss + (*Lam) * lcld;
        out[1] = lss;
        out[2] = lcld;
    }
}

// ------------------------- host launcher -----------------------------------
extern "C" void kernel_launch(void* const* d_in, const int* in_sizes, int n_in,
                              void* d_out, int out_size)
{
    (void)in_sizes; (void)n_in; (void)out_size;
    const float* y1    = (const float*)d_in[0];
    const float* y2    = (const float*)d_in[1];
    const float* Lam   = (const float*)d_in[2];
    const float* W1    = (const float*)d_in[3];
    const float* b1    = (const float*)d_in[4];
    const float* gamma = (const float*)d_in[5];
    const float* beta  = (const float*)d_in[6];
    const float* W2    = (const float*)d_in[7];
    const float* b2    = (const float*)d_in[8];
    const float* Wc    = (const float*)d_in[9];
    float* out = (float*)d_out;
    float* z1H = out + 3;
    float* z1L = out + 3 + (size_t)B_ * DOUT;

    float *p_h = 0, *p_zH2 = 0, *p_zL = 0, *p_wcinv = 0, *p_rowss = 0;
    __half *p_yf = 0, *p_hf = 0;
    __half *p_w1h = 0, *p_w1l = 0, *p_w2h = 0, *p_w2l = 0, *p_wch = 0, *p_wcl = 0;
    cudaGetSymbolAddress((void**)&p_h,     g_h);
    cudaGetSymbolAddress((void**)&p_zH2,   g_zH2);
    cudaGetSymbolAddress((void**)&p_zL,    g_zL);
    cudaGetSymbolAddress((void**)&p_wcinv, g_wcinv);
    cudaGetSymbolAddress((void**)&p_rowss, g_rowss);
    cudaGetSymbolAddress((void**)&p_yf,    g_yf);
    cudaGetSymbolAddress((void**)&p_hf,    g_hf);
    cudaGetSymbolAddress((void**)&p_w1h,   g_w1h);
    cudaGetSymbolAddress((void**)&p_w1l,   g_w1l);
    cudaGetSymbolAddress((void**)&p_w2h,   g_w2h);
    cudaGetSymbolAddress((void**)&p_w2l,   g_w2l);
    cudaGetSymbolAddress((void**)&p_wch,   g_wch);
    cudaGetSymbolAddress((void**)&p_wcl,   g_wcl);

    cudaFuncSetAttribute(mma_gemm<0>, cudaFuncAttributeMaxDynamicSharedMemorySize,
                         GEMM_SMEM);
    cudaFuncSetAttribute(mma_gemm<1>, cudaFuncAttributeMaxDynamicSharedMemorySize,
                         GEMM_SMEM);
    const int KM_SMEM = 2 * KC * DCLD * (int)sizeof(float);
    cudaFuncSetAttribute(km_step, cudaFuncAttributeMaxDynamicSharedMemorySize,
                         KM_SMEM);

    const int NY4 = B_ * DIN / 4;

    // launches 1-3: GEMM1 prerequisites; launch 4 = GEMM1 (ncu captures #4)
    conv_fp16<<<NY4 / 256, 256>>>((const float4*)y1, (uint2*)p_yf, NY4);
    conv_fp16<<<NY4 / 256, 256>>>((const float4*)y2,
        (uint2*)(p_yf + (size_t)B_ * DIN), NY4);
    split_w16<<<(DIN * DHID / 4) / 256, 256>>>((const float4*)W1,
        (uint2*)p_w1h, (uint2*)p_w1l, DIN * DHID / 4);

    // GEMM1: h = y @ W1 + b1 (both views via z-dim)
    mma_gemm<0><<<dim3(DHID / 128, B_ / 128, 2), 256, GEMM_SMEM>>>(
        p_yf, p_yf + (size_t)B_ * DIN,
        p_h, p_h + (size_t)B_ * DHID,
        p_w1h, p_w1l, b1, 0, 0, DHID, DIN);

    init_zero<<<160, 256>>>();
    wc_part<<<dim3(DCLD / 256, 16), 256>>>(Wc);
    wc_fin<<<DCLD / 256, 256>>>();
    split_w16<<<(DHID * DOUT / 4) / 256, 256>>>((const float4*)W2,
        (uint2*)p_w2h, (uint2*)p_w2l, DHID * DOUT / 4);
    split_w16<<<(DIN * DCLD / 4) / 256, 256>>>((const float4*)Wc,
        (uint2*)p_wch, (uint2*)p_wcl, DIN * DCLD / 4);

    for (int v = 0; v < 2; v++) bn_partial<<<dim3(DHID / 256, 32), 256>>>(v);
    for (int v = 0; v < 2; v++) bn_finish<<<DHID / 256, 256>>>(v);
    for (int v = 0; v < 2; v++) bn_relu<<<(B_ * DHID) / 256, 256>>>(v, gamma, beta);

    // GEMM2: z_H = relu_h @ W2 + b2
    mma_gemm<0><<<dim3(DOUT / 128, B_ / 128, 2), 256, GEMM_SMEM>>>(
        p_hf, p_hf + (size_t)B_ * DHID,
        z1H, p_zH2,
        p_w2h, p_w2l, b2, 0, 0, DOUT, DHID);

    // GEMM3: z_L_pre = (y @ Wc) * wcinv  (+ row sumsq)
    mma_gemm<1><<<dim3(DCLD / 128, B_ / 128, 2), 256, GEMM_SMEM>>>(
        p_yf, p_yf + (size_t)B_ * DIN,
        p_zL, p_zL + (size_t)B_ * DCLD,
        p_wch, p_wcl, p_wcinv, p_rowss, p_rowss + B_, DCLD, DIN);

    row_scale<<<dim3((B_ * DCLD / 4) / 256, 2), 256>>>(z1L);
    cos_kernel<<<dim3(128, 2), 256>>>(z1H, y1, y2);

    km_init<<<dim3(KC, 2), 256>>>();
    for (int it = 0; it < NIT; it++)
        km_step<<<dim3(B_ / 128, 2), 256, KM_SMEM>>>(it);

    ce_kernel<<<dim3(64, 2), 256>>>();
    final_kernel<<<1, 32>>>(out, Lam);
}

// round 12
// speedup vs baseline: 3.8015x; 1.2704x over previous
#include <cuda_runtime.h>
#include <cuda_fp16.h>
#include <cstdint>

#define B_    8192
#define DIN   2048
#define DHID  512
#define DOUT  2048
#define DCLD  1024
#define KC    10
#define NIT   10

// ------------------------- device scratch (static, no runtime alloc) ------
__device__ float g_h[2][B_*DHID];          // hidden activations fp32 (for BN stats)
__device__ float g_zH2[B_*DOUT];           // z2_H
__device__ float g_zL[2][B_*DCLD];         // aligned internal copies of z1_L/z2_L
__device__ float g_wcsq[DCLD];
__device__ float g_wcinv[DCLD];
__device__ float g_bns[2][DHID];
__device__ float g_bns2[2][DHID];
__device__ float g_bnm[2][DHID];
__device__ float g_bnis[2][DHID];
__device__ float g_rowss[2][B_];
__device__ float g_csum3[3][2][KC*DCLD];   // rotating kmeans segment sums
__device__ float g_ccnt3[3][2][KC];
__device__ int   g_cl[2][B_];
__device__ float g_scal[4];                // cos1_sum, cos2_sum, ce1_sum, ce2_sum
// fp16 operands
__device__ __half g_yf[2][B_*DIN];
__device__ __half g_hf[2][B_*DHID];
__device__ __half g_w1f[DIN*DHID];
__device__ __half g_w2f[DHID*DOUT];
__device__ __half g_wcf[DIN*DCLD];

// ------------------------- helpers ---------------------------------------
__device__ __forceinline__ void ldsm_x4(uint32_t* r, uint32_t addr) {
    asm volatile("ldmatrix.sync.aligned.m8n8.x4.shared.b16 {%0,%1,%2,%3}, [%4];\n"
        : "=r"(r[0]), "=r"(r[1]), "=r"(r[2]), "=r"(r[3]) : "r"(addr));
}
__device__ __forceinline__ void ldsm_x4_t(uint32_t* r, uint32_t addr) {
    asm volatile("ldmatrix.sync.aligned.m8n8.x4.trans.shared.b16 {%0,%1,%2,%3}, [%4];\n"
        : "=r"(r[0]), "=r"(r[1]), "=r"(r[2]), "=r"(r[3]) : "r"(addr));
}
__device__ __forceinline__ void mma16816h(float* c, const uint32_t* a, const uint32_t* b) {
    asm volatile(
        "mma.sync.aligned.m16n8k16.row.col.f32.f16.f16.f32 "
        "{%0,%1,%2,%3}, {%4,%5,%6,%7}, {%8,%9}, {%0,%1,%2,%3};\n"
        : "+f"(c[0]), "+f"(c[1]), "+f"(c[2]), "+f"(c[3])
        : "r"(a[0]), "r"(a[1]), "r"(a[2]), "r"(a[3]), "r"(b[0]), "r"(b[1]));
}

#define CP_ASYNC16(dst, src) \
    asm volatile("cp.async.cg.shared.global [%0], [%1], 16;\n" \
        :: "r"(dst), "l"((const void*)(src)))
#define CP_COMMIT() asm volatile("cp.async.commit_group;\n" ::: "memory")
#define CP_WAIT2()  asm volatile("cp.async.wait_group 2;\n" ::: "memory")

__device__ __forceinline__ uint32_t packh2(float a, float b) {
    __half ha = __float2half_rn(a), hb = __float2half_rn(b);
    return ((uint32_t)__half_as_ushort(hb) << 16) | (uint32_t)__half_as_ushort(ha);
}

// ------------------------- init / preprocessing ---------------------------
__global__ void init_zero() {
    int i = blockIdx.x * 256 + threadIdx.x;   // 160 blocks
    if (i < 4) g_scal[i] = 0.f;
    if (i < 2 * B_) ((float*)g_rowss)[i] = 0.f;
    if (i < 2 * 2 * KC * DCLD) ((float*)g_csum3)[i] = 0.f;   // bufs 0,1
    if (i < 2 * 2 * KC) ((float*)g_ccnt3)[i] = 0.f;          // bufs 0,1
    if (i < DCLD) g_wcsq[i] = 0.f;
}

__global__ void wc_part(const float* __restrict__ Wc) {   // grid (4,16)
    int c  = blockIdx.x * 256 + threadIdx.x;
    int r0 = blockIdx.y * 128;
    float s = 0.f;
    for (int r = r0; r < r0 + 128; r++) {
        float v = Wc[(size_t)r * DCLD + c];
        s = fmaf(v, v, s);
    }
    atomicAdd(&g_wcsq[c], s);
}
__global__ void wc_fin() {
    int c = blockIdx.x * 256 + threadIdx.x;
    if (c < DCLD) g_wcinv[c] = 1.f / fmaxf(sqrtf(g_wcsq[c]), 1e-12f);
}

// fp32 -> fp16; optionally zeroes BN stat accumulators (first launch only)
__global__ void conv_fp16(const float4* __restrict__ src, uint2* __restrict__ dst,
                          int n4, int zflag) {
    int i = blockIdx.x * 256 + threadIdx.x;
    if (zflag && i < 2 * DHID) {
        ((float*)g_bns)[i]  = 0.f;
        ((float*)g_bns2)[i] = 0.f;
    }
    if (i >= n4) return;
    float4 v = src[i];
    dst[i] = make_uint2(packh2(v.x, v.y), packh2(v.z, v.w));
}

// ------------------------- pipelined mma.sync GEMM ------------------------
// Block 128x128, 8 warps (warp 32x64), K-chunks of 32, 4-stage cp.async ring,
// ONE __syncthreads per chunk, 2 CTAs/SM. Single fp16 x fp16, fp32 accum.
// MODE 0: C = A*B + aux[col]   (scalar stores: C may be only 4B-aligned)
// MODE 1: C = (A*B)*aux[col] + per-row sumsq atomics into rowss.
// MODE 2: C = A*B + aux[col] (aligned, float2) + BN column sum/sumsq atomics.
#define APAD 40            // A smem row: 32 k + 8 pad halfs; 80 B/row
#define BPAD 136           // B smem row: 128 n + 8 pad halfs; 272 B/row
#define ST_A 10240         // 128*APAD*2
#define ST_B 8704          // 32*BPAD*2
#define STAGE 18944        // ST_A + ST_B
#define NSTG  4
#define GEMM_SMEM (NSTG * STAGE)

template<int MODE>
__global__ void __launch_bounds__(256, 2) mma_gemm(
    const __half* __restrict__ Af0, const __half* __restrict__ Af1,
    float* __restrict__ C0, float* __restrict__ C1,
    const __half* __restrict__ B_g,
    const float* __restrict__ aux,
    float* __restrict__ rowss0, float* __restrict__ rowss1,
    int N, int Kd)
{
    extern __shared__ char smc[];
    const int tid  = threadIdx.x;
    const int lane = tid & 31;
    const int warp = tid >> 5;
    const int wm   = warp >> 1;       // 0..3
    const int wn   = warp & 1;        // 0..1
    const int mBase = blockIdx.y * 128;
    const int nBase = blockIdx.x * 128;
    const int view = blockIdx.z;
    const __half* A_g = view ? Af1 : Af0;
    float* C     = view ? C1 : C0;
    float* rowss = view ? rowss1 : rowss0;

    const uint32_t sb = (uint32_t)__cvta_generic_to_shared(smc);

    // cp.async coords (per thread: A 2x16B, B 2x16B per chunk)
    const int arow = tid >> 2, aseg = tid & 3;      // rows + i*64
    const int brow = tid >> 4, bseg = tid & 15;     // rows + i*16

    // ldmatrix per-lane element offsets
    const int l7 = lane & 7;
    const int aRowSel = l7 + ((lane & 8) ? 8 : 0);
    const int aKSel   = (lane & 16) ? 8 : 0;
    uint32_t aoff[2];
#pragma unroll
    for (int i = 0; i < 2; i++)
        aoff[i] = (uint32_t)((wm * 32 + i * 16 + aRowSel) * APAD + aKSel);
    const int bKSel = l7 + ((lane & 8) ? 8 : 0);
    const int bNSel = (lane & 16) ? 8 : 0;
    uint32_t boff[4];
#pragma unroll
    for (int jp = 0; jp < 4; jp++)
        boff[jp] = (uint32_t)(bKSel * BPAD + wn * 64 + jp * 16 + bNSel);

    float acc[2][8][4];
#pragma unroll
    for (int i = 0; i < 2; i++)
#pragma unroll
        for (int j = 0; j < 8; j++)
#pragma unroll
            for (int r = 0; r < 4; r++) acc[i][j][r] = 0.f;

    const int nk = Kd >> 5;

#define LOAD_CHUNK(kt, s) do { \
    const int _k0 = (kt) * 32; \
    const uint32_t _st = sb + (uint32_t)(s) * STAGE; \
    _Pragma("unroll") \
    for (int _i = 0; _i < 2; _i++) { \
        int _ar = arow + _i * 64; \
        CP_ASYNC16(_st + _ar * 80 + aseg * 16, \
                   A_g + (size_t)(mBase + _ar) * Kd + _k0 + aseg * 8); \
        int _br = brow + _i * 16; \
        CP_ASYNC16(_st + ST_A + _br * 272 + bseg * 16, \
                   B_g + (size_t)(_k0 + _br) * N + nBase + bseg * 8); \
    } \
    CP_COMMIT(); \
} while (0)

    LOAD_CHUNK(0, 0);
    LOAD_CHUNK(1, 1);
    LOAD_CHUNK(2, 2);

    for (int kt = 0; kt < nk; kt++) {
        CP_WAIT2();
        __syncthreads();   // all warps done reading stage (kt-1)&3 before reuse
        if (kt + 3 < nk) LOAD_CHUNK(kt + 3, (kt + 3) & 3);

        const uint32_t st = sb + (uint32_t)(kt & 3) * STAGE;
        const uint32_t aB = st;
        const uint32_t bBs = st + ST_A;
#pragma unroll
        for (int ks = 0; ks < 2; ks++) {
            uint32_t a[2][4];
#pragma unroll
            for (int i = 0; i < 2; i++)
                ldsm_x4(a[i], aB + (aoff[i] + ks * 16) * 2u);
            uint32_t b[4][4];
#pragma unroll
            for (int jp = 0; jp < 4; jp++)
                ldsm_x4_t(b[jp], bBs + (boff[jp] + ks * 16 * BPAD) * 2u);
#pragma unroll
            for (int i = 0; i < 2; i++)
#pragma unroll
                for (int jp = 0; jp < 4; jp++) {
                    mma16816h(acc[i][2 * jp],     a[i], &b[jp][0]);
                    mma16816h(acc[i][2 * jp + 1], a[i], &b[jp][2]);
                }
        }
    }

    // epilogue
    const int g  = lane >> 2;
    const int t4 = lane & 3;
    if (MODE == 2) {
        // aligned float2 stores + BN column statistics
#pragma unroll
        for (int j = 0; j < 8; j++) {
            const int n = nBase + wn * 64 + j * 8 + 2 * t4;
            const float a0 = aux[n], a1 = aux[n + 1];
            float sA = 0.f, sB = 0.f, qA = 0.f, qB = 0.f;
#pragma unroll
            for (int i = 0; i < 2; i++) {
                const int r0 = mBase + wm * 32 + i * 16 + g;
                float v0 = acc[i][j][0] + a0, v1 = acc[i][j][1] + a1;
                float v2 = acc[i][j][2] + a0, v3 = acc[i][j][3] + a1;
                *(float2*)(C + (size_t)r0 * N + n)       = make_float2(v0, v1);
                *(float2*)(C + (size_t)(r0 + 8) * N + n) = make_float2(v2, v3);
                sA += v0 + v2;
                sB += v1 + v3;
                qA = fmaf(v0, v0, fmaf(v2, v2, qA));
                qB = fmaf(v1, v1, fmaf(v3, v3, qB));
            }
#pragma unroll
            for (int o = 4; o <= 16; o <<= 1) {
                sA += __shfl_xor_sync(0xffffffffu, sA, o);
                sB += __shfl_xor_sync(0xffffffffu, sB, o);
                qA += __shfl_xor_sync(0xffffffffu, qA, o);
                qB += __shfl_xor_sync(0xffffffffu, qB, o);
            }
            if (lane < 4) {   // lane == t4 group representative
                atomicAdd(&g_bns[view][n],      sA);
                atomicAdd(&g_bns[view][n + 1],  sB);
                atomicAdd(&g_bns2[view][n],     qA);
                atomicAdd(&g_bns2[view][n + 1], qB);
            }
        }
        return;
    }
#pragma unroll
    for (int i = 0; i < 2; i++) {
        const int r0 = mBase + wm * 32 + i * 16 + g;
        float s0 = 0.f, s1 = 0.f;
#pragma unroll
        for (int j = 0; j < 8; j++) {
            const int n = nBase + wn * 64 + j * 8 + 2 * t4;
            float a0 = aux[n], a1 = aux[n + 1];
            if (MODE == 0) {
                float* c0 = C + (size_t)r0 * N + n;
                float* c1 = C + (size_t)(r0 + 8) * N + n;
                c0[0] = acc[i][j][0] + a0;
                c0[1] = acc[i][j][1] + a1;
                c1[0] = acc[i][j][2] + a0;
                c1[1] = acc[i][j][3] + a1;
            } else {
                float v0 = acc[i][j][0] * a0, v1 = acc[i][j][1] * a1;
                float v2 = acc[i][j][2] * a0, v3 = acc[i][j][3] * a1;
                *(float2*)(C + (size_t)r0 * N + n)       = make_float2(v0, v1);
                *(float2*)(C + (size_t)(r0 + 8) * N + n) = make_float2(v2, v3);
                s0 = fmaf(v0, v0, fmaf(v1, v1, s0));
                s1 = fmaf(v2, v2, fmaf(v3, v3, s1));
            }
        }
        if (MODE == 1) {
            s0 += __shfl_xor_sync(0xffffffffu, s0, 1);
            s0 += __shfl_xor_sync(0xffffffffu, s0, 2);
            s1 += __shfl_xor_sync(0xffffffffu, s1, 1);
            s1 += __shfl_xor_sync(0xffffffffu, s1, 2);
            if (t4 == 0) {
                atomicAdd(&rowss[r0], s0);
                atomicAdd(&rowss[r0 + 8], s1);
            }
        }
    }
#undef LOAD_CHUNK
}

// ------------------------- batchnorm --------------------------------------
__global__ void bn_finish(int view) {
    int c = blockIdx.x * 256 + threadIdx.x;
    if (c >= DHID) return;
    float m = g_bns[view][c] * (1.f / B_);
    float v = g_bns2[view][c] * (1.f / B_) - m * m;
    g_bnm[view][c]  = m;
    g_bnis[view][c] = rsqrtf(v + 1e-5f);
}

// BN+relu, emits fp16 activation for GEMM2
__global__ void bn_relu(int view, const float* __restrict__ gamma,
                        const float* __restrict__ beta) {
    int i = blockIdx.x * 256 + threadIdx.x;
    int c = i & (DHID - 1);
    float h = g_h[view][i];
    float v = fmaf(gamma[c] * (h - g_bnm[view][c]), g_bnis[view][c], beta[c]);
    v = fmaxf(v, 0.f);
    g_hf[view][i] = __float2half_rn(v);
}

// ------------------------- z_L row normalization + copy-out ---------------
__global__ void row_scale(float* __restrict__ z1L_out) {
    const int view = blockIdx.y;
    size_t i4 = (size_t)blockIdx.x * 256 + threadIdx.x;
    float4* z = (float4*)g_zL[view];
    float4 v = z[i4];
    int row = (int)((i4 * 4) >> 10);
    float rs = rsqrtf(g_rowss[view][row]);
    v.x *= rs; v.y *= rs; v.z *= rs; v.w *= rs;
    z[i4] = v;
    if (view == 0) {
        size_t b = i4 * 4;
        z1L_out[b]   = v.x;
        z1L_out[b+1] = v.y;
        z1L_out[b+2] = v.z;
        z1L_out[b+3] = v.w;
    }
}

// ------------------------- cosine(z_H, y_other) mean ----------------------
__global__ void __launch_bounds__(256) cos_kernel(const float* __restrict__ z1H,
                                                  const float* __restrict__ y1,
                                                  const float* __restrict__ y2) {
    const int pair = blockIdx.y;
    const float* a = pair ? g_zH2 : z1H;
    const float* b = pair ? y1 : y2;
    const int tid = threadIdx.x, lane = tid & 31, wid = tid >> 5;
    __shared__ float sw[8];
    float local = 0.f;
    for (int row = blockIdx.x * 8 + wid; row < B_; row += gridDim.x * 8) {
        const float* ar = a + (size_t)row * DOUT;
        const float* br = b + (size_t)row * DOUT;
        float d = 0.f, na = 0.f, nb = 0.f;
        for (int j = lane; j < DOUT; j += 32) {
            float x = ar[j], y = br[j];
            d  = fmaf(x, y, d);
            na = fmaf(x, x, na);
            nb = fmaf(y, y, nb);
        }
#pragma unroll
        for (int o = 16; o; o >>= 1) {
            d  += __shfl_xor_sync(0xffffffffu, d, o);
            na += __shfl_xor_sync(0xffffffffu, na, o);
            nb += __shfl_xor_sync(0xffffffffu, nb, o);
        }
        local += d / (fmaxf(sqrtf(na), 1e-8f) * fmaxf(sqrtf(nb), 1e-8f));
    }
    if (lane == 0) sw[wid] = local;
    __syncthreads();
    if (tid == 0) {
        float s = 0.f;
        for (int i = 0; i < 8; i++) s += sw[i];
        atomicAdd(&g_scal[pair], s);
    }
}

// ------------------------- kmeans ------------------------------------------
// seed: csum buf2 = first KC rows, ccnt buf2 = 1  (centers = csum/ccnt)
__global__ void km_init() {
    const int view = blockIdx.y, k = blockIdx.x, tid = threadIdx.x;
    for (int j = tid; j < DCLD; j += 256)
        g_csum3[2][view][k * DCLD + j] = g_zL[view][(size_t)k * DCLD + j];
    if (tid == 0) g_ccnt3[2][view][k] = 1.f;
}

// one full kmeans iteration: build centers from csum[rbuf], label 128 rows,
// accumulate segment sums into csum[wbuf], zero csum[zbuf] slice.
__global__ void __launch_bounds__(256) km_step(int it) {
    extern __shared__ float sm[];
    float* sc = sm;                 // KC*DCLD centers
    float* ps = sm + KC * DCLD;     // KC*DCLD partial sums
    __shared__ float sinv[KC], scn2[KC];
    __shared__ float sred[KC][8];
    __shared__ int   scnt[KC], slab[128];
    const int view = blockIdx.y;
    const int tid = threadIdx.x, lane = tid & 31, wid = tid >> 5;
    const int rbuf = (it + 2) % 3, wbuf = it % 3, zbuf = (it + 1) % 3;
    const float* z = g_zL[view];

    if (tid < KC) {
        sinv[tid] = 1.f / fmaxf(g_ccnt3[rbuf][view][tid], 1.f);
        scnt[tid] = 0;
    }
    __syncthreads();
    for (int i = tid; i < KC * DCLD; i += 256) {
        sc[i] = g_csum3[rbuf][view][i] * sinv[i >> 10];
        ps[i] = 0.f;
    }
    __syncthreads();
    // centers' squared norms (block-wide, one sync)
    float loc[KC];
#pragma unroll
    for (int k = 0; k < KC; k++) {
        float s = 0.f;
#pragma unroll
        for (int j = 0; j < 4; j++) {
            float v = sc[k * DCLD + tid + j * 256];
            s = fmaf(v, v, s);
        }
        loc[k] = s;
    }
#pragma unroll
    for (int k = 0; k < KC; k++)
#pragma unroll
        for (int o = 16; o; o >>= 1)
            loc[k] += __shfl_xor_sync(0xffffffffu, loc[k], o);
    if (lane == 0)
#pragma unroll
        for (int k = 0; k < KC; k++) sred[k][wid] = loc[k];
    __syncthreads();
    if (tid < KC) {
        float s = 0.f;
#pragma unroll
        for (int w = 0; w < 8; w++) s += sred[tid][w];
        scn2[tid] = s;
    }
    __syncthreads();

    const int rbase = blockIdx.x * 128;
    // phase A: labels (warp per row, 16 rows per warp)
    for (int rr = 0; rr < 16; rr++) {
        const int r = wid * 16 + rr;
        const float4* xr = (const float4*)(z + (size_t)(rbase + r) * DCLD);
        float dots[KC];
#pragma unroll
        for (int k = 0; k < KC; k++) dots[k] = 0.f;
        for (int j = lane; j < DCLD / 4; j += 32) {
            float4 xv = xr[j];
#pragma unroll
            for (int k = 0; k < KC; k++) {
                float4 cv = *(const float4*)&sc[k * DCLD + 4 * j];
                dots[k] += xv.x * cv.x + xv.y * cv.y + xv.z * cv.z + xv.w * cv.w;
            }
        }
#pragma unroll
        for (int k = 0; k < KC; k++)
#pragma unroll
            for (int o = 16; o; o >>= 1)
                dots[k] += __shfl_xor_sync(0xffffffffu, dots[k], o);
        int bi = 0;
        float bd = scn2[0] - 2.f * dots[0];
#pragma unroll
        for (int k = 1; k < KC; k++) {
            float d = scn2[k] - 2.f * dots[k];
            if (d < bd) { bd = d; bi = k; }   // strict <: first-min like argmin
        }
        if (lane == 0) {
            g_cl[view][rbase + r] = bi;
            atomicAdd(&scnt[bi], 1);
            slab[r] = bi;
        }
    }
    __syncthreads();
    // phase B: column-owned accumulation
    for (int r = 0; r < 128; r++) {
        const int lb = slab[r];
        const float* zr = z + (size_t)(rbase + r) * DCLD;
#pragma unroll
        for (int j = 0; j < 4; j++)
            ps[lb * DCLD + tid + j * 256] += zr[tid + j * 256];
    }
    __syncthreads();
    for (int i = tid; i < KC * DCLD; i += 256) {
        float v = ps[i];
        if (v != 0.f) atomicAdd(&g_csum3[wbuf][view][i], v);
    }
    if (tid < KC && scnt[tid]) atomicAdd(&g_ccnt3[wbuf][view][tid], (float)scnt[tid]);
    // zero zbuf (read last iteration; next written at it+1 after launch boundary)
    if (tid < KC * DCLD / 64)
        g_csum3[zbuf][view][blockIdx.x * (KC * DCLD / 64) + tid] = 0.f;
    if (blockIdx.x == 0 && tid < KC) g_ccnt3[zbuf][view][tid] = 0.f;
}

// ------------------------- cross entropy -----------------------------------
// final centers = csum[(NIT-1)%3] / ccnt ; labels = g_cl (iteration NIT)
#define CE_BUF ((NIT - 1) % 3)
__global__ void __launch_bounds__(256) ce_kernel() {
    __shared__ float sc[KC * DCLD];
    __shared__ float swarp[8];
    __shared__ float sinv[KC];
    const int view = blockIdx.y;
    const float* z   = g_zL[view];
    const int*   lab = g_cl[view ^ 1];
    const int tid = threadIdx.x;
    if (tid < KC)
        sinv[tid] = 1.f / fmaxf(g_ccnt3[CE_BUF][view ^ 1][tid], 1.f);
    __syncthreads();
    for (int i = tid; i < KC * DCLD; i += 256)
        sc[i] = g_csum3[CE_BUF][view ^ 1][i] * sinv[i >> 10];
    __syncthreads();
    const int lane = tid & 31, wid = tid >> 5;
    float local = 0.f;
    const float invT = 1.f / 0.07f;
    for (int row = blockIdx.x * 8 + wid; row < B_; row += gridDim.x * 8) {
        const float4* xr = (const float4*)(z + (size_t)row * DCLD);
        float dots[KC];
#pragma unroll
        for (int k = 0; k < KC; k++) dots[k] = 0.f;
        for (int j = lane; j < DCLD / 4; j += 32) {
            float4 xv = xr[j];
#pragma unroll
            for (int k = 0; k < KC; k++) {
                float4 cv = *(const float4*)&sc[k * DCLD + 4 * j];
                dots[k] += xv.x * cv.x + xv.y * cv.y + xv.z * cv.z + xv.w * cv.w;
            }
        }
#pragma unroll
        for (int k = 0; k < KC; k++)
#pragma unroll
            for (int o = 16; o; o >>= 1)
                dots[k] += __shfl_xor_sync(0xffffffffu, dots[k], o);
        float m = -1e30f;
#pragma unroll
        for (int k = 0; k < KC; k++) { dots[k] *= invT; m = fmaxf(m, dots[k]); }
        float s = 0.f;
#pragma unroll
        for (int k = 0; k < KC; k++) s += expf(dots[k] - m);
        float lse = logf(s) + m;
        local += lse - dots[lab[row]];
    }
    if (lane == 0) swarp[wid] = local;
    __syncthreads();
    if (tid == 0) {
        float s = 0.f;
        for (int i = 0; i < 8; i++) s += swarp[i];
        atomicAdd(&g_scal[2 + view], s);
    }
}

// ------------------------- finalize ----------------------------------------
__global__ void final_kernel(float* __restrict__ out,
                             const float* __restrict__ Lam) {
    if (threadIdx.x == 0) {
        float cos1 = g_scal[0] * (1.f / B_);
        float cos2 = g_scal[1] * (1.f / B_);
        float lss  = 2.f - cos1 - cos2;
        float ce1  = g_scal[2] * (1.f / B_);
        float ce2  = g_scal[3] * (1.f / B_);
        float lcld = 0.5f * (ce1 + ce2);
        out[0] = lss + (*Lam) * lcld;
        out[1] = lss;
        out[2] = lcld;
    }
}

// ------------------------- host launcher -----------------------------------
extern "C" void kernel_launch(void* const* d_in, const int* in_sizes, int n_in,
                              void* d_out, int out_size)
{
    (void)in_sizes; (void)n_in; (void)out_size;
    const float* y1    = (const float*)d_in[0];
    const float* y2    = (const float*)d_in[1];
    const float* Lam   = (const float*)d_in[2];
    const float* W1    = (const float*)d_in[3];
    const float* b1    = (const float*)d_in[4];
    const float* gamma = (const float*)d_in[5];
    const float* beta  = (const float*)d_in[6];
    const float* W2    = (const float*)d_in[7];
    const float* b2    = (const float*)d_in[8];
    const float* Wc    = (const float*)d_in[9];
    float* out = (float*)d_out;
    float* z1H = out + 3;
    float* z1L = out + 3 + (size_t)B_ * DOUT;

    float *p_h = 0, *p_zH2 = 0, *p_zL = 0, *p_wcinv = 0, *p_rowss = 0;
    __half *p_yf = 0, *p_hf = 0, *p_w1f = 0, *p_w2f = 0, *p_wcf = 0;
    cudaGetSymbolAddress((void**)&p_h,     g_h);
    cudaGetSymbolAddress((void**)&p_zH2,   g_zH2);
    cudaGetSymbolAddress((void**)&p_zL,    g_zL);
    cudaGetSymbolAddress((void**)&p_wcinv, g_wcinv);
    cudaGetSymbolAddress((void**)&p_rowss, g_rowss);
    cudaGetSymbolAddress((void**)&p_yf,    g_yf);
    cudaGetSymbolAddress((void**)&p_hf,    g_hf);
    cudaGetSymbolAddress((void**)&p_w1f,   g_w1f);
    cudaGetSymbolAddress((void**)&p_w2f,   g_w2f);
    cudaGetSymbolAddress((void**)&p_wcf,   g_wcf);

    cudaFuncSetAttribute(mma_gemm<0>, cudaFuncAttributeMaxDynamicSharedMemorySize,
                         GEMM_SMEM);
    cudaFuncSetAttribute(mma_gemm<1>, cudaFuncAttributeMaxDynamicSharedMemorySize,
                         GEMM_SMEM);
    cudaFuncSetAttribute(mma_gemm<2>, cudaFuncAttributeMaxDynamicSharedMemorySize,
                         GEMM_SMEM);
    const int KM_SMEM = 2 * KC * DCLD * (int)sizeof(float);
    cudaFuncSetAttribute(km_step, cudaFuncAttributeMaxDynamicSharedMemorySize,
                         KM_SMEM);

    const int NY4 = B_ * DIN / 4;

    // launches 1-3 feed GEMM1; launch 4 = GEMM1 (ncu captures slot 4)
    conv_fp16<<<NY4 / 256, 256>>>((const float4*)y1, (uint2*)p_yf, NY4, 1);
    conv_fp16<<<NY4 / 256, 256>>>((const float4*)y2,
        (uint2*)(p_yf + (size_t)B_ * DIN), NY4, 0);
    conv_fp16<<<(DIN * DHID / 4) / 256, 256>>>((const float4*)W1,
        (uint2*)p_w1f, DIN * DHID / 4, 0);

    // GEMM1: h = y @ W1 + b1 (both views, fused BN column stats)
    mma_gemm<2><<<dim3(DHID / 128, B_ / 128, 2), 256, GEMM_SMEM>>>(
        p_yf, p_yf + (size_t)B_ * DIN,
        p_h, p_h + (size_t)B_ * DHID,
        p_w1f, b1, 0, 0, DHID, DIN);

    init_zero<<<160, 256>>>();
    wc_part<<<dim3(DCLD / 256, 16), 256>>>(Wc);
    wc_fin<<<DCLD / 256, 256>>>();
    conv_fp16<<<(DHID * DOUT / 4) / 256, 256>>>((const float4*)W2,
        (uint2*)p_w2f, DHID * DOUT / 4, 0);
    conv_fp16<<<(DIN * DCLD / 4) / 256, 256>>>((const float4*)Wc,
        (uint2*)p_wcf, DIN * DCLD / 4, 0);

    for (int v = 0; v < 2; v++) bn_finish<<<DHID / 256, 256>>>(v);
    for (int v = 0; v < 2; v++) bn_relu<<<(B_ * DHID) / 256, 256>>>(v, gamma, beta);

    // GEMM2: z_H = relu_h @ W2 + b2
    mma_gemm<0><<<dim3(DOUT / 128, B_ / 128, 2), 256, GEMM_SMEM>>>(
        p_hf, p_hf + (size_t)B_ * DHID,
        z1H, p_zH2,
        p_w2f, b2, 0, 0, DOUT, DHID);

    // GEMM3: z_L_pre = (y @ Wc) * wcinv  (+ row sumsq)
    mma_gemm<1><<<dim3(DCLD / 128, B_ / 128, 2), 256, GEMM_SMEM>>>(
        p_yf, p_yf + (size_t)B_ * DIN,
        p_zL, p_zL + (size_t)B_ * DCLD,
        p_wcf, p_wcinv, p_rowss, p_rowss + B_, DCLD, DIN);

    row_scale<<<dim3((B_ * DCLD / 4) / 256, 2), 256>>>(z1L);
    cos_kernel<<<dim3(128, 2), 256>>>(z1H, y1, y2);

    km_init<<<dim3(KC, 2), 256>>>();
    for (int it = 0; it < NIT; it++)
        km_step<<<dim3(B_ / 128, 2), 256, KM_SMEM>>>(it);

    ce_kernel<<<dim3(64, 2), 256>>>();
    final_kernel<<<1, 32>>>(out, Lam);
}

// round 13
// speedup vs baseline: 4.7117x; 1.2394x over previous
#include <cuda_runtime.h>
#include <cuda_fp16.h>
#include <cstdint>

#define B_    8192
#define DIN   2048
#define DHID  512
#define DOUT  2048
#define DCLD  1024
#define KC    10
#define NIT   10

// ------------------------- device scratch (static, no runtime alloc) ------
__device__ float g_h[2][B_*DHID];          // hidden activations fp32
__device__ float g_zH2[B_*DOUT];           // z2_H
__device__ float g_zL[2][B_*DCLD];         // aligned internal copies of z1_L/z2_L
__device__ float g_wcsq[DCLD];
__device__ float g_wcinv[DCLD];
__device__ float g_bns[2][DHID];
__device__ float g_bns2[2][DHID];
__device__ float g_bnm[2][DHID];
__device__ float g_bnis[2][DHID];
__device__ float g_rowss[2][B_];
__device__ float g_csum3[3][2][KC*DCLD];   // rotating kmeans segment sums
__device__ float g_ccnt3[3][2][KC];
__device__ int   g_cl[2][B_];
__device__ float g_scal[4];                // cos1_sum, cos2_sum, ce1_sum, ce2_sum
// fp16 operands
__device__ __half g_yf[2][B_*DIN];
__device__ __half g_hf[2][B_*DHID];
__device__ __half g_w1f[DIN*DHID];
__device__ __half g_w2f[DHID*DOUT];
__device__ __half g_wcf[DIN*DCLD];

// ------------------------- helpers ---------------------------------------
__device__ __forceinline__ void ldsm_x4(uint32_t* r, uint32_t addr) {
    asm volatile("ldmatrix.sync.aligned.m8n8.x4.shared.b16 {%0,%1,%2,%3}, [%4];\n"
        : "=r"(r[0]), "=r"(r[1]), "=r"(r[2]), "=r"(r[3]) : "r"(addr));
}
__device__ __forceinline__ void ldsm_x4_t(uint32_t* r, uint32_t addr) {
    asm volatile("ldmatrix.sync.aligned.m8n8.x4.trans.shared.b16 {%0,%1,%2,%3}, [%4];\n"
        : "=r"(r[0]), "=r"(r[1]), "=r"(r[2]), "=r"(r[3]) : "r"(addr));
}
__device__ __forceinline__ void mma16816h(float* c, const uint32_t* a, const uint32_t* b) {
    asm volatile(
        "mma.sync.aligned.m16n8k16.row.col.f32.f16.f16.f32 "
        "{%0,%1,%2,%3}, {%4,%5,%6,%7}, {%8,%9}, {%0,%1,%2,%3};\n"
        : "+f"(c[0]), "+f"(c[1]), "+f"(c[2]), "+f"(c[3])
        : "r"(a[0]), "r"(a[1]), "r"(a[2]), "r"(a[3]), "r"(b[0]), "r"(b[1]));
}

#define CP_ASYNC16(dst, src) \
    asm volatile("cp.async.cg.shared.global [%0], [%1], 16;\n" \
        :: "r"(dst), "l"((const void*)(src)))
#define CP_COMMIT() asm volatile("cp.async.commit_group;\n" ::: "memory")
#define CP_WAIT2()  asm volatile("cp.async.wait_group 2;\n" ::: "memory")

__device__ __forceinline__ uint32_t packh2(float a, float b) {
    __half ha = __float2half_rn(a), hb = __float2half_rn(b);
    return ((uint32_t)__half_as_ushort(hb) << 16) | (uint32_t)__half_as_ushort(ha);
}

// ------------------------- init / preprocessing ---------------------------
__global__ void init_zero() {
    int i = blockIdx.x * 256 + threadIdx.x;   // 160 blocks
    if (i < 4) g_scal[i] = 0.f;
    if (i < 2 * B_) ((float*)g_rowss)[i] = 0.f;
    if (i < 2 * 2 * KC * DCLD) ((float*)g_csum3)[i] = 0.f;   // bufs 0,1
    if (i < 2 * 2 * KC) ((float*)g_ccnt3)[i] = 0.f;          // bufs 0,1
    if (i < DCLD) g_wcsq[i] = 0.f;
}

__global__ void wc_part(const float* __restrict__ Wc) {   // grid (4,16)
    int c  = blockIdx.x * 256 + threadIdx.x;
    int r0 = blockIdx.y * 128;
    float s = 0.f;
    for (int r = r0; r < r0 + 128; r++) {
        float v = Wc[(size_t)r * DCLD + c];
        s = fmaf(v, v, s);
    }
    atomicAdd(&g_wcsq[c], s);
}
__global__ void wc_fin() {
    int c = blockIdx.x * 256 + threadIdx.x;
    if (c < DCLD) g_wcinv[c] = 1.f / fmaxf(sqrtf(g_wcsq[c]), 1e-12f);
}

// both y views fp32 -> fp16 in one launch; blockIdx.y==0 also zeroes BN stats
__global__ void conv_y(const float4* __restrict__ y1, const float4* __restrict__ y2,
                       uint2* __restrict__ dst, int n4) {
    int i = blockIdx.x * 256 + threadIdx.x;
    const int vw = blockIdx.y;
    if (vw == 0 && i < 2 * DHID) {
        ((float*)g_bns)[i]  = 0.f;
        ((float*)g_bns2)[i] = 0.f;
    }
    if (i >= n4) return;
    float4 v = vw ? y2[i] : y1[i];
    dst[(size_t)vw * n4 + i] = make_uint2(packh2(v.x, v.y), packh2(v.z, v.w));
}

// fp32 -> fp16 (weights)
__global__ void conv_fp16(const float4* __restrict__ src, uint2* __restrict__ dst,
                          int n4) {
    int i = blockIdx.x * 256 + threadIdx.x;
    if (i >= n4) return;
    float4 v = src[i];
    dst[i] = make_uint2(packh2(v.x, v.y), packh2(v.z, v.w));
}

// ------------------------- pipelined mma.sync GEMM ------------------------
// Block 128x128, 8 warps (warp 32x64), K-chunks of 32, 4-stage cp.async ring,
// ONE __syncthreads per chunk, 2 CTAs/SM. Single fp16 x fp16, fp32 accum.
// MODE 0: C = A*B + aux[col]   (scalar stores: C may be only 4B-aligned)
// MODE 1: C = (A*B)*aux[col] + per-row sumsq atomics into rowss.
// MODE 2: C = A*B + aux[col] (aligned, float2) + BN column sum/sumsq atomics.
#define APAD 40            // A smem row: 32 k + 8 pad halfs; 80 B/row
#define BPAD 136           // B smem row: 128 n + 8 pad halfs; 272 B/row
#define ST_A 10240         // 128*APAD*2
#define ST_B 8704          // 32*BPAD*2
#define STAGE 18944        // ST_A + ST_B
#define NSTG  4
#define GEMM_SMEM (NSTG * STAGE)

template<int MODE>
__global__ void __launch_bounds__(256, 2) mma_gemm(
    const __half* __restrict__ Af0, const __half* __restrict__ Af1,
    float* __restrict__ C0, float* __restrict__ C1,
    const __half* __restrict__ B_g,
    const float* __restrict__ aux,
    float* __restrict__ rowss0, float* __restrict__ rowss1,
    int N, int Kd)
{
    extern __shared__ char smc[];
    const int tid  = threadIdx.x;
    const int lane = tid & 31;
    const int warp = tid >> 5;
    const int wm   = warp >> 1;       // 0..3
    const int wn   = warp & 1;        // 0..1
    const int mBase = blockIdx.y * 128;
    const int nBase = blockIdx.x * 128;
    const int view = blockIdx.z;
    const __half* A_g = view ? Af1 : Af0;
    float* C     = view ? C1 : C0;
    float* rowss = view ? rowss1 : rowss0;

    const uint32_t sb = (uint32_t)__cvta_generic_to_shared(smc);

    // cp.async coords (per thread: A 2x16B, B 2x16B per chunk)
    const int arow = tid >> 2, aseg = tid & 3;      // rows + i*64
    const int brow = tid >> 4, bseg = tid & 15;     // rows + i*16

    // ldmatrix per-lane element offsets
    const int l7 = lane & 7;
    const int aRowSel = l7 + ((lane & 8) ? 8 : 0);
    const int aKSel   = (lane & 16) ? 8 : 0;
    uint32_t aoff[2];
#pragma unroll
    for (int i = 0; i < 2; i++)
        aoff[i] = (uint32_t)((wm * 32 + i * 16 + aRowSel) * APAD + aKSel);
    const int bKSel = l7 + ((lane & 8) ? 8 : 0);
    const int bNSel = (lane & 16) ? 8 : 0;
    uint32_t boff[4];
#pragma unroll
    for (int jp = 0; jp < 4; jp++)
        boff[jp] = (uint32_t)(bKSel * BPAD + wn * 64 + jp * 16 + bNSel);

    float acc[2][8][4];
#pragma unroll
    for (int i = 0; i < 2; i++)
#pragma unroll
        for (int j = 0; j < 8; j++)
#pragma unroll
            for (int r = 0; r < 4; r++) acc[i][j][r] = 0.f;

    const int nk = Kd >> 5;

#define LOAD_CHUNK(kt, s) do { \
    const int _k0 = (kt) * 32; \
    const uint32_t _st = sb + (uint32_t)(s) * STAGE; \
    _Pragma("unroll") \
    for (int _i = 0; _i < 2; _i++) { \
        int _ar = arow + _i * 64; \
        CP_ASYNC16(_st + _ar * 80 + aseg * 16, \
                   A_g + (size_t)(mBase + _ar) * Kd + _k0 + aseg * 8); \
        int _br = brow + _i * 16; \
        CP_ASYNC16(_st + ST_A + _br * 272 + bseg * 16, \
                   B_g + (size_t)(_k0 + _br) * N + nBase + bseg * 8); \
    } \
    CP_COMMIT(); \
} while (0)

    LOAD_CHUNK(0, 0);
    LOAD_CHUNK(1, 1);
    LOAD_CHUNK(2, 2);

    for (int kt = 0; kt < nk; kt++) {
        CP_WAIT2();
        __syncthreads();   // all warps done reading stage (kt-1)&3 before reuse
        if (kt + 3 < nk) LOAD_CHUNK(kt + 3, (kt + 3) & 3);

        const uint32_t st = sb + (uint32_t)(kt & 3) * STAGE;
        const uint32_t aB = st;
        const uint32_t bBs = st + ST_A;
#pragma unroll
        for (int ks = 0; ks < 2; ks++) {
            uint32_t a[2][4];
#pragma unroll
            for (int i = 0; i < 2; i++)
                ldsm_x4(a[i], aB + (aoff[i] + ks * 16) * 2u);
            uint32_t b[4][4];
#pragma unroll
            for (int jp = 0; jp < 4; jp++)
                ldsm_x4_t(b[jp], bBs + (boff[jp] + ks * 16 * BPAD) * 2u);
#pragma unroll
            for (int i = 0; i < 2; i++)
#pragma unroll
                for (int jp = 0; jp < 4; jp++) {
                    mma16816h(acc[i][2 * jp],     a[i], &b[jp][0]);
                    mma16816h(acc[i][2 * jp + 1], a[i], &b[jp][2]);
                }
        }
    }

    // epilogue
    const int g  = lane >> 2;
    const int t4 = lane & 3;
    if (MODE == 2) {
        // aligned float2 stores + BN column statistics
#pragma unroll
        for (int j = 0; j < 8; j++) {
            const int n = nBase + wn * 64 + j * 8 + 2 * t4;
            const float a0 = aux[n], a1 = aux[n + 1];
            float sA = 0.f, sB = 0.f, qA = 0.f, qB = 0.f;
#pragma unroll
            for (int i = 0; i < 2; i++) {
                const int r0 = mBase + wm * 32 + i * 16 + g;
                float v0 = acc[i][j][0] + a0, v1 = acc[i][j][1] + a1;
                float v2 = acc[i][j][2] + a0, v3 = acc[i][j][3] + a1;
                *(float2*)(C + (size_t)r0 * N + n)       = make_float2(v0, v1);
                *(float2*)(C + (size_t)(r0 + 8) * N + n) = make_float2(v2, v3);
                sA += v0 + v2;
                sB += v1 + v3;
                qA = fmaf(v0, v0, fmaf(v2, v2, qA));
                qB = fmaf(v1, v1, fmaf(v3, v3, qB));
            }
#pragma unroll
            for (int o = 4; o <= 16; o <<= 1) {
                sA += __shfl_xor_sync(0xffffffffu, sA, o);
                sB += __shfl_xor_sync(0xffffffffu, sB, o);
                qA += __shfl_xor_sync(0xffffffffu, qA, o);
                qB += __shfl_xor_sync(0xffffffffu, qB, o);
            }
            if (lane < 4) {   // lane == t4 group representative
                atomicAdd(&g_bns[view][n],      sA);
                atomicAdd(&g_bns[view][n + 1],  sB);
                atomicAdd(&g_bns2[view][n],     qA);
                atomicAdd(&g_bns2[view][n + 1], qB);
            }
        }
        return;
    }
#pragma unroll
    for (int i = 0; i < 2; i++) {
        const int r0 = mBase + wm * 32 + i * 16 + g;
        float s0 = 0.f, s1 = 0.f;
#pragma unroll
        for (int j = 0; j < 8; j++) {
            const int n = nBase + wn * 64 + j * 8 + 2 * t4;
            float a0 = aux[n], a1 = aux[n + 1];
            if (MODE == 0) {
                float* c0 = C + (size_t)r0 * N + n;
                float* c1 = C + (size_t)(r0 + 8) * N + n;
                c0[0] = acc[i][j][0] + a0;
                c0[1] = acc[i][j][1] + a1;
                c1[0] = acc[i][j][2] + a0;
                c1[1] = acc[i][j][3] + a1;
            } else {
                float v0 = acc[i][j][0] * a0, v1 = acc[i][j][1] * a1;
                float v2 = acc[i][j][2] * a0, v3 = acc[i][j][3] * a1;
                *(float2*)(C + (size_t)r0 * N + n)       = make_float2(v0, v1);
                *(float2*)(C + (size_t)(r0 + 8) * N + n) = make_float2(v2, v3);
                s0 = fmaf(v0, v0, fmaf(v1, v1, s0));
                s1 = fmaf(v2, v2, fmaf(v3, v3, s1));
            }
        }
        if (MODE == 1) {
            s0 += __shfl_xor_sync(0xffffffffu, s0, 1);
            s0 += __shfl_xor_sync(0xffffffffu, s0, 2);
            s1 += __shfl_xor_sync(0xffffffffu, s1, 1);
            s1 += __shfl_xor_sync(0xffffffffu, s1, 2);
            if (t4 == 0) {
                atomicAdd(&rowss[r0], s0);
                atomicAdd(&rowss[r0 + 8], s1);
            }
        }
    }
#undef LOAD_CHUNK
}

// ------------------------- batchnorm --------------------------------------
__global__ void bn_finish(int view) {
    int c = blockIdx.x * 256 + threadIdx.x;
    if (c >= DHID) return;
    float m = g_bns[view][c] * (1.f / B_);
    float v = g_bns2[view][c] * (1.f / B_) - m * m;
    g_bnm[view][c]  = m;
    g_bnis[view][c] = rsqrtf(v + 1e-5f);
}

// BN+relu, emits fp16 activation for GEMM2
__global__ void bn_relu(int view, const float* __restrict__ gamma,
                        const float* __restrict__ beta) {
    int i = blockIdx.x * 256 + threadIdx.x;
    int c = i & (DHID - 1);
    float h = g_h[view][i];
    float v = fmaf(gamma[c] * (h - g_bnm[view][c]), g_bnis[view][c], beta[c]);
    v = fmaxf(v, 0.f);
    g_hf[view][i] = __float2half_rn(v);
}

// ------------------------- z_L row normalization + copy-out ---------------
__global__ void row_scale(float* __restrict__ z1L_out) {
    const int view = blockIdx.y;
    size_t i4 = (size_t)blockIdx.x * 256 + threadIdx.x;
    float4* z = (float4*)g_zL[view];
    float4 v = z[i4];
    int row = (int)((i4 * 4) >> 10);
    float rs = rsqrtf(g_rowss[view][row]);
    v.x *= rs; v.y *= rs; v.z *= rs; v.w *= rs;
    z[i4] = v;
    if (view == 0) {
        size_t b = i4 * 4;
        z1L_out[b]   = v.x;
        z1L_out[b+1] = v.y;
        z1L_out[b+2] = v.z;
        z1L_out[b+3] = v.w;
    }
}

// ------------------------- cosine(z_H, y_other) mean ----------------------
__global__ void __launch_bounds__(256) cos_kernel(const float* __restrict__ z1H,
                                                  const float* __restrict__ y1,
                                                  const float* __restrict__ y2) {
    const int pair = blockIdx.y;
    const float* a = pair ? g_zH2 : z1H;
    const float* b = pair ? y1 : y2;
    const int tid = threadIdx.x, lane = tid & 31, wid = tid >> 5;
    __shared__ float sw[8];
    float local = 0.f;
    const bool a_vec = (((uintptr_t)a) & 15u) == 0;   // z1H (out+3) is NOT 16B aligned
    for (int row = blockIdx.x * 8 + wid; row < B_; row += gridDim.x * 8) {
        const float* ar = a + (size_t)row * DOUT;
        const float* br = b + (size_t)row * DOUT;
        float d = 0.f, na = 0.f, nb = 0.f;
        if (a_vec) {
            const float4* ar4 = (const float4*)ar;
            const float4* br4 = (const float4*)br;
            for (int j = lane; j < DOUT / 4; j += 32) {
                float4 x = ar4[j], y = br4[j];
                d  = fmaf(x.x, y.x, fmaf(x.y, y.y, fmaf(x.z, y.z, fmaf(x.w, y.w, d))));
                na = fmaf(x.x, x.x, fmaf(x.y, x.y, fmaf(x.z, x.z, fmaf(x.w, x.w, na))));
                nb = fmaf(y.x, y.x, fmaf(y.y, y.y, fmaf(y.z, y.z, fmaf(y.w, y.w, nb))));
            }
        } else {
            const float4* br4 = (const float4*)br;
            for (int j = lane; j < DOUT / 4; j += 32) {
                float4 y = br4[j];
                float x0 = ar[4*j], x1 = ar[4*j+1], x2 = ar[4*j+2], x3 = ar[4*j+3];
                d  = fmaf(x0, y.x, fmaf(x1, y.y, fmaf(x2, y.z, fmaf(x3, y.w, d))));
                na = fmaf(x0, x0, fmaf(x1, x1, fmaf(x2, x2, fmaf(x3, x3, na))));
                nb = fmaf(y.x, y.x, fmaf(y.y, y.y, fmaf(y.z, y.z, fmaf(y.w, y.w, nb))));
            }
        }
#pragma unroll
        for (int o = 16; o; o >>= 1) {
            d  += __shfl_xor_sync(0xffffffffu, d, o);
            na += __shfl_xor_sync(0xffffffffu, na, o);
            nb += __shfl_xor_sync(0xffffffffu, nb, o);
        }
        local += d / (fmaxf(sqrtf(na), 1e-8f) * fmaxf(sqrtf(nb), 1e-8f));
    }
    if (lane == 0) sw[wid] = local;
    __syncthreads();
    if (tid == 0) {
        float s = 0.f;
        for (int i = 0; i < 8; i++) s += sw[i];
        atomicAdd(&g_scal[pair], s);
    }
}

// ------------------------- kmeans ------------------------------------------
// seed: csum buf2 = first KC rows, ccnt buf2 = 1  (centers = csum/ccnt)
__global__ void km_init() {
    const int view = blockIdx.y, k = blockIdx.x, tid = threadIdx.x;
    for (int j = tid; j < DCLD; j += 256)
        g_csum3[2][view][k * DCLD + j] = g_zL[view][(size_t)k * DCLD + j];
    if (tid == 0) g_ccnt3[2][view][k] = 1.f;
}

// one kmeans iteration. Phase A: 4-row register blocking (centers smem read
// amortized over 4 rows -> crossbar traffic /4). Phase B unchanged.
__global__ void __launch_bounds__(256) km_step(int it) {
    extern __shared__ float sm[];
    float* sc = sm;                 // KC*DCLD centers
    float* ps = sm + KC * DCLD;     // KC*DCLD partial sums
    __shared__ float sinv[KC], scn2[KC];
    __shared__ float sred[KC][8];
    __shared__ int   scnt[KC], slab[128];
    const int view = blockIdx.y;
    const int tid = threadIdx.x, lane = tid & 31, wid = tid >> 5;
    const int rbuf = (it + 2) % 3, wbuf = it % 3, zbuf = (it + 1) % 3;
    const float* z = g_zL[view];

    if (tid < KC) {
        sinv[tid] = 1.f / fmaxf(g_ccnt3[rbuf][view][tid], 1.f);
        scnt[tid] = 0;
    }
    __syncthreads();
    for (int i = tid; i < KC * DCLD; i += 256) {
        sc[i] = g_csum3[rbuf][view][i] * sinv[i >> 10];
        ps[i] = 0.f;
    }
    __syncthreads();
    // centers' squared norms
    float loc[KC];
#pragma unroll
    for (int k = 0; k < KC; k++) {
        float s = 0.f;
#pragma unroll
        for (int j = 0; j < 4; j++) {
            float v = sc[k * DCLD + tid + j * 256];
            s = fmaf(v, v, s);
        }
        loc[k] = s;
    }
#pragma unroll
    for (int k = 0; k < KC; k++)
#pragma unroll
        for (int o = 16; o; o >>= 1)
            loc[k] += __shfl_xor_sync(0xffffffffu, loc[k], o);
    if (lane == 0)
#pragma unroll
        for (int k = 0; k < KC; k++) sred[k][wid] = loc[k];
    __syncthreads();
    if (tid < KC) {
        float s = 0.f;
#pragma unroll
        for (int w = 0; w < 8; w++) s += sred[tid][w];
        scn2[tid] = s;
    }
    __syncthreads();

    const int rbase = blockIdx.x * 128;
    // phase A: labels, 4 rows at a time per warp
    for (int rr = 0; rr < 16; rr += 4) {
        const int r0g = rbase + wid * 16 + rr;
        const float4* xr0 = (const float4*)(z + (size_t)r0g * DCLD);
        const float4* xr1 = (const float4*)(z + (size_t)(r0g + 1) * DCLD);
        const float4* xr2 = (const float4*)(z + (size_t)(r0g + 2) * DCLD);
        const float4* xr3 = (const float4*)(z + (size_t)(r0g + 3) * DCLD);
        float dots[4][KC];
#pragma unroll
        for (int q = 0; q < 4; q++)
#pragma unroll
            for (int k = 0; k < KC; k++) dots[q][k] = 0.f;
        for (int j = lane; j < DCLD / 4; j += 32) {
            float4 x0 = xr0[j], x1 = xr1[j], x2 = xr2[j], x3 = xr3[j];
#pragma unroll
            for (int k = 0; k < KC; k++) {
                float4 cv = *(const float4*)&sc[k * DCLD + 4 * j];
                dots[0][k] += x0.x * cv.x + x0.y * cv.y + x0.z * cv.z + x0.w * cv.w;
                dots[1][k] += x1.x * cv.x + x1.y * cv.y + x1.z * cv.z + x1.w * cv.w;
                dots[2][k] += x2.x * cv.x + x2.y * cv.y + x2.z * cv.z + x2.w * cv.w;
                dots[3][k] += x3.x * cv.x + x3.y * cv.y + x3.z * cv.z + x3.w * cv.w;
            }
        }
#pragma unroll
        for (int q = 0; q < 4; q++)
#pragma unroll
            for (int k = 0; k < KC; k++)
#pragma unroll
                for (int o = 16; o; o >>= 1)
                    dots[q][k] += __shfl_xor_sync(0xffffffffu, dots[q][k], o);
#pragma unroll
        for (int q = 0; q < 4; q++) {
            int bi = 0;
            float bd = scn2[0] - 2.f * dots[q][0];
#pragma unroll
            for (int k = 1; k < KC; k++) {
                float d = scn2[k] - 2.f * dots[q][k];
                if (d < bd) { bd = d; bi = k; }   // strict <: first-min argmin
            }
            if (lane == 0) {
                g_cl[view][r0g + q] = bi;
                atomicAdd(&scnt[bi], 1);
                slab[wid * 16 + rr + q] = bi;
            }
        }
    }
    __syncthreads();
    // phase B: column-owned accumulation
    for (int r = 0; r < 128; r++) {
        const int lb = slab[r];
        const float* zr = z + (size_t)(rbase + r) * DCLD;
#pragma unroll
        for (int j = 0; j < 4; j++)
            ps[lb * DCLD + tid + j * 256] += zr[tid + j * 256];
    }
    __syncthreads();
    for (int i = tid; i < KC * DCLD; i += 256) {
        float v = ps[i];
        if (v != 0.f) atomicAdd(&g_csum3[wbuf][view][i], v);
    }
    if (tid < KC && scnt[tid]) atomicAdd(&g_ccnt3[wbuf][view][tid], (float)scnt[tid]);
    // zero zbuf (read last iteration; next written at it+1 after launch boundary)
    if (tid < KC * DCLD / 64)
        g_csum3[zbuf][view][blockIdx.x * (KC * DCLD / 64) + tid] = 0.f;
    if (blockIdx.x == 0 && tid < KC) g_ccnt3[zbuf][view][tid] = 0.f;
}

// ------------------------- cross entropy -----------------------------------
// final centers = csum[(NIT-1)%3] / ccnt ; labels = g_cl (iteration NIT)
#define CE_BUF ((NIT - 1) % 3)
__global__ void __launch_bounds__(256) ce_kernel() {
    __shared__ float sc[KC * DCLD];
    __shared__ float swarp[8];
    __shared__ float sinv[KC];
    const int view = blockIdx.y;
    const float* z   = g_zL[view];
    const int*   lab = g_cl[view ^ 1];
    const int tid = threadIdx.x;
    if (tid < KC)
        sinv[tid] = 1.f / fmaxf(g_ccnt3[CE_BUF][view ^ 1][tid], 1.f);
    __syncthreads();
    for (int i = tid; i < KC * DCLD; i += 256)
        sc[i] = g_csum3[CE_BUF][view ^ 1][i] * sinv[i >> 10];
    __syncthreads();
    const int lane = tid & 31, wid = tid >> 5;
    float local = 0.f;
    const float invT = 1.f / 0.07f;
    for (int row = blockIdx.x * 8 + wid; row < B_; row += gridDim.x * 8) {
        const float4* xr = (const float4*)(z + (size_t)row * DCLD);
        float dots[KC];
#pragma unroll
        for (int k = 0; k < KC; k++) dots[k] = 0.f;
        for (int j = lane; j < DCLD / 4; j += 32) {
            float4 xv = xr[j];
#pragma unroll
            for (int k = 0; k < KC; k++) {
                float4 cv = *(const float4*)&sc[k * DCLD + 4 * j];
                dots[k] += xv.x * cv.x + xv.y * cv.y + xv.z * cv.z + xv.w * cv.w;
            }
        }
#pragma unroll
        for (int k = 0; k < KC; k++)
#pragma unroll
            for (int o = 16; o; o >>= 1)
                dots[k] += __shfl_xor_sync(0xffffffffu, dots[k], o);
        float m = -1e30f;
#pragma unroll
        for (int k = 0; k < KC; k++) { dots[k] *= invT; m = fmaxf(m, dots[k]); }
        float s = 0.f;
#pragma unroll
        for (int k = 0; k < KC; k++) s += expf(dots[k] - m);
        float lse = logf(s) + m;
        local += lse - dots[lab[row]];
    }
    if (lane == 0) swarp[wid] = local;
    __syncthreads();
    if (tid == 0) {
        float s = 0.f;
        for (int i = 0; i < 8; i++) s += swarp[i];
        atomicAdd(&g_scal[2 + view], s);
    }
}

// ------------------------- finalize ----------------------------------------
__global__ void final_kernel(float* __restrict__ out,
                             const float* __restrict__ Lam) {
    if (threadIdx.x == 0) {
        float cos1 = g_scal[0] * (1.f / B_);
        float cos2 = g_scal[1] * (1.f / B_);
        float lss  = 2.f - cos1 - cos2;
        float ce1  = g_scal[2] * (1.f / B_);
        float ce2  = g_scal[3] * (1.f / B_);
        float lcld = 0.5f * (ce1 + ce2);
        out[0] = lss + (*Lam) * lcld;
        out[1] = lss;
        out[2] = lcld;
    }
}

// ------------------------- host launcher -----------------------------------
extern "C" void kernel_launch(void* const* d_in, const int* in_sizes, int n_in,
                              void* d_out, int out_size)
{
    (void)in_sizes; (void)n_in; (void)out_size;
    const float* y1    = (const float*)d_in[0];
    const float* y2    = (const float*)d_in[1];
    const float* Lam   = (const float*)d_in[2];
    const float* W1    = (const float*)d_in[3];
    const float* b1    = (const float*)d_in[4];
    const float* gamma = (const float*)d_in[5];
    const float* beta  = (const float*)d_in[6];
    const float* W2    = (const float*)d_in[7];
    const float* b2    = (const float*)d_in[8];
    const float* Wc    = (const float*)d_in[9];
    float* out = (float*)d_out;
    float* z1H = out + 3;
    float* z1L = out + 3 + (size_t)B_ * DOUT;

    float *p_h = 0, *p_zH2 = 0, *p_zL = 0, *p_wcinv = 0, *p_rowss = 0;
    __half *p_yf = 0, *p_hf = 0, *p_w1f = 0, *p_w2f = 0, *p_wcf = 0;
    cudaGetSymbolAddress((void**)&p_h,     g_h);
    cudaGetSymbolAddress((void**)&p_zH2,   g_zH2);
    cudaGetSymbolAddress((void**)&p_zL,    g_zL);
    cudaGetSymbolAddress((void**)&p_wcinv, g_wcinv);
    cudaGetSymbolAddress((void**)&p_rowss, g_rowss);
    cudaGetSymbolAddress((void**)&p_yf,    g_yf);
    cudaGetSymbolAddress((void**)&p_hf,    g_hf);
    cudaGetSymbolAddress((void**)&p_w1f,   g_w1f);
    cudaGetSymbolAddress((void**)&p_w2f,   g_w2f);
    cudaGetSymbolAddress((void**)&p_wcf,   g_wcf);

    cudaFuncSetAttribute(mma_gemm<0>, cudaFuncAttributeMaxDynamicSharedMemorySize,
                         GEMM_SMEM);
    cudaFuncSetAttribute(mma_gemm<1>, cudaFuncAttributeMaxDynamicSharedMemorySize,
                         GEMM_SMEM);
    cudaFuncSetAttribute(mma_gemm<2>, cudaFuncAttributeMaxDynamicSharedMemorySize,
                         GEMM_SMEM);
    const int KM_SMEM = 2 * KC * DCLD * (int)sizeof(float);
    cudaFuncSetAttribute(km_step, cudaFuncAttributeMaxDynamicSharedMemorySize,
                         KM_SMEM);

    const int NY4 = B_ * DIN / 4;

    // launches 1-3 feed GEMM1; launch 4 = GEMM1 (ncu captures slot 4)
    conv_y<<<dim3(NY4 / 256, 2), 256>>>((const float4*)y1, (const float4*)y2,
                                        (uint2*)p_yf, NY4);
    conv_fp16<<<(DIN * DHID / 4) / 256, 256>>>((const float4*)W1,
        (uint2*)p_w1f, DIN * DHID / 4);
    init_zero<<<160, 256>>>();

    // GEMM1: h = y @ W1 + b1 (both views, fused BN column stats)
    mma_gemm<2><<<dim3(DHID / 128, B_ / 128, 2), 256, GEMM_SMEM>>>(
        p_yf, p_yf + (size_t)B_ * DIN,
        p_h, p_h + (size_t)B_ * DHID,
        p_w1f, b1, 0, 0, DHID, DIN);

    wc_part<<<dim3(DCLD / 256, 16), 256>>>(Wc);
    wc_fin<<<DCLD / 256, 256>>>();
    conv_fp16<<<(DHID * DOUT / 4) / 256, 256>>>((const float4*)W2,
        (uint2*)p_w2f, DHID * DOUT / 4);
    conv_fp16<<<(DIN * DCLD / 4) / 256, 256>>>((const float4*)Wc,
        (uint2*)p_wcf, DIN * DCLD / 4);

    for (int v = 0; v < 2; v++) bn_finish<<<DHID / 256, 256>>>(v);
    for (int v = 0; v < 2; v++) bn_relu<<<(B_ * DHID) / 256, 256>>>(v, gamma, beta);

    // GEMM2: z_H = relu_h @ W2 + b2
    mma_gemm<0><<<dim3(DOUT / 128, B_ / 128, 2), 256, GEMM_SMEM>>>(
        p_hf, p_hf + (size_t)B_ * DHID,
        z1H, p_zH2,
        p_w2f, b2, 0, 0, DOUT, DHID);

    // GEMM3: z_L_pre = (y @ Wc) * wcinv  (+ row sumsq)
    mma_gemm<1><<<dim3(DCLD / 128, B_ / 128, 2), 256, GEMM_SMEM>>>(
        p_yf, p_yf + (size_t)B_ * DIN,
        p_zL, p_zL + (size_t)B_ * DCLD,
        p_wcf, p_wcinv, p_rowss, p_rowss + B_, DCLD, DIN);

    row_scale<<<dim3((B_ * DCLD / 4) / 256, 2), 256>>>(z1L);
    cos_kernel<<<dim3(128, 2), 256>>>(z1H, y1, y2);

    km_init<<<dim3(KC, 2), 256>>>();
    for (int it = 0; it < NIT; it++)
        km_step<<<dim3(B_ / 128, 2), 256, KM_SMEM>>>(it);

    ce_kernel<<<dim3(64, 2), 256>>>();
    final_kernel<<<1, 32>>>(out, Lam);
}